// round 1
// baseline (speedup 1.0000x reference)
#include <cuda_runtime.h>

#define NROWS 8192
#define DIN   1024
#define DH    128

// Scratch (static device allocations are allowed)
__device__ float g_H[NROWS * DH];
__device__ float g_Q[NROWS * DH];
__device__ float g_K[NROWS * DH];
__device__ float g_V[NROWS * DH];
__device__ float g_U[NROWS];

__device__ __forceinline__ float sigmoidf_(float z) {
    return 1.0f / (1.0f + __expf(-z));
}

// ---------------------------------------------------------------------------
// Kernel A: H = (x @ W_fc + b_fc) * sigmoid(x @ W_gate + b_gate)
// grid 128 (BM=64 rows), 256 threads. KB=32.
// Thread: 8 rows x 4 cols, both fc and gate (64 accumulators).
// ---------------------------------------------------------------------------
__global__ void __launch_bounds__(256) gated_fc_kernel(
    const float* __restrict__ x,
    const float* __restrict__ Wfc, const float* __restrict__ bfc,
    const float* __restrict__ Wg,  const float* __restrict__ bg)
{
    __shared__ float xs[64][32];
    __shared__ float wfc_s[32][DH];
    __shared__ float wg_s[32][DH];

    const int t  = threadIdx.x;
    const int rb = blockIdx.x * 64;
    const int tx = t % 32;   // cols 4*tx .. 4*tx+3
    const int ty = t / 32;   // rows 8*ty .. 8*ty+7

    float afc[8][4];
    float ag[8][4];
#pragma unroll
    for (int i = 0; i < 8; i++)
#pragma unroll
        for (int j = 0; j < 4; j++) { afc[i][j] = 0.f; ag[i][j] = 0.f; }

    for (int k0 = 0; k0 < DIN; k0 += 32) {
        // load x tile 64x32 (512 float4, 2 per thread), coalesced
#pragma unroll
        for (int i = 0; i < 2; i++) {
            int s = t + 256 * i;
            int r = s / 8, c4 = s % 8;
            float4 v = *(const float4*)&x[(size_t)(rb + r) * DIN + k0 + c4 * 4];
            *(float4*)&xs[r][c4 * 4] = v;
        }
        // load W tiles 32x128 each (1024 float4, 4 per thread), coalesced
#pragma unroll
        for (int i = 0; i < 4; i++) {
            int s = t + 256 * i;
            int r = s / 32, c4 = s % 32;
            *(float4*)&wfc_s[r][c4 * 4] = *(const float4*)&Wfc[(size_t)(k0 + r) * DH + c4 * 4];
            *(float4*)&wg_s[r][c4 * 4]  = *(const float4*)&Wg [(size_t)(k0 + r) * DH + c4 * 4];
        }
        __syncthreads();

#pragma unroll 8
        for (int kk = 0; kk < 32; kk++) {
            float4 wf = *(const float4*)&wfc_s[kk][tx * 4];
            float4 wg4 = *(const float4*)&wg_s[kk][tx * 4];
#pragma unroll
            for (int i = 0; i < 8; i++) {
                float xv = xs[ty * 8 + i][kk];
                afc[i][0] = fmaf(xv, wf.x, afc[i][0]);
                afc[i][1] = fmaf(xv, wf.y, afc[i][1]);
                afc[i][2] = fmaf(xv, wf.z, afc[i][2]);
                afc[i][3] = fmaf(xv, wf.w, afc[i][3]);
                ag[i][0]  = fmaf(xv, wg4.x, ag[i][0]);
                ag[i][1]  = fmaf(xv, wg4.y, ag[i][1]);
                ag[i][2]  = fmaf(xv, wg4.z, ag[i][2]);
                ag[i][3]  = fmaf(xv, wg4.w, ag[i][3]);
            }
        }
        __syncthreads();
    }

    float4 bf = *(const float4*)&bfc[tx * 4];
    float4 bgv = *(const float4*)&bg[tx * 4];
#pragma unroll
    for (int i = 0; i < 8; i++) {
        int r = rb + ty * 8 + i;
        float4 h;
        h.x = (afc[i][0] + bf.x) * sigmoidf_(ag[i][0] + bgv.x);
        h.y = (afc[i][1] + bf.y) * sigmoidf_(ag[i][1] + bgv.y);
        h.z = (afc[i][2] + bf.z) * sigmoidf_(ag[i][2] + bgv.z);
        h.w = (afc[i][3] + bf.w) * sigmoidf_(ag[i][3] + bgv.w);
        *(float4*)&g_H[(size_t)r * DH + tx * 4] = h;
    }
}

// ---------------------------------------------------------------------------
// Kernel B: {Q,K,V} = H @ W_{q,k,v} + b.   grid (128, 3), 256 threads.
// BM=64 rows x 128 cols, KB=32. Thread: 8 rows x 4 cols.
// ---------------------------------------------------------------------------
__global__ void __launch_bounds__(256) qkv_kernel(
    const float* __restrict__ Wq, const float* __restrict__ bq,
    const float* __restrict__ Wk, const float* __restrict__ bk,
    const float* __restrict__ Wv, const float* __restrict__ bv)
{
    __shared__ float hs[64][32];
    __shared__ float ws[32][DH];

    const int t  = threadIdx.x;
    const int rb = blockIdx.x * 64;
    const int m  = blockIdx.y;   // 0=Q, 1=K, 2=V
    const int tx = t % 32;
    const int ty = t / 32;

    const float* W = (m == 0) ? Wq : (m == 1) ? Wk : Wv;
    const float* b = (m == 0) ? bq : (m == 1) ? bk : bv;
    float* Out = (m == 0) ? g_Q : (m == 1) ? g_K : g_V;

    float acc[8][4];
#pragma unroll
    for (int i = 0; i < 8; i++)
#pragma unroll
        for (int j = 0; j < 4; j++) acc[i][j] = 0.f;

    for (int k0 = 0; k0 < DH; k0 += 32) {
#pragma unroll
        for (int i = 0; i < 2; i++) {
            int s = t + 256 * i;
            int r = s / 8, c4 = s % 8;
            *(float4*)&hs[r][c4 * 4] = *(const float4*)&g_H[(size_t)(rb + r) * DH + k0 + c4 * 4];
        }
#pragma unroll
        for (int i = 0; i < 4; i++) {
            int s = t + 256 * i;
            int r = s / 32, c4 = s % 32;
            *(float4*)&ws[r][c4 * 4] = *(const float4*)&W[(size_t)(k0 + r) * DH + c4 * 4];
        }
        __syncthreads();

#pragma unroll 8
        for (int kk = 0; kk < 32; kk++) {
            float4 w4 = *(const float4*)&ws[kk][tx * 4];
#pragma unroll
            for (int i = 0; i < 8; i++) {
                float hv = hs[ty * 8 + i][kk];
                acc[i][0] = fmaf(hv, w4.x, acc[i][0]);
                acc[i][1] = fmaf(hv, w4.y, acc[i][1]);
                acc[i][2] = fmaf(hv, w4.z, acc[i][2]);
                acc[i][3] = fmaf(hv, w4.w, acc[i][3]);
            }
        }
        __syncthreads();
    }

    float4 bv4 = *(const float4*)&b[tx * 4];
#pragma unroll
    for (int i = 0; i < 8; i++) {
        int r = rb + ty * 8 + i;
        float4 o;
        o.x = acc[i][0] + bv4.x;
        o.y = acc[i][1] + bv4.y;
        o.z = acc[i][2] + bv4.z;
        o.w = acc[i][3] + bv4.w;
        *(float4*)&Out[(size_t)r * DH + tx * 4] = o;
    }
}

// ---------------------------------------------------------------------------
// Kernel C: U = V @ W_out  (scalar per row).  8192 threads.
// ---------------------------------------------------------------------------
__global__ void __launch_bounds__(256) u_kernel(const float* __restrict__ Wout)
{
    int i = blockIdx.x * 256 + threadIdx.x;
    const float4* wp = (const float4*)Wout;
    float s = 0.f;
#pragma unroll
    for (int d4 = 0; d4 < DH / 4; d4++) {
        float4 v = *(const float4*)&g_V[(size_t)i * DH + d4 * 4];
        float4 w = __ldg(&wp[d4]);
        s = fmaf(v.x, w.x, s);
        s = fmaf(v.y, w.y, s);
        s = fmaf(v.z, w.z, s);
        s = fmaf(v.w, w.w, s);
    }
    g_U[i] = s;
}

// ---------------------------------------------------------------------------
// Kernel D: out_i = sum_j exp(q_i.k_j/sqrt(128)) * u_j / sum_j exp(...) + b_out
// Flash-style, no max subtraction (scores bounded ~|2.5|).
// grid 128 (BM=64 q rows), 256 threads, BN=64 k rows per tile.
// Smem: qs[128][64], ks[128][64] transposed ([d][row]) -> dynamic 64 KB.
// Thread (tx=t%16, ty=t/16): 4 rows x 4 cols of S per tile; per d:
// 2x LDS.128 + 16 FFMA (FFMA-pipe bound). Scale folded into qs.
// ---------------------------------------------------------------------------
__global__ void __launch_bounds__(256) attn_kernel(
    const float* __restrict__ bout, float* __restrict__ out)
{
    extern __shared__ float sm[];
    float (*qs)[64] = (float(*)[64])sm;               // [128][64]
    float (*ks)[64] = (float(*)[64])(sm + 128 * 64);  // [128][64]

    const int t  = threadIdx.x;
    const int rb = blockIdx.x * 64;
    const int tx = t % 16;       // cols c0 = 4*tx
    const int ty = t / 16;       // rows r0 = 4*ty
    const float scale = 0.0883883476483184405502f;  // 1/sqrt(128)

    // Load q tile transposed + pre-scaled. j fixed per thread -> STS column
    // index varies across warp -> conflict-free stores.
    {
        int j = t % 64, d4b = t / 64;
#pragma unroll
        for (int i = 0; i < 8; i++) {
            int d4 = d4b + 4 * i;
            float4 v = *(const float4*)&g_Q[(size_t)(rb + j) * DH + d4 * 4];
            qs[d4 * 4 + 0][j] = v.x * scale;
            qs[d4 * 4 + 1][j] = v.y * scale;
            qs[d4 * 4 + 2][j] = v.z * scale;
            qs[d4 * 4 + 3][j] = v.w * scale;
        }
    }

    float num[4] = {0.f, 0.f, 0.f, 0.f};
    float den[4] = {0.f, 0.f, 0.f, 0.f};

    for (int jb = 0; jb < NROWS; jb += 64) {
        __syncthreads();  // protect ks from previous iteration readers (and qs first time)
        {
            int j = t % 64, d4b = t / 64;
#pragma unroll
            for (int i = 0; i < 8; i++) {
                int d4 = d4b + 4 * i;
                float4 v = *(const float4*)&g_K[(size_t)(jb + j) * DH + d4 * 4];
                ks[d4 * 4 + 0][j] = v.x;
                ks[d4 * 4 + 1][j] = v.y;
                ks[d4 * 4 + 2][j] = v.z;
                ks[d4 * 4 + 3][j] = v.w;
            }
        }
        __syncthreads();

        float S[4][4];
#pragma unroll
        for (int a = 0; a < 4; a++)
#pragma unroll
            for (int b = 0; b < 4; b++) S[a][b] = 0.f;

#pragma unroll 8
        for (int d = 0; d < 128; d++) {
            float4 qv = *(const float4*)&qs[d][ty * 4];
            float4 kv = *(const float4*)&ks[d][tx * 4];
            S[0][0] = fmaf(qv.x, kv.x, S[0][0]);
            S[0][1] = fmaf(qv.x, kv.y, S[0][1]);
            S[0][2] = fmaf(qv.x, kv.z, S[0][2]);
            S[0][3] = fmaf(qv.x, kv.w, S[0][3]);
            S[1][0] = fmaf(qv.y, kv.x, S[1][0]);
            S[1][1] = fmaf(qv.y, kv.y, S[1][1]);
            S[1][2] = fmaf(qv.y, kv.z, S[1][2]);
            S[1][3] = fmaf(qv.y, kv.w, S[1][3]);
            S[2][0] = fmaf(qv.z, kv.x, S[2][0]);
            S[2][1] = fmaf(qv.z, kv.y, S[2][1]);
            S[2][2] = fmaf(qv.z, kv.z, S[2][2]);
            S[2][3] = fmaf(qv.z, kv.w, S[2][3]);
            S[3][0] = fmaf(qv.w, kv.x, S[3][0]);
            S[3][1] = fmaf(qv.w, kv.y, S[3][1]);
            S[3][2] = fmaf(qv.w, kv.z, S[3][2]);
            S[3][3] = fmaf(qv.w, kv.w, S[3][3]);
        }

#pragma unroll
        for (int jj = 0; jj < 4; jj++) {
            float u = __ldg(&g_U[jb + tx * 4 + jj]);
#pragma unroll
            for (int ii = 0; ii < 4; ii++) {
                float e = __expf(S[ii][jj]);
                num[ii] = fmaf(e, u, num[ii]);
                den[ii] += e;
            }
        }
    }

    // Reduce across the 16 tx lanes (xor stays inside each 16-lane half-warp)
#pragma unroll
    for (int ii = 0; ii < 4; ii++) {
#pragma unroll
        for (int o = 8; o >= 1; o >>= 1) {
            num[ii] += __shfl_xor_sync(0xffffffffu, num[ii], o);
            den[ii] += __shfl_xor_sync(0xffffffffu, den[ii], o);
        }
    }

    if (tx == 0) {
        float b0 = __ldg(bout);
#pragma unroll
        for (int ii = 0; ii < 4; ii++)
            out[rb + ty * 4 + ii] = num[ii] / den[ii] + b0;
    }
}

// ---------------------------------------------------------------------------
extern "C" void kernel_launch(void* const* d_in, const int* in_sizes, int n_in,
                              void* d_out, int out_size)
{
    const float* x    = (const float*)d_in[0];
    const float* Wfc  = (const float*)d_in[1];
    const float* bfc  = (const float*)d_in[2];
    const float* Wg   = (const float*)d_in[3];
    const float* bg   = (const float*)d_in[4];
    const float* Wq   = (const float*)d_in[5];
    const float* bq   = (const float*)d_in[6];
    const float* Wk   = (const float*)d_in[7];
    const float* bk   = (const float*)d_in[8];
    const float* Wv   = (const float*)d_in[9];
    const float* bv   = (const float*)d_in[10];
    const float* Wout = (const float*)d_in[11];
    const float* bout = (const float*)d_in[12];
    float* out = (float*)d_out;

    // Idempotent, non-stream API: safe under graph capture.
    cudaFuncSetAttribute(attn_kernel, cudaFuncAttributeMaxDynamicSharedMemorySize, 65536);

    gated_fc_kernel<<<NROWS / 64, 256>>>(x, Wfc, bfc, Wg, bg);
    qkv_kernel<<<dim3(NROWS / 64, 3), 256>>>(Wq, bq, Wk, bk, Wv, bv);
    u_kernel<<<NROWS / 256, 256>>>(Wout);
    attn_kernel<<<NROWS / 64, 256, 65536>>>(bout, out);
}

// round 4
// speedup vs baseline: 3.5230x; 3.5230x over previous
#include <cuda_runtime.h>
#include <cstdint>

#define NROWS 8192
#define DIN   1024
#define DH    128

// ---------------------------------------------------------------------------
// Scratch
// ---------------------------------------------------------------------------
__device__ float g_H[NROWS * DH];
__device__ float g_Q[NROWS * DH];
__device__ float g_K[NROWS * DH];
__device__ float g_V[NROWS * DH];
__device__ float g_U[NROWS];
__device__ float g_PN[2 * NROWS];
__device__ float g_PD[2 * NROWS];

__device__ __forceinline__ float sigmoidf_(float z) {
    return 1.0f / (1.0f + __expf(-z));
}

__device__ __forceinline__ uint32_t smem_u32(const void* p) {
    uint32_t a;
    asm("{ .reg .u64 t; cvta.to.shared.u64 t, %1; cvt.u32.u64 %0, t; }" : "=r"(a) : "l"(p));
    return a;
}
__device__ __forceinline__ float to_tf32(float x) {
    float r; asm("cvt.rna.tf32.f32 %0, %1;" : "=f"(r) : "f"(x)); return r;
}
__device__ __forceinline__ void cp_async16(uint32_t dst, const void* src) {
    asm volatile("cp.async.cg.shared.global [%0], [%1], 16;" :: "r"(dst), "l"(src) : "memory");
}
__device__ __forceinline__ void cp_commit() {
    asm volatile("cp.async.commit_group;" ::: "memory");
}
template <int N>
__device__ __forceinline__ void cp_wait() {
    asm volatile("cp.async.wait_group %0;" :: "n"(N) : "memory");
}
__device__ __forceinline__ uint32_t lds32(uint32_t addr) {
    uint32_t v; asm volatile("ld.shared.b32 %0, [%1];" : "=r"(v) : "r"(addr)); return v;
}
__device__ __forceinline__ void mma_16x8x8(float c[4], const uint32_t a[4],
                                           uint32_t b0, uint32_t b1) {
    asm volatile(
        "mma.sync.aligned.m16n8k8.row.col.f32.tf32.tf32.f32 "
        "{%0,%1,%2,%3}, {%4,%5,%6,%7}, {%8,%9}, {%0,%1,%2,%3};"
        : "+f"(c[0]), "+f"(c[1]), "+f"(c[2]), "+f"(c[3])
        : "r"(a[0]), "r"(a[1]), "r"(a[2]), "r"(a[3]), "r"(b0), "r"(b1));
}
__device__ __forceinline__ float ex2f_(float x) {
    float r; asm("ex2.approx.f32 %0, %1;" : "=f"(r) : "f"(x)); return r;
}

// ---------------------------------------------------------------------------
// Kernel A: gated linear
// ---------------------------------------------------------------------------
__global__ void __launch_bounds__(256) gated_fc_kernel(
    const float* __restrict__ x,
    const float* __restrict__ Wfc, const float* __restrict__ bfc,
    const float* __restrict__ Wg,  const float* __restrict__ bg)
{
    __shared__ float xs[64][32];
    __shared__ float wfc_s[32][DH];
    __shared__ float wg_s[32][DH];

    const int t  = threadIdx.x;
    const int rb = blockIdx.x * 64;
    const int tx = t % 32;
    const int ty = t / 32;

    float afc[8][4], ag[8][4];
#pragma unroll
    for (int i = 0; i < 8; i++)
#pragma unroll
        for (int j = 0; j < 4; j++) { afc[i][j] = 0.f; ag[i][j] = 0.f; }

    for (int k0 = 0; k0 < DIN; k0 += 32) {
#pragma unroll
        for (int i = 0; i < 2; i++) {
            int s = t + 256 * i;
            int r = s / 8, c4 = s % 8;
            *(float4*)&xs[r][c4 * 4] = *(const float4*)&x[(size_t)(rb + r) * DIN + k0 + c4 * 4];
        }
#pragma unroll
        for (int i = 0; i < 4; i++) {
            int s = t + 256 * i;
            int r = s / 32, c4 = s % 32;
            *(float4*)&wfc_s[r][c4 * 4] = *(const float4*)&Wfc[(size_t)(k0 + r) * DH + c4 * 4];
            *(float4*)&wg_s[r][c4 * 4]  = *(const float4*)&Wg [(size_t)(k0 + r) * DH + c4 * 4];
        }
        __syncthreads();

#pragma unroll 8
        for (int kk = 0; kk < 32; kk++) {
            float4 wf  = *(const float4*)&wfc_s[kk][tx * 4];
            float4 wg4 = *(const float4*)&wg_s[kk][tx * 4];
#pragma unroll
            for (int i = 0; i < 8; i++) {
                float xv = xs[ty * 8 + i][kk];
                afc[i][0] = fmaf(xv, wf.x, afc[i][0]);
                afc[i][1] = fmaf(xv, wf.y, afc[i][1]);
                afc[i][2] = fmaf(xv, wf.z, afc[i][2]);
                afc[i][3] = fmaf(xv, wf.w, afc[i][3]);
                ag[i][0]  = fmaf(xv, wg4.x, ag[i][0]);
                ag[i][1]  = fmaf(xv, wg4.y, ag[i][1]);
                ag[i][2]  = fmaf(xv, wg4.z, ag[i][2]);
                ag[i][3]  = fmaf(xv, wg4.w, ag[i][3]);
            }
        }
        __syncthreads();
    }

    float4 bf  = *(const float4*)&bfc[tx * 4];
    float4 bgv = *(const float4*)&bg[tx * 4];
#pragma unroll
    for (int i = 0; i < 8; i++) {
        int r = rb + ty * 8 + i;
        float4 h;
        h.x = (afc[i][0] + bf.x) * sigmoidf_(ag[i][0] + bgv.x);
        h.y = (afc[i][1] + bf.y) * sigmoidf_(ag[i][1] + bgv.y);
        h.z = (afc[i][2] + bf.z) * sigmoidf_(ag[i][2] + bgv.z);
        h.w = (afc[i][3] + bf.w) * sigmoidf_(ag[i][3] + bgv.w);
        *(float4*)&g_H[(size_t)r * DH + tx * 4] = h;
    }
}

// ---------------------------------------------------------------------------
// Kernel B: QKV projections. K output rounded to tf32 (rna) for the MMA.
// ---------------------------------------------------------------------------
__global__ void __launch_bounds__(256) qkv_kernel(
    const float* __restrict__ Wq, const float* __restrict__ bq,
    const float* __restrict__ Wk, const float* __restrict__ bk,
    const float* __restrict__ Wv, const float* __restrict__ bv)
{
    __shared__ float hs[64][32];
    __shared__ float ws[32][DH];

    const int t  = threadIdx.x;
    const int rb = blockIdx.x * 64;
    const int m  = blockIdx.y;
    const int tx = t % 32;
    const int ty = t / 32;

    const float* W = (m == 0) ? Wq : (m == 1) ? Wk : Wv;
    const float* b = (m == 0) ? bq : (m == 1) ? bk : bv;
    float* Out = (m == 0) ? g_Q : (m == 1) ? g_K : g_V;

    float acc[8][4];
#pragma unroll
    for (int i = 0; i < 8; i++)
#pragma unroll
        for (int j = 0; j < 4; j++) acc[i][j] = 0.f;

    for (int k0 = 0; k0 < DH; k0 += 32) {
#pragma unroll
        for (int i = 0; i < 2; i++) {
            int s = t + 256 * i;
            int r = s / 8, c4 = s % 8;
            *(float4*)&hs[r][c4 * 4] = *(const float4*)&g_H[(size_t)(rb + r) * DH + k0 + c4 * 4];
        }
#pragma unroll
        for (int i = 0; i < 4; i++) {
            int s = t + 256 * i;
            int r = s / 32, c4 = s % 32;
            *(float4*)&ws[r][c4 * 4] = *(const float4*)&W[(size_t)(k0 + r) * DH + c4 * 4];
        }
        __syncthreads();

#pragma unroll 8
        for (int kk = 0; kk < 32; kk++) {
            float4 w4 = *(const float4*)&ws[kk][tx * 4];
#pragma unroll
            for (int i = 0; i < 8; i++) {
                float hv = hs[ty * 8 + i][kk];
                acc[i][0] = fmaf(hv, w4.x, acc[i][0]);
                acc[i][1] = fmaf(hv, w4.y, acc[i][1]);
                acc[i][2] = fmaf(hv, w4.z, acc[i][2]);
                acc[i][3] = fmaf(hv, w4.w, acc[i][3]);
            }
        }
        __syncthreads();
    }

    float4 bv4 = *(const float4*)&b[tx * 4];
#pragma unroll
    for (int i = 0; i < 8; i++) {
        int r = rb + ty * 8 + i;
        float4 o;
        o.x = acc[i][0] + bv4.x;
        o.y = acc[i][1] + bv4.y;
        o.z = acc[i][2] + bv4.z;
        o.w = acc[i][3] + bv4.w;
        if (m == 1) {  // K: pre-round to tf32 so HMMA truncation is exact
            o.x = to_tf32(o.x); o.y = to_tf32(o.y);
            o.z = to_tf32(o.z); o.w = to_tf32(o.w);
        }
        *(float4*)&Out[(size_t)r * DH + tx * 4] = o;
    }
}

// ---------------------------------------------------------------------------
// Kernel C: U = V @ W_out
// ---------------------------------------------------------------------------
__global__ void __launch_bounds__(256) u_kernel(const float* __restrict__ Wout)
{
    int i = blockIdx.x * 256 + threadIdx.x;
    const float4* wp = (const float4*)Wout;
    float s = 0.f;
#pragma unroll
    for (int d4 = 0; d4 < DH / 4; d4++) {
        float4 v = *(const float4*)&g_V[(size_t)i * DH + d4 * 4];
        float4 w = __ldg(&wp[d4]);
        s = fmaf(v.x, w.x, s);
        s = fmaf(v.y, w.y, s);
        s = fmaf(v.z, w.z, s);
        s = fmaf(v.w, w.w, s);
    }
    g_U[i] = s;
}

// ---------------------------------------------------------------------------
// Kernel D: flash attention with mma.sync tf32.
// grid (64 qblocks, 2 kv-splits), 256 threads (8 warps: 4 m-groups x 2 n-groups).
// Q tile (128x128) lives in registers as pre-built tf32 A-fragments.
// K tiles of 64 rows double-buffered in smem via cp.async.
// Smem layout (dynamic):
//   K buffers: 2 x 64 rows x (128+4) floats  = 2 x 33792 B
//   u slice:   4096 floats                   = 16384 B
//   reduction: rn[2][128], rd[2][128]        = 2048 B
// ---------------------------------------------------------------------------
#define KT 64                       // K-tile rows
#define NT (4096 / KT)              // tiles per split
#define KROW 132                    // padded row, floats
#define SM_K0   0
#define SM_K1   33792
#define SM_U    67584
#define SM_RN   83968
#define SM_RD   84992
#define SMEM_ATTN 86016

__device__ __forceinline__ void issue_ktile(uint32_t dstb, int j0, int tid) {
    const char* gk = (const char*)g_K + (size_t)j0 * (DH * 4);
#pragma unroll
    for (int i = 0; i < 8; i++) {
        int s = tid + 256 * i;
        int n = s >> 5, k4 = s & 31;
        cp_async16(dstb + n * (KROW * 4) + k4 * 16, gk + (size_t)n * 512 + k4 * 16);
    }
}

__global__ void __launch_bounds__(256, 1) attn_mma_kernel()
{
    extern __shared__ char smem[];
    const uint32_t sb = smem_u32(smem);
    const int tid  = threadIdx.x;
    const int lane = tid & 31;
    const int wid  = tid >> 5;
    const int wm   = wid >> 1;      // 0..3 : 32 q-rows each
    const int wn   = wid & 1;       // 0..1 : 32 k-cols each
    const int qb   = blockIdx.x;
    const int sp   = blockIdx.y;
    const int j_base = sp * 4096;

    // ---- u slice -> smem ----
#pragma unroll
    for (int i = 0; i < 4; i++) {
        int s = tid + 256 * i;
        *(float4*)(smem + SM_U + s * 16) = *(const float4*)&g_U[j_base + s * 4];
    }

    // ---- Q fragments -> registers (scaled by (1/sqrt(128))*log2(e), tf32) ----
    const float QS = 0.1275174341917854f;
    uint32_t qa[2][16][4];
    {
        const float* qp = g_Q + (size_t)(qb * 128 + wm * 32) * DH;
        const int r = lane >> 2, c = lane & 3;
#pragma unroll
        for (int im = 0; im < 2; im++) {
#pragma unroll
            for (int kf = 0; kf < 16; kf++) {
                const float* base = qp + (size_t)(im * 16 + r) * DH + kf * 8 + c;
                qa[im][kf][0] = __float_as_uint(to_tf32(base[0] * QS));
                qa[im][kf][1] = __float_as_uint(to_tf32(base[8 * DH] * QS));
                qa[im][kf][2] = __float_as_uint(to_tf32(base[4] * QS));
                qa[im][kf][3] = __float_as_uint(to_tf32(base[8 * DH + 4] * QS));
            }
        }
    }

    // ---- pipeline prologue ----
    issue_ktile(sb + SM_K0, j_base, tid);
    cp_commit();

    float num[4] = {0.f, 0.f, 0.f, 0.f};
    float den[4] = {0.f, 0.f, 0.f, 0.f};

    // per-thread B base: n = wn*32 + jn*8 + lane>>2 ; k = kf*8 + lane&3
    const uint32_t bbase = sb + (uint32_t)(wn * 32 + (lane >> 2)) * (KROW * 4)
                         + (uint32_t)(lane & 3) * 4;

#pragma unroll 1
    for (int t = 0; t < NT; t++) {
        if (t + 1 < NT) {
            issue_ktile(sb + (((t + 1) & 1) ? SM_K1 : SM_K0), j_base + (t + 1) * KT, tid);
            cp_commit();
            cp_wait<1>();
        } else {
            cp_wait<0>();
        }
        __syncthreads();

        const uint32_t kb = bbase + ((t & 1) ? SM_K1 : SM_K0);
        float c[2][4][4];
#pragma unroll
        for (int im = 0; im < 2; im++)
#pragma unroll
            for (int jn = 0; jn < 4; jn++)
#pragma unroll
                for (int v = 0; v < 4; v++) c[im][jn][v] = 0.f;

#pragma unroll
        for (int kf = 0; kf < 16; kf++) {
#pragma unroll
            for (int jn = 0; jn < 4; jn++) {
                uint32_t addr = kb + (uint32_t)jn * (8 * KROW * 4) + (uint32_t)kf * 32;
                uint32_t b0 = lds32(addr);
                uint32_t b1 = lds32(addr + 16);
                mma_16x8x8(c[0][jn], qa[0][kf], b0, b1);
                mma_16x8x8(c[1][jn], qa[1][kf], b0, b1);
            }
        }

        // epilogue: e = exp2(s); num += e*u; den += e
        const float* us = (const float*)(smem + SM_U) + t * KT;
#pragma unroll
        for (int jn = 0; jn < 4; jn++) {
            const int c0 = wn * 32 + jn * 8 + 2 * (lane & 3);
            const float2 uv = *(const float2*)&us[c0];
#pragma unroll
            for (int im = 0; im < 2; im++) {
                float e0 = ex2f_(c[im][jn][0]);
                float e1 = ex2f_(c[im][jn][1]);
                float e2 = ex2f_(c[im][jn][2]);
                float e3 = ex2f_(c[im][jn][3]);
                num[im * 2 + 0] = fmaf(e0, uv.x, num[im * 2 + 0]);
                num[im * 2 + 0] = fmaf(e1, uv.y, num[im * 2 + 0]);
                den[im * 2 + 0] += e0 + e1;
                num[im * 2 + 1] = fmaf(e2, uv.x, num[im * 2 + 1]);
                num[im * 2 + 1] = fmaf(e3, uv.y, num[im * 2 + 1]);
                den[im * 2 + 1] += e2 + e3;
            }
        }
        __syncthreads();
    }

    // ---- reduce: across lane%4, then across the two wn warps via smem ----
#pragma unroll
    for (int s = 0; s < 4; s++) {
        num[s] += __shfl_xor_sync(0xffffffffu, num[s], 1);
        num[s] += __shfl_xor_sync(0xffffffffu, num[s], 2);
        den[s] += __shfl_xor_sync(0xffffffffu, den[s], 1);
        den[s] += __shfl_xor_sync(0xffffffffu, den[s], 2);
    }
    if ((lane & 3) == 0) {
        float* rn = (float*)(smem + SM_RN);
        float* rd = (float*)(smem + SM_RD);
#pragma unroll
        for (int s = 0; s < 4; s++) {
            int row = wm * 32 + (s >> 1) * 16 + (s & 1) * 8 + (lane >> 2);
            rn[wn * 128 + row] = num[s];
            rd[wn * 128 + row] = den[s];
        }
    }
    __syncthreads();
    if (tid < 128) {
        const float* rn = (const float*)(smem + SM_RN);
        const float* rd = (const float*)(smem + SM_RD);
        g_PN[sp * NROWS + qb * 128 + tid] = rn[tid] + rn[128 + tid];
        g_PD[sp * NROWS + qb * 128 + tid] = rd[tid] + rd[128 + tid];
    }
}

// ---------------------------------------------------------------------------
// Kernel E: combine the two kv-splits
// ---------------------------------------------------------------------------
__global__ void __launch_bounds__(256) combine_kernel(const float* __restrict__ bout,
                                                      float* __restrict__ out)
{
    int i = blockIdx.x * 256 + threadIdx.x;
    float n = g_PN[i] + g_PN[NROWS + i];
    float d = g_PD[i] + g_PD[NROWS + i];
    out[i] = n / d + __ldg(bout);
}

// ---------------------------------------------------------------------------
extern "C" void kernel_launch(void* const* d_in, const int* in_sizes, int n_in,
                              void* d_out, int out_size)
{
    const float* x    = (const float*)d_in[0];
    const float* Wfc  = (const float*)d_in[1];
    const float* bfc  = (const float*)d_in[2];
    const float* Wg   = (const float*)d_in[3];
    const float* bg   = (const float*)d_in[4];
    const float* Wq   = (const float*)d_in[5];
    const float* bq   = (const float*)d_in[6];
    const float* Wk   = (const float*)d_in[7];
    const float* bk   = (const float*)d_in[8];
    const float* Wv   = (const float*)d_in[9];
    const float* bv   = (const float*)d_in[10];
    const float* Wout = (const float*)d_in[11];
    const float* bout = (const float*)d_in[12];
    float* out = (float*)d_out;

    cudaFuncSetAttribute(attn_mma_kernel, cudaFuncAttributeMaxDynamicSharedMemorySize, SMEM_ATTN);

    gated_fc_kernel<<<NROWS / 64, 256>>>(x, Wfc, bfc, Wg, bg);
    qkv_kernel<<<dim3(NROWS / 64, 3), 256>>>(Wq, bq, Wk, bk, Wv, bv);
    u_kernel<<<NROWS / 256, 256>>>(Wout);
    attn_mma_kernel<<<dim3(NROWS / 128, 2), 256, SMEM_ATTN>>>();
    combine_kernel<<<NROWS / 256, 256>>>(bout, out);
}

// round 6
// speedup vs baseline: 3.5259x; 1.0008x over previous
#include <cuda_runtime.h>
#include <cuda_bf16.h>
#include <cstdint>

#define NROWS 8192
#define DIN   1024
#define DH    128

// ---------------------------------------------------------------------------
// Scratch
// ---------------------------------------------------------------------------
__device__ float g_H[NROWS * DH];
__device__ float g_Q[NROWS * DH];
__device__ float g_K[NROWS * DH];
__device__ float g_V[NROWS * DH];
__device__ float g_U[NROWS];
__device__ float g_PN[2 * NROWS];
__device__ float g_PD[2 * NROWS];
__device__ __nv_bfloat16 g_xh[NROWS * DIN];
__device__ __nv_bfloat16 g_xl[NROWS * DIN];
__device__ __nv_bfloat16 g_wth[256 * DIN];   // [n][k], n: 0-127 fc, 128-255 gate
__device__ __nv_bfloat16 g_wtl[256 * DIN];

__device__ __forceinline__ float sigmoidf_(float z) {
    return 1.0f / (1.0f + __expf(-z));
}
__device__ __forceinline__ uint32_t smem_u32(const void* p) {
    uint32_t a;
    asm("{ .reg .u64 t; cvta.to.shared.u64 t, %1; cvt.u32.u64 %0, t; }" : "=r"(a) : "l"(p));
    return a;
}
__device__ __forceinline__ float to_tf32(float x) {
    float r; asm("cvt.rna.tf32.f32 %0, %1;" : "=f"(r) : "f"(x)); return r;
}
__device__ __forceinline__ void cp_async16(uint32_t dst, const void* src) {
    asm volatile("cp.async.cg.shared.global [%0], [%1], 16;" :: "r"(dst), "l"(src) : "memory");
}
__device__ __forceinline__ void cp_commit() {
    asm volatile("cp.async.commit_group;" ::: "memory");
}
template <int N>
__device__ __forceinline__ void cp_wait() {
    asm volatile("cp.async.wait_group %0;" :: "n"(N) : "memory");
}
__device__ __forceinline__ uint32_t lds32(uint32_t addr) {
    uint32_t v; asm volatile("ld.shared.b32 %0, [%1];" : "=r"(v) : "r"(addr)); return v;
}
__device__ __forceinline__ void mma_16x8x8(float c[4], const uint32_t a[4],
                                           uint32_t b0, uint32_t b1) {
    asm volatile(
        "mma.sync.aligned.m16n8k8.row.col.f32.tf32.tf32.f32 "
        "{%0,%1,%2,%3}, {%4,%5,%6,%7}, {%8,%9}, {%0,%1,%2,%3};"
        : "+f"(c[0]), "+f"(c[1]), "+f"(c[2]), "+f"(c[3])
        : "r"(a[0]), "r"(a[1]), "r"(a[2]), "r"(a[3]), "r"(b0), "r"(b1));
}
__device__ __forceinline__ void mma_bf16(float c[4], const uint32_t a[4],
                                         uint32_t b0, uint32_t b1) {
    asm volatile(
        "mma.sync.aligned.m16n8k16.row.col.f32.bf16.bf16.f32 "
        "{%0,%1,%2,%3}, {%4,%5,%6,%7}, {%8,%9}, {%0,%1,%2,%3};"
        : "+f"(c[0]), "+f"(c[1]), "+f"(c[2]), "+f"(c[3])
        : "r"(a[0]), "r"(a[1]), "r"(a[2]), "r"(a[3]), "r"(b0), "r"(b1));
}
__device__ __forceinline__ float ex2f_(float x) {
    float r; asm("ex2.approx.f32 %0, %1;" : "=f"(r) : "f"(x)); return r;
}

// ---------------------------------------------------------------------------
// Prekernel: x -> bf16 hi/lo
// ---------------------------------------------------------------------------
__global__ void __launch_bounds__(256) cvt_x_kernel(const float* __restrict__ x)
{
    int i = (blockIdx.x * 256 + threadIdx.x) * 4;
    float4 v = *(const float4*)&x[i];
    __nv_bfloat16 h0 = __float2bfloat16(v.x);
    __nv_bfloat16 h1 = __float2bfloat16(v.y);
    __nv_bfloat16 h2 = __float2bfloat16(v.z);
    __nv_bfloat16 h3 = __float2bfloat16(v.w);
    g_xh[i + 0] = h0; g_xh[i + 1] = h1; g_xh[i + 2] = h2; g_xh[i + 3] = h3;
    g_xl[i + 0] = __float2bfloat16(v.x - __bfloat162float(h0));
    g_xl[i + 1] = __float2bfloat16(v.y - __bfloat162float(h1));
    g_xl[i + 2] = __float2bfloat16(v.z - __bfloat162float(h2));
    g_xl[i + 3] = __float2bfloat16(v.w - __bfloat162float(h3));
}

// ---------------------------------------------------------------------------
// Prekernel: W_fc|W_gate -> bf16 hi/lo, transposed to [n][k]
// ---------------------------------------------------------------------------
__global__ void __launch_bounds__(256) cvt_w_kernel(const float* __restrict__ Wfc,
                                                    const float* __restrict__ Wg)
{
    int idx = blockIdx.x * 256 + threadIdx.x;   // n*1024 + k
    int n = idx >> 10, k = idx & 1023;
    float v = (n < 128) ? Wfc[(size_t)k * DH + n] : Wg[(size_t)k * DH + (n - 128)];
    __nv_bfloat16 h = __float2bfloat16(v);
    g_wth[idx] = h;
    g_wtl[idx] = __float2bfloat16(v - __bfloat162float(h));
}

// ---------------------------------------------------------------------------
// Kernel A: gated linear on tensor cores (bf16 3-term split, error-free).
// grid 128 (64 rows/CTA), 256 threads = 8 warps (wm = wid&1 -> 32 rows,
// wn = wid>>1 -> 32 fc cols + matching 32 gate cols).
// K staged at 32 cols, cp.async double-buffered. Smem rows padded to 40 bf16
// (80 B) for conflict-free lds32 fragment loads.
// ---------------------------------------------------------------------------
#define GF_PITCH 80
#define GF_BUF   51200
#define GF_XH(b)  ((b) * GF_BUF + 0)
#define GF_XL(b)  ((b) * GF_BUF + 5120)
#define GF_WH(b)  ((b) * GF_BUF + 10240)
#define GF_WL(b)  ((b) * GF_BUF + 30720)
#define GF_SMEM  (2 * GF_BUF)

__device__ __forceinline__ void gf_issue(uint32_t sb, int buf, int s, int rb, int tid)
{
    const int k0 = s * 32;
    {
        int row = tid >> 2, cc = tid & 3;
        size_t so = ((size_t)(rb + row) * DIN + k0) * 2 + cc * 16;
        cp_async16(sb + GF_XH(buf) + row * GF_PITCH + cc * 16, (const char*)g_xh + so);
        cp_async16(sb + GF_XL(buf) + row * GF_PITCH + cc * 16, (const char*)g_xl + so);
    }
#pragma unroll
    for (int i = 0; i < 4; i++) {
        int c = tid + 256 * i;
        int n = c >> 2, cc = c & 3;
        size_t so = ((size_t)n * DIN + k0) * 2 + cc * 16;
        cp_async16(sb + GF_WH(buf) + n * GF_PITCH + cc * 16, (const char*)g_wth + so);
        cp_async16(sb + GF_WL(buf) + n * GF_PITCH + cc * 16, (const char*)g_wtl + so);
    }
}

__global__ void __launch_bounds__(256, 1) gated_fc_mma_kernel(
    const float* __restrict__ bfc, const float* __restrict__ bg)
{
    extern __shared__ char smem[];
    const uint32_t sb = smem_u32(smem);
    const int tid  = threadIdx.x;
    const int lane = tid & 31;
    const int wid  = tid >> 5;
    const int wm   = wid & 1;        // 32 rows
    const int wn   = wid >> 1;       // 0..3
    const int rb   = blockIdx.x * 64;

    float c[2][8][4];
#pragma unroll
    for (int im = 0; im < 2; im++)
#pragma unroll
        for (int jn = 0; jn < 8; jn++)
#pragma unroll
            for (int v = 0; v < 4; v++) c[im][jn][v] = 0.f;

    gf_issue(sb, 0, 0, rb, tid);
    cp_commit();

    const uint32_t a_off = (uint32_t)(wm * 32 + (lane >> 2)) * GF_PITCH + (lane & 3) * 4;
    const uint32_t b_lane = (uint32_t)(lane >> 2) * GF_PITCH + (lane & 3) * 4;

#pragma unroll 1
    for (int s = 0; s < 32; s++) {
        if (s + 1 < 32) {
            gf_issue(sb, (s + 1) & 1, s + 1, rb, tid);
            cp_commit();
            cp_wait<1>();
        } else {
            cp_wait<0>();
        }
        __syncthreads();

        const int buf = s & 1;
        const uint32_t xh = sb + GF_XH(buf) + a_off;
        const uint32_t xl = sb + GF_XL(buf) + a_off;
        const uint32_t wh = sb + GF_WH(buf) + b_lane;
        const uint32_t wl = sb + GF_WL(buf) + b_lane;

#pragma unroll
        for (int kf = 0; kf < 2; kf++) {
            uint32_t ah[2][4], al[2][4];
#pragma unroll
            for (int im = 0; im < 2; im++) {
                uint32_t ar = xh + (uint32_t)im * (16 * GF_PITCH) + kf * 32;
                uint32_t alr = xl + (uint32_t)im * (16 * GF_PITCH) + kf * 32;
                ah[im][0] = lds32(ar);
                ah[im][1] = lds32(ar + 8 * GF_PITCH);
                ah[im][2] = lds32(ar + 16);
                ah[im][3] = lds32(ar + 8 * GF_PITCH + 16);
                al[im][0] = lds32(alr);
                al[im][1] = lds32(alr + 8 * GF_PITCH);
                al[im][2] = lds32(alr + 16);
                al[im][3] = lds32(alr + 8 * GF_PITCH + 16);
            }
#pragma unroll
            for (int jn = 0; jn < 8; jn++) {
                const int n0 = (jn < 4) ? wn * 32 + jn * 8 : 128 + wn * 32 + (jn - 4) * 8;
                uint32_t br  = wh + (uint32_t)n0 * GF_PITCH + kf * 32;
                uint32_t blr = wl + (uint32_t)n0 * GF_PITCH + kf * 32;
                uint32_t bh0 = lds32(br),  bh1 = lds32(br + 16);
                uint32_t bl0 = lds32(blr), bl1 = lds32(blr + 16);
#pragma unroll
                for (int im = 0; im < 2; im++) {
                    mma_bf16(c[im][jn], ah[im], bh0, bh1);
                    mma_bf16(c[im][jn], ah[im], bl0, bl1);
                    mma_bf16(c[im][jn], al[im], bh0, bh1);
                }
            }
        }
        __syncthreads();
    }

    // epilogue: h = (fc + bfc) * sigmoid(gate + bg)
    const int rr = rb + wm * 32 + (lane >> 2);
#pragma unroll
    for (int im = 0; im < 2; im++) {
#pragma unroll
        for (int jn = 0; jn < 4; jn++) {
            const int n0 = wn * 32 + jn * 8 + 2 * (lane & 3);
            float2 bf = *(const float2*)&bfc[n0];
            float2 bg2 = *(const float2*)&bg[n0];
            int r0 = rr + im * 16, r1 = r0 + 8;
            float2 h0, h1;
            h0.x = (c[im][jn][0] + bf.x) * sigmoidf_(c[im][jn + 4][0] + bg2.x);
            h0.y = (c[im][jn][1] + bf.y) * sigmoidf_(c[im][jn + 4][1] + bg2.y);
            h1.x = (c[im][jn][2] + bf.x) * sigmoidf_(c[im][jn + 4][2] + bg2.x);
            h1.y = (c[im][jn][3] + bf.y) * sigmoidf_(c[im][jn + 4][3] + bg2.y);
            *(float2*)&g_H[(size_t)r0 * DH + n0] = h0;
            *(float2*)&g_H[(size_t)r1 * DH + n0] = h1;
        }
    }
}

// ---------------------------------------------------------------------------
// Kernel B: QKV projections (scalar; K rounded to tf32)
// ---------------------------------------------------------------------------
__global__ void __launch_bounds__(256) qkv_kernel(
    const float* __restrict__ Wq, const float* __restrict__ bq,
    const float* __restrict__ Wk, const float* __restrict__ bk,
    const float* __restrict__ Wv, const float* __restrict__ bv)
{
    __shared__ float hs[64][32];
    __shared__ float ws[32][DH];

    const int t  = threadIdx.x;
    const int rb = blockIdx.x * 64;
    const int m  = blockIdx.y;
    const int tx = t % 32;
    const int ty = t / 32;

    const float* W = (m == 0) ? Wq : (m == 1) ? Wk : Wv;
    const float* b = (m == 0) ? bq : (m == 1) ? bk : bv;
    float* Out = (m == 0) ? g_Q : (m == 1) ? g_K : g_V;

    float acc[8][4];
#pragma unroll
    for (int i = 0; i < 8; i++)
#pragma unroll
        for (int j = 0; j < 4; j++) acc[i][j] = 0.f;

    for (int k0 = 0; k0 < DH; k0 += 32) {
#pragma unroll
        for (int i = 0; i < 2; i++) {
            int s = t + 256 * i;
            int r = s / 8, c4 = s % 8;
            *(float4*)&hs[r][c4 * 4] = *(const float4*)&g_H[(size_t)(rb + r) * DH + k0 + c4 * 4];
        }
#pragma unroll
        for (int i = 0; i < 4; i++) {
            int s = t + 256 * i;
            int r = s / 32, c4 = s % 32;
            *(float4*)&ws[r][c4 * 4] = *(const float4*)&W[(size_t)(k0 + r) * DH + c4 * 4];
        }
        __syncthreads();

#pragma unroll 8
        for (int kk = 0; kk < 32; kk++) {
            float4 w4 = *(const float4*)&ws[kk][tx * 4];
#pragma unroll
            for (int i = 0; i < 8; i++) {
                float hv = hs[ty * 8 + i][kk];
                acc[i][0] = fmaf(hv, w4.x, acc[i][0]);
                acc[i][1] = fmaf(hv, w4.y, acc[i][1]);
                acc[i][2] = fmaf(hv, w4.z, acc[i][2]);
                acc[i][3] = fmaf(hv, w4.w, acc[i][3]);
            }
        }
        __syncthreads();
    }

    float4 bv4 = *(const float4*)&b[tx * 4];
#pragma unroll
    for (int i = 0; i < 8; i++) {
        int r = rb + ty * 8 + i;
        float4 o;
        o.x = acc[i][0] + bv4.x;
        o.y = acc[i][1] + bv4.y;
        o.z = acc[i][2] + bv4.z;
        o.w = acc[i][3] + bv4.w;
        if (m == 1) {
            o.x = to_tf32(o.x); o.y = to_tf32(o.y);
            o.z = to_tf32(o.z); o.w = to_tf32(o.w);
        }
        *(float4*)&Out[(size_t)r * DH + tx * 4] = o;
    }
}

// ---------------------------------------------------------------------------
// Kernel C: U = V @ W_out
// ---------------------------------------------------------------------------
__global__ void __launch_bounds__(256) u_kernel(const float* __restrict__ Wout)
{
    int i = blockIdx.x * 256 + threadIdx.x;
    const float4* wp = (const float4*)Wout;
    float s = 0.f;
#pragma unroll
    for (int d4 = 0; d4 < DH / 4; d4++) {
        float4 v = *(const float4*)&g_V[(size_t)i * DH + d4 * 4];
        float4 w = __ldg(&wp[d4]);
        s = fmaf(v.x, w.x, s);
        s = fmaf(v.y, w.y, s);
        s = fmaf(v.z, w.z, s);
        s = fmaf(v.w, w.w, s);
    }
    g_U[i] = s;
}

// ---------------------------------------------------------------------------
// Kernel D: flash attention, mma.sync tf32, pipelined epilogue.
// ---------------------------------------------------------------------------
#define KT 64
#define NT (4096 / KT)
#define KROW 132
#define SM_K0   0
#define SM_K1   33792
#define SM_U    67584
#define SM_RN   83968
#define SM_RD   84992
#define SMEM_ATTN 86016

__device__ __forceinline__ void issue_ktile(uint32_t dstb, int j0, int tid) {
    const char* gk = (const char*)g_K + (size_t)j0 * (DH * 4);
#pragma unroll
    for (int i = 0; i < 8; i++) {
        int s = tid + 256 * i;
        int n = s >> 5, k4 = s & 31;
        cp_async16(dstb + n * (KROW * 4) + k4 * 16, gk + (size_t)n * 512 + k4 * 16);
    }
}

__device__ __forceinline__ void attn_epilogue(const float c[2][4][4], const float* us,
                                              int wn, int lane, float num[4], float den[4])
{
#pragma unroll
    for (int jn = 0; jn < 4; jn++) {
        const int c0 = wn * 32 + jn * 8 + 2 * (lane & 3);
        const float2 uv = *(const float2*)&us[c0];
#pragma unroll
        for (int im = 0; im < 2; im++) {
            float e0 = ex2f_(c[im][jn][0]);
            float e1 = ex2f_(c[im][jn][1]);
            float e2 = ex2f_(c[im][jn][2]);
            float e3 = ex2f_(c[im][jn][3]);
            num[im * 2 + 0] = fmaf(e0, uv.x, num[im * 2 + 0]);
            num[im * 2 + 0] = fmaf(e1, uv.y, num[im * 2 + 0]);
            den[im * 2 + 0] += e0 + e1;
            num[im * 2 + 1] = fmaf(e2, uv.x, num[im * 2 + 1]);
            num[im * 2 + 1] = fmaf(e3, uv.y, num[im * 2 + 1]);
            den[im * 2 + 1] += e2 + e3;
        }
    }
}

__global__ void __launch_bounds__(256, 1) attn_mma_kernel()
{
    extern __shared__ char smem[];
    const uint32_t sb = smem_u32(smem);
    const int tid  = threadIdx.x;
    const int lane = tid & 31;
    const int wid  = tid >> 5;
    const int wm   = wid >> 1;
    const int wn   = wid & 1;
    const int qb   = blockIdx.x;
    const int sp   = blockIdx.y;
    const int j_base = sp * 4096;

#pragma unroll
    for (int i = 0; i < 4; i++) {
        int s = tid + 256 * i;
        *(float4*)(smem + SM_U + s * 16) = *(const float4*)&g_U[j_base + s * 4];
    }

    const float QS = 0.1275174341917854f;   // log2(e)/sqrt(128)
    uint32_t qa[2][16][4];
    {
        const float* qp = g_Q + (size_t)(qb * 128 + wm * 32) * DH;
        const int r = lane >> 2, cc = lane & 3;
#pragma unroll
        for (int im = 0; im < 2; im++) {
#pragma unroll
            for (int kf = 0; kf < 16; kf++) {
                const float* base = qp + (size_t)(im * 16 + r) * DH + kf * 8 + cc;
                qa[im][kf][0] = __float_as_uint(to_tf32(base[0] * QS));
                qa[im][kf][1] = __float_as_uint(to_tf32(base[8 * DH] * QS));
                qa[im][kf][2] = __float_as_uint(to_tf32(base[4] * QS));
                qa[im][kf][3] = __float_as_uint(to_tf32(base[8 * DH + 4] * QS));
            }
        }
    }

    issue_ktile(sb + SM_K0, j_base, tid);
    cp_commit();

    float num[4] = {0.f, 0.f, 0.f, 0.f};
    float den[4] = {0.f, 0.f, 0.f, 0.f};
    float cbuf[2][2][4][4];

    const uint32_t bbase = sb + (uint32_t)(wn * 32 + (lane >> 2)) * (KROW * 4)
                         + (uint32_t)(lane & 3) * 4;

#pragma unroll 1
    for (int t = 0; t < NT; t++) {
        if (t + 1 < NT) {
            issue_ktile(sb + (((t + 1) & 1) ? SM_K1 : SM_K0), j_base + (t + 1) * KT, tid);
            cp_commit();
            cp_wait<1>();
        } else {
            cp_wait<0>();
        }
        __syncthreads();

        const uint32_t kb = bbase + ((t & 1) ? SM_K1 : SM_K0);
        float (*c)[4][4] = cbuf[t & 1];
#pragma unroll
        for (int im = 0; im < 2; im++)
#pragma unroll
            for (int jn = 0; jn < 4; jn++)
#pragma unroll
                for (int v = 0; v < 4; v++) c[im][jn][v] = 0.f;

#pragma unroll
        for (int kf = 0; kf < 16; kf++) {
#pragma unroll
            for (int jn = 0; jn < 4; jn++) {
                uint32_t addr = kb + (uint32_t)jn * (8 * KROW * 4) + (uint32_t)kf * 32;
                uint32_t b0 = lds32(addr);
                uint32_t b1 = lds32(addr + 16);
                mma_16x8x8(c[0][jn], qa[0][kf], b0, b1);
                mma_16x8x8(c[1][jn], qa[1][kf], b0, b1);
            }
        }

        // overlap: epilogue of previous tile runs against this tile's MMAs
        if (t > 0) {
            const float* us = (const float*)(smem + SM_U) + (t - 1) * KT;
            attn_epilogue(cbuf[(t - 1) & 1], us, wn, lane, num, den);
        }
        __syncthreads();
    }
    {
        const float* us = (const float*)(smem + SM_U) + (NT - 1) * KT;
        attn_epilogue(cbuf[(NT - 1) & 1], us, wn, lane, num, den);
    }

#pragma unroll
    for (int s = 0; s < 4; s++) {
        num[s] += __shfl_xor_sync(0xffffffffu, num[s], 1);
        num[s] += __shfl_xor_sync(0xffffffffu, num[s], 2);
        den[s] += __shfl_xor_sync(0xffffffffu, den[s], 1);
        den[s] += __shfl_xor_sync(0xffffffffu, den[s], 2);
    }
    if ((lane & 3) == 0) {
        float* rn = (float*)(smem + SM_RN);
        float* rd = (float*)(smem + SM_RD);
#pragma unroll
        for (int s = 0; s < 4; s++) {
            int row = wm * 32 + (s >> 1) * 16 + (s & 1) * 8 + (lane >> 2);
            rn[wn * 128 + row] = num[s];
            rd[wn * 128 + row] = den[s];
        }
    }
    __syncthreads();
    if (tid < 128) {
        const float* rn = (const float*)(smem + SM_RN);
        const float* rd = (const float*)(smem + SM_RD);
        g_PN[sp * NROWS + qb * 128 + tid] = rn[tid] + rn[128 + tid];
        g_PD[sp * NROWS + qb * 128 + tid] = rd[tid] + rd[128 + tid];
    }
}

// ---------------------------------------------------------------------------
// Kernel E: combine splits
// ---------------------------------------------------------------------------
__global__ void __launch_bounds__(256) combine_kernel(const float* __restrict__ bout,
                                                      float* __restrict__ out)
{
    int i = blockIdx.x * 256 + threadIdx.x;
    float n = g_PN[i] + g_PN[NROWS + i];
    float d = g_PD[i] + g_PD[NROWS + i];
    out[i] = n / d + __ldg(bout);
}

// ---------------------------------------------------------------------------
extern "C" void kernel_launch(void* const* d_in, const int* in_sizes, int n_in,
                              void* d_out, int out_size)
{
    const float* x    = (const float*)d_in[0];
    const float* Wfc  = (const float*)d_in[1];
    const float* bfc  = (const float*)d_in[2];
    const float* Wg   = (const float*)d_in[3];
    const float* bg   = (const float*)d_in[4];
    const float* Wq   = (const float*)d_in[5];
    const float* bq   = (const float*)d_in[6];
    const float* Wk   = (const float*)d_in[7];
    const float* bk   = (const float*)d_in[8];
    const float* Wv   = (const float*)d_in[9];
    const float* bv   = (const float*)d_in[10];
    const float* Wout = (const float*)d_in[11];
    const float* bout = (const float*)d_in[12];
    float* out = (float*)d_out;

    cudaFuncSetAttribute(attn_mma_kernel, cudaFuncAttributeMaxDynamicSharedMemorySize, SMEM_ATTN);
    cudaFuncSetAttribute(gated_fc_mma_kernel, cudaFuncAttributeMaxDynamicSharedMemorySize, GF_SMEM);

    cvt_x_kernel<<<NROWS * DIN / 1024, 256>>>(x);
    cvt_w_kernel<<<256 * DIN / 256, 256>>>(Wfc, Wg);
    gated_fc_mma_kernel<<<NROWS / 64, 256, GF_SMEM>>>(bfc, bg);
    qkv_kernel<<<dim3(NROWS / 64, 3), 256>>>(Wq, bq, Wk, bk, Wv, bv);
    u_kernel<<<NROWS / 256, 256>>>(Wout);
    attn_mma_kernel<<<dim3(NROWS / 128, 2), 256, SMEM_ATTN>>>();
    combine_kernel<<<NROWS / 256, 256>>>(bout, out);
}

// round 8
// speedup vs baseline: 4.1356x; 1.1729x over previous
#include <cuda_runtime.h>
#include <cuda_bf16.h>
#include <cstdint>

#define NROWS 8192
#define DIN   1024
#define DH    128

// ---------------------------------------------------------------------------
// Scratch
// ---------------------------------------------------------------------------
__device__ float g_H[NROWS * DH];
__device__ float g_Q[NROWS * DH];
__device__ float g_V[NROWS * DH];
__device__ float g_U[NROWS];
__device__ float g_PN[2 * NROWS];
__device__ float g_PD[2 * NROWS];
// Packed K: 128 tiles of [64 rows][528 B] = 33792 B each
__device__ __align__(1024) char g_Kp[128 * 33792];
// Packed x hi/lo: per (rowblock of 64, stage of 32k): [hi 64x80B][lo 64x80B]
__device__ __align__(1024) char g_xp[128 * 32 * 10240];
// Packed W hi/lo: per stage: [wh 256x80B][wl 256x80B]
__device__ __align__(1024) char g_wp[32 * 40960];

__device__ __forceinline__ float sigmoidf_(float z) {
    return 1.0f / (1.0f + __expf(-z));
}
__device__ __forceinline__ uint32_t smem_u32(const void* p) {
    uint32_t a;
    asm("{ .reg .u64 t; cvta.to.shared.u64 t, %1; cvt.u32.u64 %0, t; }" : "=r"(a) : "l"(p));
    return a;
}
__device__ __forceinline__ float to_tf32(float x) {
    float r; asm("cvt.rna.tf32.f32 %0, %1;" : "=f"(r) : "f"(x)); return r;
}
__device__ __forceinline__ uint32_t lds32(uint32_t addr) {
    uint32_t v; asm volatile("ld.shared.b32 %0, [%1];" : "=r"(v) : "r"(addr)); return v;
}
__device__ __forceinline__ void mma_16x8x8(float c[4], const uint32_t a[4],
                                           uint32_t b0, uint32_t b1) {
    asm volatile(
        "mma.sync.aligned.m16n8k8.row.col.f32.tf32.tf32.f32 "
        "{%0,%1,%2,%3}, {%4,%5,%6,%7}, {%8,%9}, {%0,%1,%2,%3};"
        : "+f"(c[0]), "+f"(c[1]), "+f"(c[2]), "+f"(c[3])
        : "r"(a[0]), "r"(a[1]), "r"(a[2]), "r"(a[3]), "r"(b0), "r"(b1));
}
__device__ __forceinline__ void mma_bf16(float c[4], const uint32_t a[4],
                                         uint32_t b0, uint32_t b1) {
    asm volatile(
        "mma.sync.aligned.m16n8k16.row.col.f32.bf16.bf16.f32 "
        "{%0,%1,%2,%3}, {%4,%5,%6,%7}, {%8,%9}, {%0,%1,%2,%3};"
        : "+f"(c[0]), "+f"(c[1]), "+f"(c[2]), "+f"(c[3])
        : "r"(a[0]), "r"(a[1]), "r"(a[2]), "r"(a[3]), "r"(b0), "r"(b1));
}
__device__ __forceinline__ float ex2f_(float x) {
    float r; asm("ex2.approx.f32 %0, %1;" : "=f"(r) : "f"(x)); return r;
}
// ---- bulk copy + mbarrier ----
__device__ __forceinline__ void bulk_g2s(uint32_t dst, const void* src,
                                         uint32_t bytes, uint32_t mbar) {
    asm volatile(
        "cp.async.bulk.shared::cluster.global.mbarrier::complete_tx::bytes [%0], [%1], %2, [%3];"
        :: "r"(dst), "l"(src), "r"(bytes), "r"(mbar) : "memory");
}
#define MBARRIER_INIT(addr, cnt) \
    asm volatile("mbarrier.init.shared.b64 [%0], %1;" :: "r"(addr), "r"(cnt) : "memory")
#define MBARRIER_EXPECT_TX(addr, bytes) \
    asm volatile("mbarrier.arrive.expect_tx.shared.b64 _, [%0], %1;" \
                 :: "r"(addr), "r"(bytes) : "memory")
#define MBARRIER_WAIT_PARITY(addr, ph) do {                                    \
    uint32_t _m = (uint32_t)(addr);                                            \
    uint32_t _p = (uint32_t)(ph);                                              \
    uint32_t _d;                                                               \
    asm volatile("{\n\t.reg .pred p;\n\t"                                      \
        "mbarrier.try_wait.parity.acquire.cta.shared::cta.b64 p, [%1], %2;\n\t"\
        "selp.b32 %0, 1, 0, p;\n\t}" : "=r"(_d) : "r"(_m), "r"(_p) : "memory");\
    if (!_d) {                                                                 \
        asm volatile("{\n\t.reg .pred P1;\n\t"                                 \
            "WL_%=:\n\t"                                                       \
            "mbarrier.try_wait.parity.acquire.cta.shared::cta.b64 P1, [%0], %1, 0x989680;\n\t" \
            "@P1 bra.uni WD_%=;\n\t"                                           \
            "bra.uni WL_%=;\n\t"                                               \
            "WD_%=:\n\t}" :: "r"(_m), "r"(_p) : "memory");                     \
    }                                                                          \
} while (0)

// ---------------------------------------------------------------------------
// Prekernel: x -> packed bf16 hi/lo tiles
// ---------------------------------------------------------------------------
__global__ void __launch_bounds__(256) cvt_x_kernel(const float* __restrict__ x)
{
    int i = (blockIdx.x * 256 + threadIdx.x) * 4;
    int row = i >> 10, k = i & 1023;
    float4 v = *(const float4*)&x[i];
    __nv_bfloat16 h0 = __float2bfloat16(v.x);
    __nv_bfloat16 h1 = __float2bfloat16(v.y);
    __nv_bfloat16 h2 = __float2bfloat16(v.z);
    __nv_bfloat16 h3 = __float2bfloat16(v.w);
    __nv_bfloat16 l0 = __float2bfloat16(v.x - __bfloat162float(h0));
    __nv_bfloat16 l1 = __float2bfloat16(v.y - __bfloat162float(h1));
    __nv_bfloat16 l2 = __float2bfloat16(v.z - __bfloat162float(h2));
    __nv_bfloat16 l3 = __float2bfloat16(v.w - __bfloat162float(h3));
    int rb = row >> 6, r = row & 63, stage = k >> 5, kk = k & 31;
    size_t base = (size_t)(rb * 32 + stage) * 10240 + r * 80 + kk * 2;
    uint32_t hp0 = ((uint32_t)__bfloat16_as_ushort(h1) << 16) | __bfloat16_as_ushort(h0);
    uint32_t hp1 = ((uint32_t)__bfloat16_as_ushort(h3) << 16) | __bfloat16_as_ushort(h2);
    uint32_t lp0 = ((uint32_t)__bfloat16_as_ushort(l1) << 16) | __bfloat16_as_ushort(l0);
    uint32_t lp1 = ((uint32_t)__bfloat16_as_ushort(l3) << 16) | __bfloat16_as_ushort(l2);
    *(uint2*)(g_xp + base)        = make_uint2(hp0, hp1);
    *(uint2*)(g_xp + base + 5120) = make_uint2(lp0, lp1);
}

// ---------------------------------------------------------------------------
// Prekernel: W_fc|W_gate -> packed bf16 hi/lo tiles, transposed to [n][k]
// ---------------------------------------------------------------------------
__global__ void __launch_bounds__(256) cvt_w_kernel(const float* __restrict__ Wfc,
                                                    const float* __restrict__ Wg)
{
    int idx = blockIdx.x * 256 + threadIdx.x;   // n*1024 + k
    int n = idx >> 10, k = idx & 1023;
    float v = (n < 128) ? Wfc[(size_t)k * DH + n] : Wg[(size_t)k * DH + (n - 128)];
    __nv_bfloat16 h = __float2bfloat16(v);
    __nv_bfloat16 l = __float2bfloat16(v - __bfloat162float(h));
    int stage = k >> 5, kk = k & 31;
    size_t base = (size_t)stage * 40960 + n * 80 + kk * 2;
    *(__nv_bfloat16*)(g_wp + base)         = h;
    *(__nv_bfloat16*)(g_wp + base + 20480) = l;
}

// ---------------------------------------------------------------------------
// Kernel A: gated linear, bf16 3-term MMA, cp.async.bulk double-buffered.
// ---------------------------------------------------------------------------
#define GF_PITCH 80
#define GF_BUF   51200
#define GF_XH(b)  ((b) * GF_BUF + 0)
#define GF_XL(b)  ((b) * GF_BUF + 5120)
#define GF_WH(b)  ((b) * GF_BUF + 10240)
#define GF_WL(b)  ((b) * GF_BUF + 30720)
#define GF_MBAR   (2 * GF_BUF)
#define GF_SMEM   (2 * GF_BUF + 64)

__global__ void __launch_bounds__(256, 1) gated_fc_mma_kernel(
    const float* __restrict__ bfc, const float* __restrict__ bg)
{
    extern __shared__ char smem[];
    const uint32_t sb = smem_u32(smem);
    const int tid  = threadIdx.x;
    const int lane = tid & 31;
    const int wid  = tid >> 5;
    const int wm   = wid & 1;
    const int wn   = wid >> 1;
    const int rb   = blockIdx.x * 64;

    if (tid == 0) {
        MBARRIER_INIT(sb + GF_MBAR, 1);
        MBARRIER_INIT(sb + GF_MBAR + 8, 1);
    }
    __syncthreads();

    float c[2][8][4];
#pragma unroll
    for (int im = 0; im < 2; im++)
#pragma unroll
        for (int jn = 0; jn < 8; jn++)
#pragma unroll
            for (int v = 0; v < 4; v++) c[im][jn][v] = 0.f;

    if (tid == 0) {
        MBARRIER_EXPECT_TX(sb + GF_MBAR, 51200);
        bulk_g2s(sb + GF_XH(0), g_xp + (size_t)(blockIdx.x * 32) * 10240, 10240, sb + GF_MBAR);
        bulk_g2s(sb + GF_WH(0), g_wp, 40960, sb + GF_MBAR);
    }

    const uint32_t a_off = (uint32_t)(wm * 32 + (lane >> 2)) * GF_PITCH + (lane & 3) * 4;
    const uint32_t b_lane = (uint32_t)(lane >> 2) * GF_PITCH + (lane & 3) * 4;

#pragma unroll 1
    for (int s = 0; s < 32; s++) {
        if (s + 1 < 32 && tid == 0) {
            const int nb = (s + 1) & 1;
            const uint32_t mb = sb + GF_MBAR + 8 * nb;
            MBARRIER_EXPECT_TX(mb, 51200);
            bulk_g2s(sb + GF_XH(nb), g_xp + (size_t)(blockIdx.x * 32 + s + 1) * 10240, 10240, mb);
            bulk_g2s(sb + GF_WH(nb), g_wp + (size_t)(s + 1) * 40960, 40960, mb);
        }
        MBARRIER_WAIT_PARITY(sb + GF_MBAR + 8 * (s & 1), (s >> 1) & 1);

        const int buf = s & 1;
        const uint32_t xh = sb + GF_XH(buf) + a_off;
        const uint32_t xl = sb + GF_XL(buf) + a_off;
        const uint32_t wh = sb + GF_WH(buf) + b_lane;
        const uint32_t wl = sb + GF_WL(buf) + b_lane;

#pragma unroll
        for (int kf = 0; kf < 2; kf++) {
            uint32_t ah[2][4], al[2][4];
#pragma unroll
            for (int im = 0; im < 2; im++) {
                uint32_t ar  = xh + (uint32_t)im * (16 * GF_PITCH) + kf * 32;
                uint32_t alr = xl + (uint32_t)im * (16 * GF_PITCH) + kf * 32;
                ah[im][0] = lds32(ar);
                ah[im][1] = lds32(ar + 8 * GF_PITCH);
                ah[im][2] = lds32(ar + 16);
                ah[im][3] = lds32(ar + 8 * GF_PITCH + 16);
                al[im][0] = lds32(alr);
                al[im][1] = lds32(alr + 8 * GF_PITCH);
                al[im][2] = lds32(alr + 16);
                al[im][3] = lds32(alr + 8 * GF_PITCH + 16);
            }
#pragma unroll
            for (int jn = 0; jn < 8; jn++) {
                const int n0 = (jn < 4) ? wn * 32 + jn * 8 : 128 + wn * 32 + (jn - 4) * 8;
                uint32_t br  = wh + (uint32_t)n0 * GF_PITCH + kf * 32;
                uint32_t blr = wl + (uint32_t)n0 * GF_PITCH + kf * 32;
                uint32_t bh0 = lds32(br),  bh1 = lds32(br + 16);
                uint32_t bl0 = lds32(blr), bl1 = lds32(blr + 16);
#pragma unroll
                for (int im = 0; im < 2; im++) {
                    mma_bf16(c[im][jn], ah[im], bh0, bh1);
                    mma_bf16(c[im][jn], ah[im], bl0, bl1);
                    mma_bf16(c[im][jn], al[im], bh0, bh1);
                }
            }
        }
        __syncthreads();
    }

    // epilogue: h = (fc + bfc) * sigmoid(gate + bg)
    const int rr = rb + wm * 32 + (lane >> 2);
#pragma unroll
    for (int im = 0; im < 2; im++) {
#pragma unroll
        for (int jn = 0; jn < 4; jn++) {
            const int n0 = wn * 32 + jn * 8 + 2 * (lane & 3);
            float2 bf  = *(const float2*)&bfc[n0];
            float2 bg2 = *(const float2*)&bg[n0];
            int r0 = rr + im * 16, r1 = r0 + 8;
            float2 h0, h1;
            h0.x = (c[im][jn][0] + bf.x) * sigmoidf_(c[im][jn + 4][0] + bg2.x);
            h0.y = (c[im][jn][1] + bf.y) * sigmoidf_(c[im][jn + 4][1] + bg2.y);
            h1.x = (c[im][jn][2] + bf.x) * sigmoidf_(c[im][jn + 4][2] + bg2.x);
            h1.y = (c[im][jn][3] + bf.y) * sigmoidf_(c[im][jn + 4][3] + bg2.y);
            *(float2*)&g_H[(size_t)r0 * DH + n0] = h0;
            *(float2*)&g_H[(size_t)r1 * DH + n0] = h1;
        }
    }
}

// ---------------------------------------------------------------------------
// Kernel B: QKV projections (scalar). K written packed+padded+tf32-rounded.
// ---------------------------------------------------------------------------
__global__ void __launch_bounds__(256) qkv_kernel(
    const float* __restrict__ Wq, const float* __restrict__ bq,
    const float* __restrict__ Wk, const float* __restrict__ bk,
    const float* __restrict__ Wv, const float* __restrict__ bv)
{
    __shared__ float hs[64][32];
    __shared__ float ws[32][DH];

    const int t  = threadIdx.x;
    const int rb = blockIdx.x * 64;
    const int m  = blockIdx.y;
    const int tx = t % 32;
    const int ty = t / 32;

    const float* W = (m == 0) ? Wq : (m == 1) ? Wk : Wv;
    const float* b = (m == 0) ? bq : (m == 1) ? bk : bv;

    float acc[8][4];
#pragma unroll
    for (int i = 0; i < 8; i++)
#pragma unroll
        for (int j = 0; j < 4; j++) acc[i][j] = 0.f;

    for (int k0 = 0; k0 < DH; k0 += 32) {
#pragma unroll
        for (int i = 0; i < 2; i++) {
            int s = t + 256 * i;
            int r = s / 8, c4 = s % 8;
            *(float4*)&hs[r][c4 * 4] = *(const float4*)&g_H[(size_t)(rb + r) * DH + k0 + c4 * 4];
        }
#pragma unroll
        for (int i = 0; i < 4; i++) {
            int s = t + 256 * i;
            int r = s / 32, c4 = s % 32;
            *(float4*)&ws[r][c4 * 4] = *(const float4*)&W[(size_t)(k0 + r) * DH + c4 * 4];
        }
        __syncthreads();

#pragma unroll 8
        for (int kk = 0; kk < 32; kk++) {
            float4 w4 = *(const float4*)&ws[kk][tx * 4];
#pragma unroll
            for (int i = 0; i < 8; i++) {
                float hv = hs[ty * 8 + i][kk];
                acc[i][0] = fmaf(hv, w4.x, acc[i][0]);
                acc[i][1] = fmaf(hv, w4.y, acc[i][1]);
                acc[i][2] = fmaf(hv, w4.z, acc[i][2]);
                acc[i][3] = fmaf(hv, w4.w, acc[i][3]);
            }
        }
        __syncthreads();
    }

    float4 bv4 = *(const float4*)&b[tx * 4];
#pragma unroll
    for (int i = 0; i < 8; i++) {
        int r = rb + ty * 8 + i;
        float4 o;
        o.x = acc[i][0] + bv4.x;
        o.y = acc[i][1] + bv4.y;
        o.z = acc[i][2] + bv4.z;
        o.w = acc[i][3] + bv4.w;
        if (m == 1) {
            o.x = to_tf32(o.x); o.y = to_tf32(o.y);
            o.z = to_tf32(o.z); o.w = to_tf32(o.w);
            int tt = r >> 6, rr = r & 63;
            *(float4*)(g_Kp + (size_t)tt * 33792 + rr * 528 + tx * 16) = o;
        } else {
            float* Out = (m == 0) ? g_Q : g_V;
            *(float4*)&Out[(size_t)r * DH + tx * 4] = o;
        }
    }
}

// ---------------------------------------------------------------------------
// Kernel C: U = V @ W_out
// ---------------------------------------------------------------------------
__global__ void __launch_bounds__(256) u_kernel(const float* __restrict__ Wout)
{
    int i = blockIdx.x * 256 + threadIdx.x;
    const float4* wp = (const float4*)Wout;
    float s = 0.f;
#pragma unroll
    for (int d4 = 0; d4 < DH / 4; d4++) {
        float4 v = *(const float4*)&g_V[(size_t)i * DH + d4 * 4];
        float4 w = __ldg(&wp[d4]);
        s = fmaf(v.x, w.x, s);
        s = fmaf(v.y, w.y, s);
        s = fmaf(v.z, w.z, s);
        s = fmaf(v.w, w.w, s);
    }
    g_U[i] = s;
}

// ---------------------------------------------------------------------------
// Kernel D: flash attention, mma.sync tf32, bulk K loads, pipelined epilogue.
// ---------------------------------------------------------------------------
#define KT 64
#define NT (4096 / KT)
#define KROW 132
#define SM_K0   0
#define SM_K1   33792
#define SM_U    67584
#define SM_RN   83968
#define SM_RD   84992
#define SM_MB   86016
#define SMEM_ATTN 86144

__device__ __forceinline__ void attn_epilogue(const float c[2][4][4], const float* us,
                                              int wn, int lane, float num[4], float den[4])
{
#pragma unroll
    for (int jn = 0; jn < 4; jn++) {
        const int c0 = wn * 32 + jn * 8 + 2 * (lane & 3);
        const float2 uv = *(const float2*)&us[c0];
#pragma unroll
        for (int im = 0; im < 2; im++) {
            float e0 = ex2f_(c[im][jn][0]);
            float e1 = ex2f_(c[im][jn][1]);
            float e2 = ex2f_(c[im][jn][2]);
            float e3 = ex2f_(c[im][jn][3]);
            num[im * 2 + 0] = fmaf(e0, uv.x, num[im * 2 + 0]);
            num[im * 2 + 0] = fmaf(e1, uv.y, num[im * 2 + 0]);
            den[im * 2 + 0] += e0 + e1;
            num[im * 2 + 1] = fmaf(e2, uv.x, num[im * 2 + 1]);
            num[im * 2 + 1] = fmaf(e3, uv.y, num[im * 2 + 1]);
            den[im * 2 + 1] += e2 + e3;
        }
    }
}

__global__ void __launch_bounds__(256, 1) attn_mma_kernel()
{
    extern __shared__ char smem[];
    const uint32_t sb = smem_u32(smem);
    const int tid  = threadIdx.x;
    const int lane = tid & 31;
    const int wid  = tid >> 5;
    const int wm   = wid >> 1;
    const int wn   = wid & 1;
    const int qb   = blockIdx.x;
    const int sp   = blockIdx.y;
    const int j_base = sp * 4096;
    const int t_base = sp * 64;   // K tile index base

    if (tid == 0) {
        MBARRIER_INIT(sb + SM_MB, 1);
        MBARRIER_INIT(sb + SM_MB + 8, 1);
    }

#pragma unroll
    for (int i = 0; i < 4; i++) {
        int s = tid + 256 * i;
        *(float4*)(smem + SM_U + s * 16) = *(const float4*)&g_U[j_base + s * 4];
    }
    __syncthreads();

    if (tid == 0) {
        MBARRIER_EXPECT_TX(sb + SM_MB, 33792);
        bulk_g2s(sb + SM_K0, g_Kp + (size_t)t_base * 33792, 33792, sb + SM_MB);
    }

    const float QS = 0.1275174341917854f;   // log2(e)/sqrt(128)
    uint32_t qa[2][16][4];
    {
        const float* qp = g_Q + (size_t)(qb * 128 + wm * 32) * DH;
        const int r = lane >> 2, cc = lane & 3;
#pragma unroll
        for (int im = 0; im < 2; im++) {
#pragma unroll
            for (int kf = 0; kf < 16; kf++) {
                const float* base = qp + (size_t)(im * 16 + r) * DH + kf * 8 + cc;
                qa[im][kf][0] = __float_as_uint(to_tf32(base[0] * QS));
                qa[im][kf][1] = __float_as_uint(to_tf32(base[8 * DH] * QS));
                qa[im][kf][2] = __float_as_uint(to_tf32(base[4] * QS));
                qa[im][kf][3] = __float_as_uint(to_tf32(base[8 * DH + 4] * QS));
            }
        }
    }

    float num[4] = {0.f, 0.f, 0.f, 0.f};
    float den[4] = {0.f, 0.f, 0.f, 0.f};
    float cbuf[2][2][4][4];

    const uint32_t bbase = sb + (uint32_t)(wn * 32 + (lane >> 2)) * (KROW * 4)
                         + (uint32_t)(lane & 3) * 4;

#pragma unroll 1
    for (int t = 0; t < NT; t++) {
        if (t + 1 < NT && tid == 0) {
            const int nb = (t + 1) & 1;
            const uint32_t mb = sb + SM_MB + 8 * nb;
            MBARRIER_EXPECT_TX(mb, 33792);
            bulk_g2s(sb + (nb ? SM_K1 : SM_K0),
                     g_Kp + (size_t)(t_base + t + 1) * 33792, 33792, mb);
        }
        MBARRIER_WAIT_PARITY(sb + SM_MB + 8 * (t & 1), (t >> 1) & 1);

        const uint32_t kb = bbase + ((t & 1) ? SM_K1 : SM_K0);
        float (*c)[4][4] = cbuf[t & 1];
#pragma unroll
        for (int im = 0; im < 2; im++)
#pragma unroll
            for (int jn = 0; jn < 4; jn++)
#pragma unroll
                for (int v = 0; v < 4; v++) c[im][jn][v] = 0.f;

#pragma unroll
        for (int kf = 0; kf < 16; kf++) {
#pragma unroll
            for (int jn = 0; jn < 4; jn++) {
                uint32_t addr = kb + (uint32_t)jn * (8 * KROW * 4) + (uint32_t)kf * 32;
                uint32_t b0 = lds32(addr);
                uint32_t b1 = lds32(addr + 16);
                mma_16x8x8(c[0][jn], qa[0][kf], b0, b1);
                mma_16x8x8(c[1][jn], qa[1][kf], b0, b1);
            }
        }

        if (t > 0) {
            const float* us = (const float*)(smem + SM_U) + (t - 1) * KT;
            attn_epilogue(cbuf[(t - 1) & 1], us, wn, lane, num, den);
        }
        __syncthreads();
    }
    {
        const float* us = (const float*)(smem + SM_U) + (NT - 1) * KT;
        attn_epilogue(cbuf[(NT - 1) & 1], us, wn, lane, num, den);
    }

#pragma unroll
    for (int s = 0; s < 4; s++) {
        num[s] += __shfl_xor_sync(0xffffffffu, num[s], 1);
        num[s] += __shfl_xor_sync(0xffffffffu, num[s], 2);
        den[s] += __shfl_xor_sync(0xffffffffu, den[s], 1);
        den[s] += __shfl_xor_sync(0xffffffffu, den[s], 2);
    }
    if ((lane & 3) == 0) {
        float* rn = (float*)(smem + SM_RN);
        float* rd = (float*)(smem + SM_RD);
#pragma unroll
        for (int s = 0; s < 4; s++) {
            int row = wm * 32 + (s >> 1) * 16 + (s & 1) * 8 + (lane >> 2);
            rn[wn * 128 + row] = num[s];
            rd[wn * 128 + row] = den[s];
        }
    }
    __syncthreads();
    if (tid < 128) {
        const float* rn = (const float*)(smem + SM_RN);
        const float* rd = (const float*)(smem + SM_RD);
        g_PN[sp * NROWS + qb * 128 + tid] = rn[tid] + rn[128 + tid];
        g_PD[sp * NROWS + qb * 128 + tid] = rd[tid] + rd[128 + tid];
    }
}

// ---------------------------------------------------------------------------
// Kernel E: combine splits
// ---------------------------------------------------------------------------
__global__ void __launch_bounds__(256) combine_kernel(const float* __restrict__ bout,
                                                      float* __restrict__ out)
{
    int i = blockIdx.x * 256 + threadIdx.x;
    float n = g_PN[i] + g_PN[NROWS + i];
    float d = g_PD[i] + g_PD[NROWS + i];
    out[i] = n / d + __ldg(bout);
}

// ---------------------------------------------------------------------------
extern "C" void kernel_launch(void* const* d_in, const int* in_sizes, int n_in,
                              void* d_out, int out_size)
{
    const float* x    = (const float*)d_in[0];
    const float* Wfc  = (const float*)d_in[1];
    const float* bfc  = (const float*)d_in[2];
    const float* Wg   = (const float*)d_in[3];
    const float* bg   = (const float*)d_in[4];
    const float* Wq   = (const float*)d_in[5];
    const float* bq   = (const float*)d_in[6];
    const float* Wk   = (const float*)d_in[7];
    const float* bk   = (const float*)d_in[8];
    const float* Wv   = (const float*)d_in[9];
    const float* bv   = (const float*)d_in[10];
    const float* Wout = (const float*)d_in[11];
    const float* bout = (const float*)d_in[12];
    float* out = (float*)d_out;

    cudaFuncSetAttribute(attn_mma_kernel, cudaFuncAttributeMaxDynamicSharedMemorySize, SMEM_ATTN);
    cudaFuncSetAttribute(gated_fc_mma_kernel, cudaFuncAttributeMaxDynamicSharedMemorySize, GF_SMEM);

    cvt_x_kernel<<<NROWS * DIN / 1024, 256>>>(x);
    cvt_w_kernel<<<256 * DIN / 256, 256>>>(Wfc, Wg);
    gated_fc_mma_kernel<<<NROWS / 64, 256, GF_SMEM>>>(bfc, bg);
    qkv_kernel<<<dim3(NROWS / 64, 3), 256>>>(Wq, bq, Wk, bk, Wv, bv);
    u_kernel<<<NROWS / 256, 256>>>(Wout);
    attn_mma_kernel<<<dim3(NROWS / 128, 2), 256, SMEM_ATTN>>>();
    combine_kernel<<<NROWS / 256, 256>>>(bout, out);
}

// round 9
// speedup vs baseline: 4.5087x; 1.0902x over previous
#include <cuda_runtime.h>
#include <cuda_bf16.h>
#include <cstdint>

#define NROWS 8192
#define DIN   1024
#define DH    128

// ---------------------------------------------------------------------------
// Scratch
// ---------------------------------------------------------------------------
__device__ float g_Q[NROWS * DH];
__device__ float g_U[NROWS];
__device__ float g_PN[2 * NROWS];
__device__ float g_PD[2 * NROWS];
// Packed K for attn: 128 tiles of [64 rows][544 B] (paired-k perm layout)
__device__ __align__(1024) char g_Kp[128 * 34816];
// Packed x hi/lo: per (rowblock 64, stage 32k): [hi 64x80B][lo 64x80B]
__device__ __align__(1024) char g_xp[128 * 32 * 10240];
// Packed W_fc|W_gate hi/lo per stage: [wh 256x80B][wl 256x80B]
__device__ __align__(1024) char g_wp[32 * 40960];
// Packed H hi/lo: per (rowblock 64, stage 32k of DH): [hi 64x80B][lo 64x80B]
__device__ __align__(1024) char g_hp[128 * 4 * 10240];
// Packed W_qkv hi/lo per stage (k of DH): [wh 384x80B][wl 384x80B]
__device__ __align__(1024) char g_wqp[4 * 61440];

__device__ __forceinline__ float sigmoidf_(float z) {
    return 1.0f / (1.0f + __expf(-z));
}
__device__ __forceinline__ uint32_t smem_u32(const void* p) {
    uint32_t a;
    asm("{ .reg .u64 t; cvta.to.shared.u64 t, %1; cvt.u32.u64 %0, t; }" : "=r"(a) : "l"(p));
    return a;
}
__device__ __forceinline__ float to_tf32(float x) {
    float r; asm("cvt.rna.tf32.f32 %0, %1;" : "=f"(r) : "f"(x)); return r;
}
__device__ __forceinline__ uint32_t lds32(uint32_t addr) {
    uint32_t v; asm volatile("ld.shared.b32 %0, [%1];" : "=r"(v) : "r"(addr)); return v;
}
__device__ __forceinline__ void lds64(uint32_t& a, uint32_t& b, uint32_t addr) {
    asm volatile("ld.shared.v2.b32 {%0,%1}, [%2];" : "=r"(a), "=r"(b) : "r"(addr));
}
__device__ __forceinline__ void mma_16x8x8(float c[4], const uint32_t a[4],
                                           uint32_t b0, uint32_t b1) {
    asm volatile(
        "mma.sync.aligned.m16n8k8.row.col.f32.tf32.tf32.f32 "
        "{%0,%1,%2,%3}, {%4,%5,%6,%7}, {%8,%9}, {%0,%1,%2,%3};"
        : "+f"(c[0]), "+f"(c[1]), "+f"(c[2]), "+f"(c[3])
        : "r"(a[0]), "r"(a[1]), "r"(a[2]), "r"(a[3]), "r"(b0), "r"(b1));
}
__device__ __forceinline__ void mma_bf16(float c[4], const uint32_t a[4],
                                         uint32_t b0, uint32_t b1) {
    asm volatile(
        "mma.sync.aligned.m16n8k16.row.col.f32.bf16.bf16.f32 "
        "{%0,%1,%2,%3}, {%4,%5,%6,%7}, {%8,%9}, {%0,%1,%2,%3};"
        : "+f"(c[0]), "+f"(c[1]), "+f"(c[2]), "+f"(c[3])
        : "r"(a[0]), "r"(a[1]), "r"(a[2]), "r"(a[3]), "r"(b0), "r"(b1));
}
__device__ __forceinline__ float ex2f_(float x) {
    float r; asm("ex2.approx.f32 %0, %1;" : "=f"(r) : "f"(x)); return r;
}
__device__ __forceinline__ void bulk_g2s(uint32_t dst, const void* src,
                                         uint32_t bytes, uint32_t mbar) {
    asm volatile(
        "cp.async.bulk.shared::cluster.global.mbarrier::complete_tx::bytes [%0], [%1], %2, [%3];"
        :: "r"(dst), "l"(src), "r"(bytes), "r"(mbar) : "memory");
}
#define MBARRIER_INIT(addr, cnt) \
    asm volatile("mbarrier.init.shared.b64 [%0], %1;" :: "r"(addr), "r"(cnt) : "memory")
#define MBARRIER_EXPECT_TX(addr, bytes) \
    asm volatile("mbarrier.arrive.expect_tx.shared.b64 _, [%0], %1;" \
                 :: "r"(addr), "r"(bytes) : "memory")
#define MBARRIER_WAIT_PARITY(addr, ph) do {                                    \
    uint32_t _m = (uint32_t)(addr);                                            \
    uint32_t _p = (uint32_t)(ph);                                              \
    uint32_t _d;                                                               \
    asm volatile("{\n\t.reg .pred p;\n\t"                                      \
        "mbarrier.try_wait.parity.acquire.cta.shared::cta.b64 p, [%1], %2;\n\t"\
        "selp.b32 %0, 1, 0, p;\n\t}" : "=r"(_d) : "r"(_m), "r"(_p) : "memory");\
    if (!_d) {                                                                 \
        asm volatile("{\n\t.reg .pred P1;\n\t"                                 \
            "WL_%=:\n\t"                                                       \
            "mbarrier.try_wait.parity.acquire.cta.shared::cta.b64 P1, [%0], %1, 0x989680;\n\t" \
            "@P1 bra.uni WD_%=;\n\t"                                           \
            "bra.uni WL_%=;\n\t"                                               \
            "WD_%=:\n\t}" :: "r"(_m), "r"(_p) : "memory");                     \
    }                                                                          \
} while (0)

// paired-k permuted byte offset within a K row (k in 0..127)
__device__ __forceinline__ uint32_t k_perm_off(int k) {
    return (uint32_t)((k >> 3) * 32 + (k & 3) * 8 + ((k >> 2) & 1) * 4);
}

// ---------------------------------------------------------------------------
// Prekernel: x -> packed bf16 hi/lo tiles
// ---------------------------------------------------------------------------
__global__ void __launch_bounds__(256) cvt_x_kernel(const float* __restrict__ x)
{
    int i = (blockIdx.x * 256 + threadIdx.x) * 4;
    int row = i >> 10, k = i & 1023;
    float4 v = *(const float4*)&x[i];
    __nv_bfloat16 h0 = __float2bfloat16(v.x);
    __nv_bfloat16 h1 = __float2bfloat16(v.y);
    __nv_bfloat16 h2 = __float2bfloat16(v.z);
    __nv_bfloat16 h3 = __float2bfloat16(v.w);
    __nv_bfloat16 l0 = __float2bfloat16(v.x - __bfloat162float(h0));
    __nv_bfloat16 l1 = __float2bfloat16(v.y - __bfloat162float(h1));
    __nv_bfloat16 l2 = __float2bfloat16(v.z - __bfloat162float(h2));
    __nv_bfloat16 l3 = __float2bfloat16(v.w - __bfloat162float(h3));
    int rb = row >> 6, r = row & 63, stage = k >> 5, kk = k & 31;
    size_t base = (size_t)(rb * 32 + stage) * 10240 + r * 80 + kk * 2;
    uint32_t hp0 = ((uint32_t)__bfloat16_as_ushort(h1) << 16) | __bfloat16_as_ushort(h0);
    uint32_t hp1 = ((uint32_t)__bfloat16_as_ushort(h3) << 16) | __bfloat16_as_ushort(h2);
    uint32_t lp0 = ((uint32_t)__bfloat16_as_ushort(l1) << 16) | __bfloat16_as_ushort(l0);
    uint32_t lp1 = ((uint32_t)__bfloat16_as_ushort(l3) << 16) | __bfloat16_as_ushort(l2);
    *(uint2*)(g_xp + base)        = make_uint2(hp0, hp1);
    *(uint2*)(g_xp + base + 5120) = make_uint2(lp0, lp1);
}

// ---------------------------------------------------------------------------
// Prekernel: W_fc|W_gate -> packed bf16 hi/lo tiles, transposed to [n][k]
// ---------------------------------------------------------------------------
__global__ void __launch_bounds__(256) cvt_w_kernel(const float* __restrict__ Wfc,
                                                    const float* __restrict__ Wg)
{
    int idx = blockIdx.x * 256 + threadIdx.x;   // n*1024 + k
    int n = idx >> 10, k = idx & 1023;
    float v = (n < 128) ? Wfc[(size_t)k * DH + n] : Wg[(size_t)k * DH + (n - 128)];
    __nv_bfloat16 h = __float2bfloat16(v);
    __nv_bfloat16 l = __float2bfloat16(v - __bfloat162float(h));
    int stage = k >> 5, kk = k & 31;
    size_t base = (size_t)stage * 40960 + n * 80 + kk * 2;
    *(__nv_bfloat16*)(g_wp + base)         = h;
    *(__nv_bfloat16*)(g_wp + base + 20480) = l;
}

// ---------------------------------------------------------------------------
// Prekernel: W_q|W_k|W_v -> packed bf16 hi/lo tiles, transposed to [n][k]
// ---------------------------------------------------------------------------
__global__ void __launch_bounds__(256) cvt_wqkv_kernel(const float* __restrict__ Wq,
                                                       const float* __restrict__ Wk,
                                                       const float* __restrict__ Wv)
{
    int idx = blockIdx.x * 256 + threadIdx.x;   // n*128 + k, 384*128 total
    int n = idx >> 7, k = idx & 127;
    float v = (n < 128) ? Wq[(size_t)k * DH + n]
            : (n < 256) ? Wk[(size_t)k * DH + (n - 128)]
                        : Wv[(size_t)k * DH + (n - 256)];
    __nv_bfloat16 h = __float2bfloat16(v);
    __nv_bfloat16 l = __float2bfloat16(v - __bfloat162float(h));
    int stage = k >> 5, kk = k & 31;
    size_t base = (size_t)stage * 61440 + n * 80 + kk * 2;
    *(__nv_bfloat16*)(g_wqp + base)         = h;
    *(__nv_bfloat16*)(g_wqp + base + 30720) = l;
}

// ---------------------------------------------------------------------------
// Kernel A: gated linear, bf16 3-term MMA; writes H as packed bf16 hi/lo.
// ---------------------------------------------------------------------------
#define GF_PITCH 80
#define GF_BUF   51200
#define GF_XH(b)  ((b) * GF_BUF + 0)
#define GF_XL(b)  ((b) * GF_BUF + 5120)
#define GF_WH(b)  ((b) * GF_BUF + 10240)
#define GF_WL(b)  ((b) * GF_BUF + 30720)
#define GF_MBAR   (2 * GF_BUF)
#define GF_SMEM   (2 * GF_BUF + 64)

__global__ void __launch_bounds__(256, 1) gated_fc_mma_kernel(
    const float* __restrict__ bfc, const float* __restrict__ bg)
{
    extern __shared__ char smem[];
    const uint32_t sb = smem_u32(smem);
    const int tid  = threadIdx.x;
    const int lane = tid & 31;
    const int wid  = tid >> 5;
    const int wm   = wid & 1;
    const int wn   = wid >> 1;

    if (tid == 0) {
        MBARRIER_INIT(sb + GF_MBAR, 1);
        MBARRIER_INIT(sb + GF_MBAR + 8, 1);
    }
    __syncthreads();

    float c[2][8][4];
#pragma unroll
    for (int im = 0; im < 2; im++)
#pragma unroll
        for (int jn = 0; jn < 8; jn++)
#pragma unroll
            for (int v = 0; v < 4; v++) c[im][jn][v] = 0.f;

    if (tid == 0) {
        MBARRIER_EXPECT_TX(sb + GF_MBAR, 51200);
        bulk_g2s(sb + GF_XH(0), g_xp + (size_t)(blockIdx.x * 32) * 10240, 10240, sb + GF_MBAR);
        bulk_g2s(sb + GF_WH(0), g_wp, 40960, sb + GF_MBAR);
    }

    const uint32_t a_off  = (uint32_t)(wm * 32 + (lane >> 2)) * GF_PITCH + (lane & 3) * 4;
    const uint32_t b_lane = (uint32_t)(lane >> 2) * GF_PITCH + (lane & 3) * 4;

#pragma unroll 1
    for (int s = 0; s < 32; s++) {
        if (s + 1 < 32 && tid == 0) {
            const int nb = (s + 1) & 1;
            const uint32_t mb = sb + GF_MBAR + 8 * nb;
            MBARRIER_EXPECT_TX(mb, 51200);
            bulk_g2s(sb + GF_XH(nb), g_xp + (size_t)(blockIdx.x * 32 + s + 1) * 10240, 10240, mb);
            bulk_g2s(sb + GF_WH(nb), g_wp + (size_t)(s + 1) * 40960, 40960, mb);
        }
        MBARRIER_WAIT_PARITY(sb + GF_MBAR + 8 * (s & 1), (s >> 1) & 1);

        const int buf = s & 1;
        const uint32_t xh = sb + GF_XH(buf) + a_off;
        const uint32_t xl = sb + GF_XL(buf) + a_off;
        const uint32_t wh = sb + GF_WH(buf) + b_lane;
        const uint32_t wl = sb + GF_WL(buf) + b_lane;

#pragma unroll
        for (int kf = 0; kf < 2; kf++) {
            uint32_t ah[2][4], al[2][4];
#pragma unroll
            for (int im = 0; im < 2; im++) {
                uint32_t ar  = xh + (uint32_t)im * (16 * GF_PITCH) + kf * 32;
                uint32_t alr = xl + (uint32_t)im * (16 * GF_PITCH) + kf * 32;
                ah[im][0] = lds32(ar);
                ah[im][1] = lds32(ar + 8 * GF_PITCH);
                ah[im][2] = lds32(ar + 16);
                ah[im][3] = lds32(ar + 8 * GF_PITCH + 16);
                al[im][0] = lds32(alr);
                al[im][1] = lds32(alr + 8 * GF_PITCH);
                al[im][2] = lds32(alr + 16);
                al[im][3] = lds32(alr + 8 * GF_PITCH + 16);
            }
#pragma unroll
            for (int jn = 0; jn < 8; jn++) {
                const int n0 = (jn < 4) ? wn * 32 + jn * 8 : 128 + wn * 32 + (jn - 4) * 8;
                uint32_t br  = wh + (uint32_t)n0 * GF_PITCH + kf * 32;
                uint32_t blr = wl + (uint32_t)n0 * GF_PITCH + kf * 32;
                uint32_t bh0 = lds32(br),  bh1 = lds32(br + 16);
                uint32_t bl0 = lds32(blr), bl1 = lds32(blr + 16);
#pragma unroll
                for (int im = 0; im < 2; im++) {
                    mma_bf16(c[im][jn], ah[im], bh0, bh1);
                    mma_bf16(c[im][jn], ah[im], bl0, bl1);
                    mma_bf16(c[im][jn], al[im], bh0, bh1);
                }
            }
        }
        __syncthreads();
    }

    // epilogue: h = (fc + bfc) * sigmoid(gate + bg) -> packed bf16 hi/lo tiles
#pragma unroll
    for (int im = 0; im < 2; im++) {
#pragma unroll
        for (int jn = 0; jn < 4; jn++) {
            const int n0 = wn * 32 + jn * 8 + 2 * (lane & 3);
            float2 bf  = *(const float2*)&bfc[n0];
            float2 bg2 = *(const float2*)&bg[n0];
            float2 h0, h1;
            h0.x = (c[im][jn][0] + bf.x) * sigmoidf_(c[im][jn + 4][0] + bg2.x);
            h0.y = (c[im][jn][1] + bf.y) * sigmoidf_(c[im][jn + 4][1] + bg2.y);
            h1.x = (c[im][jn][2] + bf.x) * sigmoidf_(c[im][jn + 4][2] + bg2.x);
            h1.y = (c[im][jn][3] + bf.y) * sigmoidf_(c[im][jn + 4][3] + bg2.y);
            const int r0 = wm * 32 + (lane >> 2) + im * 16;   // row within block of 64
            const int stage = n0 >> 5, kk = n0 & 31;
            char* tb = g_hp + ((size_t)blockIdx.x * 4 + stage) * 10240 + kk * 2;
#pragma unroll
            for (int hh = 0; hh < 2; hh++) {
                float2 hv = hh ? h1 : h0;
                int r = r0 + hh * 8;
                __nv_bfloat16 b0 = __float2bfloat16(hv.x);
                __nv_bfloat16 b1 = __float2bfloat16(hv.y);
                __nv_bfloat16 c0 = __float2bfloat16(hv.x - __bfloat162float(b0));
                __nv_bfloat16 c1 = __float2bfloat16(hv.y - __bfloat162float(b1));
                *(uint32_t*)(tb + r * 80) =
                    ((uint32_t)__bfloat16_as_ushort(b1) << 16) | __bfloat16_as_ushort(b0);
                *(uint32_t*)(tb + r * 80 + 5120) =
                    ((uint32_t)__bfloat16_as_ushort(c1) << 16) | __bfloat16_as_ushort(c0);
            }
        }
    }
}

// ---------------------------------------------------------------------------
// Kernel B: fused QKV + U, bf16 3-term MMA.
// N = 384 cols: [0,128) Q, [128,256) K, [256,384) V (V folded into U).
// grid 128 (64 rows/CTA), 256 threads (wm 2 x wn 4, 96 cols each).
// ---------------------------------------------------------------------------
#define QV_BUF   71680
#define QV_XH(b)  ((b) * QV_BUF + 0)
#define QV_XL(b)  ((b) * QV_BUF + 5120)
#define QV_WH(b)  ((b) * QV_BUF + 10240)
#define QV_WL(b)  ((b) * QV_BUF + 40960)
#define QV_MBAR   (2 * QV_BUF)
#define QV_UPART  (2 * QV_BUF + 64)
#define QV_SMEM   (2 * QV_BUF + 64 + 256)

__global__ void __launch_bounds__(256, 1) qkv_mma_kernel(
    const float* __restrict__ bq, const float* __restrict__ bk,
    const float* __restrict__ bv, const float* __restrict__ Wout)
{
    extern __shared__ char smem[];
    const uint32_t sb = smem_u32(smem);
    float* u_part = (float*)(smem + QV_UPART);
    const int tid  = threadIdx.x;
    const int lane = tid & 31;
    const int wid  = tid >> 5;
    const int wm   = wid & 1;
    const int wn   = wid >> 1;
    const int rb   = blockIdx.x * 64;

    if (tid == 0) {
        MBARRIER_INIT(sb + QV_MBAR, 1);
        MBARRIER_INIT(sb + QV_MBAR + 8, 1);
    }
    if (tid < 64) u_part[tid] = 0.f;
    __syncthreads();

    float c[2][12][4];
#pragma unroll
    for (int im = 0; im < 2; im++)
#pragma unroll
        for (int jn = 0; jn < 12; jn++)
#pragma unroll
            for (int v = 0; v < 4; v++) c[im][jn][v] = 0.f;

    if (tid == 0) {
        MBARRIER_EXPECT_TX(sb + QV_MBAR, QV_BUF);
        bulk_g2s(sb + QV_XH(0), g_hp + (size_t)(blockIdx.x * 4) * 10240, 10240, sb + QV_MBAR);
        bulk_g2s(sb + QV_WH(0), g_wqp, 61440, sb + QV_MBAR);
    }

    const uint32_t a_off  = (uint32_t)(wm * 32 + (lane >> 2)) * GF_PITCH + (lane & 3) * 4;
    const uint32_t b_lane = (uint32_t)(lane >> 2) * GF_PITCH + (lane & 3) * 4;

#pragma unroll 1
    for (int s = 0; s < 4; s++) {
        if (s + 1 < 4 && tid == 0) {
            const int nb = (s + 1) & 1;
            const uint32_t mb = sb + QV_MBAR + 8 * nb;
            MBARRIER_EXPECT_TX(mb, QV_BUF);
            bulk_g2s(sb + QV_XH(nb), g_hp + (size_t)(blockIdx.x * 4 + s + 1) * 10240, 10240, mb);
            bulk_g2s(sb + QV_WH(nb), g_wqp + (size_t)(s + 1) * 61440, 61440, mb);
        }
        MBARRIER_WAIT_PARITY(sb + QV_MBAR + 8 * (s & 1), (s >> 1) & 1);

        const int buf = s & 1;
        const uint32_t xh = sb + QV_XH(buf) + a_off;
        const uint32_t xl = sb + QV_XL(buf) + a_off;
        const uint32_t wh = sb + QV_WH(buf) + b_lane;
        const uint32_t wl = sb + QV_WL(buf) + b_lane;

#pragma unroll
        for (int kf = 0; kf < 2; kf++) {
            uint32_t ah[2][4], al[2][4];
#pragma unroll
            for (int im = 0; im < 2; im++) {
                uint32_t ar  = xh + (uint32_t)im * (16 * GF_PITCH) + kf * 32;
                uint32_t alr = xl + (uint32_t)im * (16 * GF_PITCH) + kf * 32;
                ah[im][0] = lds32(ar);
                ah[im][1] = lds32(ar + 8 * GF_PITCH);
                ah[im][2] = lds32(ar + 16);
                ah[im][3] = lds32(ar + 8 * GF_PITCH + 16);
                al[im][0] = lds32(alr);
                al[im][1] = lds32(alr + 8 * GF_PITCH);
                al[im][2] = lds32(alr + 16);
                al[im][3] = lds32(alr + 8 * GF_PITCH + 16);
            }
#pragma unroll
            for (int jn = 0; jn < 12; jn++) {
                const int n0 = wn * 96 + jn * 8;
                uint32_t br  = wh + (uint32_t)n0 * GF_PITCH + kf * 32;
                uint32_t blr = wl + (uint32_t)n0 * GF_PITCH + kf * 32;
                uint32_t bh0 = lds32(br),  bh1 = lds32(br + 16);
                uint32_t bl0 = lds32(blr), bl1 = lds32(blr + 16);
#pragma unroll
                for (int im = 0; im < 2; im++) {
                    mma_bf16(c[im][jn], ah[im], bh0, bh1);
                    mma_bf16(c[im][jn], ah[im], bl0, bl1);
                    mma_bf16(c[im][jn], al[im], bh0, bh1);
                }
            }
        }
        __syncthreads();
    }

    // epilogue: Q store / K packed tf32 store / V -> U partials
    float up[4] = {0.f, 0.f, 0.f, 0.f};
#pragma unroll
    for (int im = 0; im < 2; im++) {
#pragma unroll
        for (int jn = 0; jn < 12; jn++) {
            const int n0 = wn * 96 + jn * 8 + 2 * (lane & 3);
            const int r0 = rb + wm * 32 + (lane >> 2) + im * 16;
            if (n0 < 128) {
                float2 bq2 = *(const float2*)&bq[n0];
                float2 q0 = make_float2(c[im][jn][0] + bq2.x, c[im][jn][1] + bq2.y);
                float2 q1 = make_float2(c[im][jn][2] + bq2.x, c[im][jn][3] + bq2.y);
                *(float2*)&g_Q[(size_t)r0 * DH + n0] = q0;
                *(float2*)&g_Q[(size_t)(r0 + 8) * DH + n0] = q1;
            } else if (n0 < 256) {
                const int kc = n0 - 128;
                float2 bk2 = *(const float2*)&bk[kc];
                uint32_t o0 = k_perm_off(kc), o1 = k_perm_off(kc + 1);
#pragma unroll
                for (int hh = 0; hh < 2; hh++) {
                    int r = r0 + hh * 8;
                    char* kb = g_Kp + (size_t)(r >> 6) * 34816 + (r & 63) * 544;
                    *(float*)(kb + o0) = to_tf32(c[im][jn][hh * 2 + 0] + bk2.x);
                    *(float*)(kb + o1) = to_tf32(c[im][jn][hh * 2 + 1] + bk2.y);
                }
            } else {
                const int vc = n0 - 256;
                float2 bv2 = *(const float2*)&bv[vc];
                float2 w2  = *(const float2*)&Wout[vc];
                up[im * 2 + 0] += (c[im][jn][0] + bv2.x) * w2.x + (c[im][jn][1] + bv2.y) * w2.y;
                up[im * 2 + 1] += (c[im][jn][2] + bv2.x) * w2.x + (c[im][jn][3] + bv2.y) * w2.y;
            }
        }
    }
    if (wn >= 2) {   // only warps owning V columns
#pragma unroll
        for (int s = 0; s < 4; s++) {
            up[s] += __shfl_xor_sync(0xffffffffu, up[s], 1);
            up[s] += __shfl_xor_sync(0xffffffffu, up[s], 2);
        }
        if ((lane & 3) == 0) {
#pragma unroll
            for (int s = 0; s < 4; s++) {
                int row = wm * 32 + (lane >> 2) + (s >> 1) * 16 + (s & 1) * 8;
                atomicAdd(&u_part[row], up[s]);
            }
        }
    }
    __syncthreads();
    if (tid < 64) g_U[rb + tid] = u_part[tid];
}

// ---------------------------------------------------------------------------
// Kernel D: flash attention, mma.sync tf32, 512 threads (16 warps),
// bulk K loads (pitch-544 paired-k layout), lds64 B fragments,
// pipelined epilogue.
// ---------------------------------------------------------------------------
#define KT 64
#define NT (4096 / KT)
#define KPITCH 544
#define KTILE  34816
#define SM_K0   0
#define SM_K1   34816
#define SM_U    69632
#define SM_RN   86016
#define SM_RD   87040
#define SM_MB   88064
#define SMEM_ATTN 88128

__device__ __forceinline__ void attn_epilogue(const float c[4][4], const float* us,
                                              int wn, int lane, float num[2], float den[2])
{
#pragma unroll
    for (int jn = 0; jn < 4; jn++) {
        const int c0 = wn * 32 + jn * 8 + 2 * (lane & 3);
        const float2 uv = *(const float2*)&us[c0];
        float e0 = ex2f_(c[jn][0]);
        float e1 = ex2f_(c[jn][1]);
        float e2 = ex2f_(c[jn][2]);
        float e3 = ex2f_(c[jn][3]);
        num[0] = fmaf(e0, uv.x, num[0]);
        num[0] = fmaf(e1, uv.y, num[0]);
        den[0] += e0 + e1;
        num[1] = fmaf(e2, uv.x, num[1]);
        num[1] = fmaf(e3, uv.y, num[1]);
        den[1] += e2 + e3;
    }
}

__global__ void __launch_bounds__(512, 1) attn_mma_kernel()
{
    extern __shared__ char smem[];
    const uint32_t sb = smem_u32(smem);
    const int tid  = threadIdx.x;
    const int lane = tid & 31;
    const int wid  = tid >> 5;
    const int wm   = wid >> 1;     // 0..7, 16 q-rows each
    const int wn   = wid & 1;      // 0..1, 32 k-cols each
    const int qb   = blockIdx.x;
    const int sp   = blockIdx.y;
    const int j_base = sp * 4096;
    const int t_base = sp * 64;

    if (tid == 0) {
        MBARRIER_INIT(sb + SM_MB, 1);
        MBARRIER_INIT(sb + SM_MB + 8, 1);
    }
#pragma unroll
    for (int i = 0; i < 2; i++) {
        int s = tid + 512 * i;
        *(float4*)(smem + SM_U + s * 16) = *(const float4*)&g_U[j_base + s * 4];
    }
    __syncthreads();

    if (tid == 0) {
        MBARRIER_EXPECT_TX(sb + SM_MB, KTILE);
        bulk_g2s(sb + SM_K0, g_Kp + (size_t)t_base * KTILE, KTILE, sb + SM_MB);
    }

    const float QS = 0.1275174341917854f;   // log2(e)/sqrt(128)
    uint32_t qa[16][4];
    {
        const float* qp = g_Q + (size_t)(qb * 128 + wm * 16) * DH;
        const int r = lane >> 2, cc = lane & 3;
#pragma unroll
        for (int kf = 0; kf < 16; kf++) {
            const float* base = qp + (size_t)r * DH + kf * 8 + cc;
            qa[kf][0] = __float_as_uint(to_tf32(base[0] * QS));
            qa[kf][1] = __float_as_uint(to_tf32(base[8 * DH] * QS));
            qa[kf][2] = __float_as_uint(to_tf32(base[4] * QS));
            qa[kf][3] = __float_as_uint(to_tf32(base[8 * DH + 4] * QS));
        }
    }

    float num[2] = {0.f, 0.f};
    float den[2] = {0.f, 0.f};
    float cbuf[2][4][4];

    // B row base: n = wn*32 + jn*8 + (lane>>2); within row: kf*32 + (lane&3)*8
    const uint32_t bbase = sb + (uint32_t)(wn * 32 + (lane >> 2)) * KPITCH
                         + (uint32_t)(lane & 3) * 8;

#pragma unroll 1
    for (int t = 0; t < NT; t++) {
        if (t + 1 < NT && tid == 0) {
            const int nb = (t + 1) & 1;
            const uint32_t mb = sb + SM_MB + 8 * nb;
            MBARRIER_EXPECT_TX(mb, KTILE);
            bulk_g2s(sb + (nb ? SM_K1 : SM_K0),
                     g_Kp + (size_t)(t_base + t + 1) * KTILE, KTILE, mb);
        }
        MBARRIER_WAIT_PARITY(sb + SM_MB + 8 * (t & 1), (t >> 1) & 1);

        const uint32_t kb = bbase + ((t & 1) ? SM_K1 : SM_K0);
        float (*c)[4] = cbuf[t & 1];
#pragma unroll
        for (int jn = 0; jn < 4; jn++)
#pragma unroll
            for (int v = 0; v < 4; v++) c[jn][v] = 0.f;

#pragma unroll
        for (int kf = 0; kf < 16; kf++) {
#pragma unroll
            for (int jn = 0; jn < 4; jn++) {
                uint32_t b0, b1;
                lds64(b0, b1, kb + (uint32_t)jn * (8 * KPITCH) + (uint32_t)kf * 32);
                mma_16x8x8(c[jn], qa[kf], b0, b1);
            }
        }

        if (t > 0) {
            const float* us = (const float*)(smem + SM_U) + (t - 1) * KT;
            attn_epilogue(cbuf[(t - 1) & 1], us, wn, lane, num, den);
        }
        __syncthreads();
    }
    {
        const float* us = (const float*)(smem + SM_U) + (NT - 1) * KT;
        attn_epilogue(cbuf[(NT - 1) & 1], us, wn, lane, num, den);
    }

#pragma unroll
    for (int s = 0; s < 2; s++) {
        num[s] += __shfl_xor_sync(0xffffffffu, num[s], 1);
        num[s] += __shfl_xor_sync(0xffffffffu, num[s], 2);
        den[s] += __shfl_xor_sync(0xffffffffu, den[s], 1);
        den[s] += __shfl_xor_sync(0xffffffffu, den[s], 2);
    }
    if ((lane & 3) == 0) {
        float* rn = (float*)(smem + SM_RN);
        float* rd = (float*)(smem + SM_RD);
        int row = wm * 16 + (lane >> 2);
        rn[wn * 128 + row]     = num[0];
        rd[wn * 128 + row]     = den[0];
        rn[wn * 128 + row + 8] = num[1];
        rd[wn * 128 + row + 8] = den[1];
    }
    __syncthreads();
    if (tid < 128) {
        const float* rn = (const float*)(smem + SM_RN);
        const float* rd = (const float*)(smem + SM_RD);
        g_PN[sp * NROWS + qb * 128 + tid] = rn[tid] + rn[128 + tid];
        g_PD[sp * NROWS + qb * 128 + tid] = rd[tid] + rd[128 + tid];
    }
}

// ---------------------------------------------------------------------------
// Kernel E: combine splits
// ---------------------------------------------------------------------------
__global__ void __launch_bounds__(256) combine_kernel(const float* __restrict__ bout,
                                                      float* __restrict__ out)
{
    int i = blockIdx.x * 256 + threadIdx.x;
    float n = g_PN[i] + g_PN[NROWS + i];
    float d = g_PD[i] + g_PD[NROWS + i];
    out[i] = n / d + __ldg(bout);
}

// ---------------------------------------------------------------------------
extern "C" void kernel_launch(void* const* d_in, const int* in_sizes, int n_in,
                              void* d_out, int out_size)
{
    const float* x    = (const float*)d_in[0];
    const float* Wfc  = (const float*)d_in[1];
    const float* bfc  = (const float*)d_in[2];
    const float* Wg   = (const float*)d_in[3];
    const float* bg   = (const float*)d_in[4];
    const float* Wq   = (const float*)d_in[5];
    const float* bq   = (const float*)d_in[6];
    const float* Wk   = (const float*)d_in[7];
    const float* bk   = (const float*)d_in[8];
    const float* Wv   = (const float*)d_in[9];
    const float* bv   = (const float*)d_in[10];
    const float* Wout = (const float*)d_in[11];
    const float* bout = (const float*)d_in[12];
    float* out = (float*)d_out;

    cudaFuncSetAttribute(attn_mma_kernel, cudaFuncAttributeMaxDynamicSharedMemorySize, SMEM_ATTN);
    cudaFuncSetAttribute(gated_fc_mma_kernel, cudaFuncAttributeMaxDynamicSharedMemorySize, GF_SMEM);
    cudaFuncSetAttribute(qkv_mma_kernel, cudaFuncAttributeMaxDynamicSharedMemorySize, QV_SMEM);

    cvt_x_kernel<<<NROWS * DIN / 1024, 256>>>(x);
    cvt_w_kernel<<<256 * DIN / 256, 256>>>(Wfc, Wg);
    cvt_wqkv_kernel<<<384 * DH / 256, 256>>>(Wq, Wk, Wv);
    gated_fc_mma_kernel<<<NROWS / 64, 256, GF_SMEM>>>(bfc, bg);
    qkv_mma_kernel<<<NROWS / 64, 256, QV_SMEM>>>(bq, bk, bv, Wout);
    attn_mma_kernel<<<dim3(NROWS / 128, 2), 512, SMEM_ATTN>>>();
    combine_kernel<<<NROWS / 256, 256>>>(bout, out);
}

// round 11
// speedup vs baseline: 5.4139x; 1.2008x over previous
#include <cuda_runtime.h>
#include <cuda_bf16.h>
#include <cuda_fp16.h>
#include <cstdint>

#define NROWS 8192
#define DIN   1024
#define DH    128

// ---------------------------------------------------------------------------
// Scratch
// ---------------------------------------------------------------------------
__device__ float g_Q[NROWS * DH];
__device__ float g_U[NROWS];
__device__ float g_PN[2 * NROWS];
__device__ float g_PD[2 * NROWS];
// Packed K (f16, paired-k perm): 64 tiles of [128 rows][288 B]
__device__ __align__(1024) char g_Kp[64 * 36864];
// Packed x hi/lo: per (rowblock 64, stage 32k): [hi 64x80B][lo 64x80B]
__device__ __align__(1024) char g_xp[128 * 32 * 10240];
// Packed W_fc|W_gate hi/lo per stage: [wh 256x80B][wl 256x80B]
__device__ __align__(1024) char g_wp[32 * 40960];
// Packed H hi/lo: per (rowblock 64, stage 32k of DH): [hi 64x80B][lo 64x80B]
__device__ __align__(1024) char g_hp[128 * 4 * 10240];
// Packed W_qkv hi/lo per stage (k of DH): [wh 384x80B][wl 384x80B]
__device__ __align__(1024) char g_wqp[4 * 61440];

__device__ __forceinline__ float sigmoidf_(float z) {
    return 1.0f / (1.0f + __expf(-z));
}
__device__ __forceinline__ uint32_t smem_u32(const void* p) {
    uint32_t a;
    asm("{ .reg .u64 t; cvta.to.shared.u64 t, %1; cvt.u32.u64 %0, t; }" : "=r"(a) : "l"(p));
    return a;
}
__device__ __forceinline__ uint32_t pack_h2(float x, float y) {
    __half2 h = __floats2half2_rn(x, y);
    return *(uint32_t*)&h;
}
__device__ __forceinline__ uint32_t lds32(uint32_t addr) {
    uint32_t v; asm volatile("ld.shared.b32 %0, [%1];" : "=r"(v) : "r"(addr)); return v;
}
__device__ __forceinline__ void lds64(uint32_t& a, uint32_t& b, uint32_t addr) {
    asm volatile("ld.shared.v2.b32 {%0,%1}, [%2];" : "=r"(a), "=r"(b) : "r"(addr));
}
__device__ __forceinline__ void mma_f16(float c[4], const uint32_t a[4],
                                        uint32_t b0, uint32_t b1) {
    asm volatile(
        "mma.sync.aligned.m16n8k16.row.col.f32.f16.f16.f32 "
        "{%0,%1,%2,%3}, {%4,%5,%6,%7}, {%8,%9}, {%0,%1,%2,%3};"
        : "+f"(c[0]), "+f"(c[1]), "+f"(c[2]), "+f"(c[3])
        : "r"(a[0]), "r"(a[1]), "r"(a[2]), "r"(a[3]), "r"(b0), "r"(b1));
}
__device__ __forceinline__ void mma_bf16(float c[4], const uint32_t a[4],
                                         uint32_t b0, uint32_t b1) {
    asm volatile(
        "mma.sync.aligned.m16n8k16.row.col.f32.bf16.bf16.f32 "
        "{%0,%1,%2,%3}, {%4,%5,%6,%7}, {%8,%9}, {%0,%1,%2,%3};"
        : "+f"(c[0]), "+f"(c[1]), "+f"(c[2]), "+f"(c[3])
        : "r"(a[0]), "r"(a[1]), "r"(a[2]), "r"(a[3]), "r"(b0), "r"(b1));
}
__device__ __forceinline__ float ex2f_(float x) {
    float r; asm("ex2.approx.f32 %0, %1;" : "=f"(r) : "f"(x)); return r;
}
__device__ __forceinline__ void bulk_g2s(uint32_t dst, const void* src,
                                         uint32_t bytes, uint32_t mbar) {
    asm volatile(
        "cp.async.bulk.shared::cluster.global.mbarrier::complete_tx::bytes [%0], [%1], %2, [%3];"
        :: "r"(dst), "l"(src), "r"(bytes), "r"(mbar) : "memory");
}
#define MBARRIER_INIT(addr, cnt) \
    asm volatile("mbarrier.init.shared.b64 [%0], %1;" :: "r"(addr), "r"(cnt) : "memory")
#define MBARRIER_EXPECT_TX(addr, bytes) \
    asm volatile("mbarrier.arrive.expect_tx.shared.b64 _, [%0], %1;" \
                 :: "r"(addr), "r"(bytes) : "memory")
#define MBARRIER_WAIT_PARITY(addr, ph) do {                                    \
    uint32_t _m = (uint32_t)(addr);                                            \
    uint32_t _p = (uint32_t)(ph);                                              \
    uint32_t _d;                                                               \
    asm volatile("{\n\t.reg .pred p;\n\t"                                      \
        "mbarrier.try_wait.parity.acquire.cta.shared::cta.b64 p, [%1], %2;\n\t"\
        "selp.b32 %0, 1, 0, p;\n\t}" : "=r"(_d) : "r"(_m), "r"(_p) : "memory");\
    if (!_d) {                                                                 \
        asm volatile("{\n\t.reg .pred P1;\n\t"                                 \
            "WL_%=:\n\t"                                                       \
            "mbarrier.try_wait.parity.acquire.cta.shared::cta.b64 P1, [%0], %1, 0x989680;\n\t" \
            "@P1 bra.uni WD_%=;\n\t"                                           \
            "bra.uni WL_%=;\n\t"                                               \
            "WD_%=:\n\t}" :: "r"(_m), "r"(_p) : "memory");                     \
    }                                                                          \
} while (0)

// paired-k byte offset of element k (even) within a 288B K row:
// 8-byte slot c=(k&7)>>1 of group k>>4 holds k = {2c,2c+1,2c+8,2c+9}
__device__ __forceinline__ uint32_t kh_off(int k) {
    return (uint32_t)((k >> 4) * 32 + ((k & 7) >> 1) * 8 + ((k >> 3) & 1) * 4);
}

// ---------------------------------------------------------------------------
// Prekernel: x -> packed bf16 hi/lo tiles
// ---------------------------------------------------------------------------
__global__ void __launch_bounds__(256) cvt_x_kernel(const float* __restrict__ x)
{
    int i = (blockIdx.x * 256 + threadIdx.x) * 4;
    int row = i >> 10, k = i & 1023;
    float4 v = *(const float4*)&x[i];
    __nv_bfloat16 h0 = __float2bfloat16(v.x);
    __nv_bfloat16 h1 = __float2bfloat16(v.y);
    __nv_bfloat16 h2 = __float2bfloat16(v.z);
    __nv_bfloat16 h3 = __float2bfloat16(v.w);
    __nv_bfloat16 l0 = __float2bfloat16(v.x - __bfloat162float(h0));
    __nv_bfloat16 l1 = __float2bfloat16(v.y - __bfloat162float(h1));
    __nv_bfloat16 l2 = __float2bfloat16(v.z - __bfloat162float(h2));
    __nv_bfloat16 l3 = __float2bfloat16(v.w - __bfloat162float(h3));
    int rb = row >> 6, r = row & 63, stage = k >> 5, kk = k & 31;
    size_t base = (size_t)(rb * 32 + stage) * 10240 + r * 80 + kk * 2;
    uint32_t hp0 = ((uint32_t)__bfloat16_as_ushort(h1) << 16) | __bfloat16_as_ushort(h0);
    uint32_t hp1 = ((uint32_t)__bfloat16_as_ushort(h3) << 16) | __bfloat16_as_ushort(h2);
    uint32_t lp0 = ((uint32_t)__bfloat16_as_ushort(l1) << 16) | __bfloat16_as_ushort(l0);
    uint32_t lp1 = ((uint32_t)__bfloat16_as_ushort(l3) << 16) | __bfloat16_as_ushort(l2);
    *(uint2*)(g_xp + base)        = make_uint2(hp0, hp1);
    *(uint2*)(g_xp + base + 5120) = make_uint2(lp0, lp1);
}

// ---------------------------------------------------------------------------
// Prekernel: W_fc|W_gate -> packed bf16 hi/lo tiles, transposed to [n][k]
// ---------------------------------------------------------------------------
__global__ void __launch_bounds__(256) cvt_w_kernel(const float* __restrict__ Wfc,
                                                    const float* __restrict__ Wg)
{
    int idx = blockIdx.x * 256 + threadIdx.x;   // n*1024 + k
    int n = idx >> 10, k = idx & 1023;
    float v = (n < 128) ? Wfc[(size_t)k * DH + n] : Wg[(size_t)k * DH + (n - 128)];
    __nv_bfloat16 h = __float2bfloat16(v);
    __nv_bfloat16 l = __float2bfloat16(v - __bfloat162float(h));
    int stage = k >> 5, kk = k & 31;
    size_t base = (size_t)stage * 40960 + n * 80 + kk * 2;
    *(__nv_bfloat16*)(g_wp + base)         = h;
    *(__nv_bfloat16*)(g_wp + base + 20480) = l;
}

// ---------------------------------------------------------------------------
// Prekernel: W_q|W_k|W_v -> packed bf16 hi/lo tiles, transposed to [n][k]
// ---------------------------------------------------------------------------
__global__ void __launch_bounds__(256) cvt_wqkv_kernel(const float* __restrict__ Wq,
                                                       const float* __restrict__ Wk,
                                                       const float* __restrict__ Wv)
{
    int idx = blockIdx.x * 256 + threadIdx.x;   // n*128 + k, 384*128 total
    int n = idx >> 7, k = idx & 127;
    float v = (n < 128) ? Wq[(size_t)k * DH + n]
            : (n < 256) ? Wk[(size_t)k * DH + (n - 128)]
                        : Wv[(size_t)k * DH + (n - 256)];
    __nv_bfloat16 h = __float2bfloat16(v);
    __nv_bfloat16 l = __float2bfloat16(v - __bfloat162float(h));
    int stage = k >> 5, kk = k & 31;
    size_t base = (size_t)stage * 61440 + n * 80 + kk * 2;
    *(__nv_bfloat16*)(g_wqp + base)         = h;
    *(__nv_bfloat16*)(g_wqp + base + 30720) = l;
}

// ---------------------------------------------------------------------------
// Kernel A: gated linear, bf16 3-term MMA, 512 threads (16 warps: wm4 x wn4).
// ---------------------------------------------------------------------------
#define GF_PITCH 80
#define GF_BUF   51200
#define GF_XH(b)  ((b) * GF_BUF + 0)
#define GF_XL(b)  ((b) * GF_BUF + 5120)
#define GF_WH(b)  ((b) * GF_BUF + 10240)
#define GF_WL(b)  ((b) * GF_BUF + 30720)
#define GF_MBAR   (2 * GF_BUF)
#define GF_SMEM   (2 * GF_BUF + 64)

__global__ void __launch_bounds__(512, 1) gated_fc_mma_kernel(
    const float* __restrict__ bfc, const float* __restrict__ bg)
{
    extern __shared__ char smem[];
    const uint32_t sb = smem_u32(smem);
    const int tid  = threadIdx.x;
    const int lane = tid & 31;
    const int wid  = tid >> 5;
    const int wm   = wid & 3;        // 16 rows each
    const int wn   = wid >> 2;       // 0..3, 32 fc + 32 gate cols

    if (tid == 0) {
        MBARRIER_INIT(sb + GF_MBAR, 1);
        MBARRIER_INIT(sb + GF_MBAR + 8, 1);
    }
    __syncthreads();

    float c[8][4];
#pragma unroll
    for (int jn = 0; jn < 8; jn++)
#pragma unroll
        for (int v = 0; v < 4; v++) c[jn][v] = 0.f;

    if (tid == 0) {
        MBARRIER_EXPECT_TX(sb + GF_MBAR, 51200);
        bulk_g2s(sb + GF_XH(0), g_xp + (size_t)(blockIdx.x * 32) * 10240, 10240, sb + GF_MBAR);
        bulk_g2s(sb + GF_WH(0), g_wp, 40960, sb + GF_MBAR);
    }

    const uint32_t a_off  = (uint32_t)(wm * 16 + (lane >> 2)) * GF_PITCH + (lane & 3) * 4;
    const uint32_t b_lane = (uint32_t)(lane >> 2) * GF_PITCH + (lane & 3) * 4;

#pragma unroll 1
    for (int s = 0; s < 32; s++) {
        if (s + 1 < 32 && tid == 0) {
            const int nb = (s + 1) & 1;
            const uint32_t mb = sb + GF_MBAR + 8 * nb;
            MBARRIER_EXPECT_TX(mb, 51200);
            bulk_g2s(sb + GF_XH(nb), g_xp + (size_t)(blockIdx.x * 32 + s + 1) * 10240, 10240, mb);
            bulk_g2s(sb + GF_WH(nb), g_wp + (size_t)(s + 1) * 40960, 40960, mb);
        }
        MBARRIER_WAIT_PARITY(sb + GF_MBAR + 8 * (s & 1), (s >> 1) & 1);

        const int buf = s & 1;
        const uint32_t xh = sb + GF_XH(buf) + a_off;
        const uint32_t xl = sb + GF_XL(buf) + a_off;
        const uint32_t wh = sb + GF_WH(buf) + b_lane;
        const uint32_t wl = sb + GF_WL(buf) + b_lane;

#pragma unroll
        for (int kf = 0; kf < 2; kf++) {
            uint32_t ah[4], al[4];
            {
                uint32_t ar  = xh + kf * 32;
                uint32_t alr = xl + kf * 32;
                ah[0] = lds32(ar);
                ah[1] = lds32(ar + 8 * GF_PITCH);
                ah[2] = lds32(ar + 16);
                ah[3] = lds32(ar + 8 * GF_PITCH + 16);
                al[0] = lds32(alr);
                al[1] = lds32(alr + 8 * GF_PITCH);
                al[2] = lds32(alr + 16);
                al[3] = lds32(alr + 8 * GF_PITCH + 16);
            }
#pragma unroll
            for (int jn = 0; jn < 8; jn++) {
                const int n0 = (jn < 4) ? wn * 32 + jn * 8 : 128 + wn * 32 + (jn - 4) * 8;
                uint32_t br  = wh + (uint32_t)n0 * GF_PITCH + kf * 32;
                uint32_t blr = wl + (uint32_t)n0 * GF_PITCH + kf * 32;
                uint32_t bh0 = lds32(br),  bh1 = lds32(br + 16);
                uint32_t bl0 = lds32(blr), bl1 = lds32(blr + 16);
                mma_bf16(c[jn], ah, bh0, bh1);
                mma_bf16(c[jn], ah, bl0, bl1);
                mma_bf16(c[jn], al, bh0, bh1);
            }
        }
        __syncthreads();
    }

    // epilogue: h = (fc + bfc) * sigmoid(gate + bg) -> packed bf16 hi/lo tiles
#pragma unroll
    for (int jn = 0; jn < 4; jn++) {
        const int n0 = wn * 32 + jn * 8 + 2 * (lane & 3);
        float2 bf  = *(const float2*)&bfc[n0];
        float2 bg2 = *(const float2*)&bg[n0];
        float2 h0, h1;
        h0.x = (c[jn][0] + bf.x) * sigmoidf_(c[jn + 4][0] + bg2.x);
        h0.y = (c[jn][1] + bf.y) * sigmoidf_(c[jn + 4][1] + bg2.y);
        h1.x = (c[jn][2] + bf.x) * sigmoidf_(c[jn + 4][2] + bg2.x);
        h1.y = (c[jn][3] + bf.y) * sigmoidf_(c[jn + 4][3] + bg2.y);
        const int r0 = wm * 16 + (lane >> 2);
        const int stage = n0 >> 5, kk = n0 & 31;
        char* tb = g_hp + ((size_t)blockIdx.x * 4 + stage) * 10240 + kk * 2;
#pragma unroll
        for (int hh = 0; hh < 2; hh++) {
            float2 hv = hh ? h1 : h0;
            int r = r0 + hh * 8;
            __nv_bfloat16 b0 = __float2bfloat16(hv.x);
            __nv_bfloat16 b1 = __float2bfloat16(hv.y);
            __nv_bfloat16 c0 = __float2bfloat16(hv.x - __bfloat162float(b0));
            __nv_bfloat16 c1 = __float2bfloat16(hv.y - __bfloat162float(b1));
            *(uint32_t*)(tb + r * 80) =
                ((uint32_t)__bfloat16_as_ushort(b1) << 16) | __bfloat16_as_ushort(b0);
            *(uint32_t*)(tb + r * 80 + 5120) =
                ((uint32_t)__bfloat16_as_ushort(c1) << 16) | __bfloat16_as_ushort(c0);
        }
    }
}

// ---------------------------------------------------------------------------
// Kernel B: fused QKV + U, bf16 3-term MMA. K written as f16 pairs (perm).
// ---------------------------------------------------------------------------
#define QV_BUF   71680
#define QV_XH(b)  ((b) * QV_BUF + 0)
#define QV_XL(b)  ((b) * QV_BUF + 5120)
#define QV_WH(b)  ((b) * QV_BUF + 10240)
#define QV_WL(b)  ((b) * QV_BUF + 40960)
#define QV_MBAR   (2 * QV_BUF)
#define QV_UPART  (2 * QV_BUF + 64)
#define QV_SMEM   (2 * QV_BUF + 64 + 256)

__global__ void __launch_bounds__(256, 1) qkv_mma_kernel(
    const float* __restrict__ bq, const float* __restrict__ bk,
    const float* __restrict__ bv, const float* __restrict__ Wout)
{
    extern __shared__ char smem[];
    const uint32_t sb = smem_u32(smem);
    float* u_part = (float*)(smem + QV_UPART);
    const int tid  = threadIdx.x;
    const int lane = tid & 31;
    const int wid  = tid >> 5;
    const int wm   = wid & 1;
    const int wn   = wid >> 1;
    const int rb   = blockIdx.x * 64;

    if (tid == 0) {
        MBARRIER_INIT(sb + QV_MBAR, 1);
        MBARRIER_INIT(sb + QV_MBAR + 8, 1);
    }
    if (tid < 64) u_part[tid] = 0.f;
    __syncthreads();

    float c[2][12][4];
#pragma unroll
    for (int im = 0; im < 2; im++)
#pragma unroll
        for (int jn = 0; jn < 12; jn++)
#pragma unroll
            for (int v = 0; v < 4; v++) c[im][jn][v] = 0.f;

    if (tid == 0) {
        MBARRIER_EXPECT_TX(sb + QV_MBAR, QV_BUF);
        bulk_g2s(sb + QV_XH(0), g_hp + (size_t)(blockIdx.x * 4) * 10240, 10240, sb + QV_MBAR);
        bulk_g2s(sb + QV_WH(0), g_wqp, 61440, sb + QV_MBAR);
    }

    const uint32_t a_off  = (uint32_t)(wm * 32 + (lane >> 2)) * GF_PITCH + (lane & 3) * 4;
    const uint32_t b_lane = (uint32_t)(lane >> 2) * GF_PITCH + (lane & 3) * 4;

#pragma unroll 1
    for (int s = 0; s < 4; s++) {
        if (s + 1 < 4 && tid == 0) {
            const int nb = (s + 1) & 1;
            const uint32_t mb = sb + QV_MBAR + 8 * nb;
            MBARRIER_EXPECT_TX(mb, QV_BUF);
            bulk_g2s(sb + QV_XH(nb), g_hp + (size_t)(blockIdx.x * 4 + s + 1) * 10240, 10240, mb);
            bulk_g2s(sb + QV_WH(nb), g_wqp + (size_t)(s + 1) * 61440, 61440, mb);
        }
        MBARRIER_WAIT_PARITY(sb + QV_MBAR + 8 * (s & 1), (s >> 1) & 1);

        const int buf = s & 1;
        const uint32_t xh = sb + QV_XH(buf) + a_off;
        const uint32_t xl = sb + QV_XL(buf) + a_off;
        const uint32_t wh = sb + QV_WH(buf) + b_lane;
        const uint32_t wl = sb + QV_WL(buf) + b_lane;

#pragma unroll
        for (int kf = 0; kf < 2; kf++) {
            uint32_t ah[2][4], al[2][4];
#pragma unroll
            for (int im = 0; im < 2; im++) {
                uint32_t ar  = xh + (uint32_t)im * (16 * GF_PITCH) + kf * 32;
                uint32_t alr = xl + (uint32_t)im * (16 * GF_PITCH) + kf * 32;
                ah[im][0] = lds32(ar);
                ah[im][1] = lds32(ar + 8 * GF_PITCH);
                ah[im][2] = lds32(ar + 16);
                ah[im][3] = lds32(ar + 8 * GF_PITCH + 16);
                al[im][0] = lds32(alr);
                al[im][1] = lds32(alr + 8 * GF_PITCH);
                al[im][2] = lds32(alr + 16);
                al[im][3] = lds32(alr + 8 * GF_PITCH + 16);
            }
#pragma unroll
            for (int jn = 0; jn < 12; jn++) {
                const int n0 = wn * 96 + jn * 8;
                uint32_t br  = wh + (uint32_t)n0 * GF_PITCH + kf * 32;
                uint32_t blr = wl + (uint32_t)n0 * GF_PITCH + kf * 32;
                uint32_t bh0 = lds32(br),  bh1 = lds32(br + 16);
                uint32_t bl0 = lds32(blr), bl1 = lds32(blr + 16);
#pragma unroll
                for (int im = 0; im < 2; im++) {
                    mma_bf16(c[im][jn], ah[im], bh0, bh1);
                    mma_bf16(c[im][jn], ah[im], bl0, bl1);
                    mma_bf16(c[im][jn], al[im], bh0, bh1);
                }
            }
        }
        __syncthreads();
    }

    // epilogue: Q store / K f16 perm store / V -> U partials
    float up[4] = {0.f, 0.f, 0.f, 0.f};
#pragma unroll
    for (int im = 0; im < 2; im++) {
#pragma unroll
        for (int jn = 0; jn < 12; jn++) {
            const int n0 = wn * 96 + jn * 8 + 2 * (lane & 3);
            const int r0 = rb + wm * 32 + (lane >> 2) + im * 16;
            if (n0 < 128) {
                float2 bq2 = *(const float2*)&bq[n0];
                float2 q0 = make_float2(c[im][jn][0] + bq2.x, c[im][jn][1] + bq2.y);
                float2 q1 = make_float2(c[im][jn][2] + bq2.x, c[im][jn][3] + bq2.y);
                *(float2*)&g_Q[(size_t)r0 * DH + n0] = q0;
                *(float2*)&g_Q[(size_t)(r0 + 8) * DH + n0] = q1;
            } else if (n0 < 256) {
                const int kc = n0 - 128;   // even
                float2 bk2 = *(const float2*)&bk[kc];
                const uint32_t off = kh_off(kc);
#pragma unroll
                for (int hh = 0; hh < 2; hh++) {
                    int r = r0 + hh * 8;
                    char* kb = g_Kp + (size_t)(r >> 7) * 36864 + (r & 127) * 288;
                    *(uint32_t*)(kb + off) =
                        pack_h2(c[im][jn][hh * 2 + 0] + bk2.x, c[im][jn][hh * 2 + 1] + bk2.y);
                }
            } else {
                const int vc = n0 - 256;
                float2 bv2 = *(const float2*)&bv[vc];
                float2 w2  = *(const float2*)&Wout[vc];
                up[im * 2 + 0] += (c[im][jn][0] + bv2.x) * w2.x + (c[im][jn][1] + bv2.y) * w2.y;
                up[im * 2 + 1] += (c[im][jn][2] + bv2.x) * w2.x + (c[im][jn][3] + bv2.y) * w2.y;
            }
        }
    }
    if (wn >= 2) {
#pragma unroll
        for (int s = 0; s < 4; s++) {
            up[s] += __shfl_xor_sync(0xffffffffu, up[s], 1);
            up[s] += __shfl_xor_sync(0xffffffffu, up[s], 2);
        }
        if ((lane & 3) == 0) {
#pragma unroll
            for (int s = 0; s < 4; s++) {
                int row = wm * 32 + (lane >> 2) + (s >> 1) * 16 + (s & 1) * 8;
                atomicAdd(&u_part[row], up[s]);
            }
        }
    }
    __syncthreads();
    if (tid < 64) g_U[rb + tid] = u_part[tid];
}

// ---------------------------------------------------------------------------
// Kernel D: flash attention, mma.sync f16 m16n8k16, 512 threads,
// KT=128 rows/tile (pitch 288, paired-k), bulk loads, pipelined epilogue.
// ---------------------------------------------------------------------------
#define KT 128
#define NT (4096 / KT)
#define KPITCH 288
#define KTILE  36864
#define SM_K0   0
#define SM_K1   36864
#define SM_U    73728
#define SM_RN   90112
#define SM_RD   91136
#define SM_MB   92160
#define SMEM_ATTN 92224

__device__ __forceinline__ void attn_epilogue(const float c[8][4], const float* us,
                                              int wn, int lane, float num[2], float den[2])
{
#pragma unroll
    for (int jn = 0; jn < 8; jn++) {
        const int c0 = wn * 64 + jn * 8 + 2 * (lane & 3);
        const float2 uv = *(const float2*)&us[c0];
        float e0 = ex2f_(c[jn][0]);
        float e1 = ex2f_(c[jn][1]);
        float e2 = ex2f_(c[jn][2]);
        float e3 = ex2f_(c[jn][3]);
        num[0] = fmaf(e0, uv.x, num[0]);
        num[0] = fmaf(e1, uv.y, num[0]);
        den[0] += e0 + e1;
        num[1] = fmaf(e2, uv.x, num[1]);
        num[1] = fmaf(e3, uv.y, num[1]);
        den[1] += e2 + e3;
    }
}

__global__ void __launch_bounds__(512, 1) attn_mma_kernel()
{
    extern __shared__ char smem[];
    const uint32_t sb = smem_u32(smem);
    const int tid  = threadIdx.x;
    const int lane = tid & 31;
    const int wid  = tid >> 5;
    const int wm   = wid >> 1;     // 0..7, 16 q-rows each
    const int wn   = wid & 1;      // 0..1, 64 k-cols each
    const int qb   = blockIdx.x;
    const int sp   = blockIdx.y;
    const int j_base = sp * 4096;
    const int t_base = sp * NT;

    if (tid == 0) {
        MBARRIER_INIT(sb + SM_MB, 1);
        MBARRIER_INIT(sb + SM_MB + 8, 1);
    }
#pragma unroll
    for (int i = 0; i < 2; i++) {
        int s = tid + 512 * i;
        *(float4*)(smem + SM_U + s * 16) = *(const float4*)&g_U[j_base + s * 4];
    }
    __syncthreads();

    if (tid == 0) {
        MBARRIER_EXPECT_TX(sb + SM_MB, KTILE);
        bulk_g2s(sb + SM_K0, g_Kp + (size_t)t_base * KTILE, KTILE, sb + SM_MB);
    }

    const float QS = 0.1275174341917854f;   // log2(e)/sqrt(128)
    uint32_t qa[8][4];
    {
        const float* qp = g_Q + (size_t)(qb * 128 + wm * 16) * DH;
        const int r = lane >> 2, c2 = (lane & 3) * 2;
#pragma unroll
        for (int kf = 0; kf < 8; kf++) {
            const float* base = qp + (size_t)r * DH + kf * 16 + c2;
            qa[kf][0] = pack_h2(base[0] * QS, base[1] * QS);
            qa[kf][1] = pack_h2(base[8 * DH] * QS, base[8 * DH + 1] * QS);
            qa[kf][2] = pack_h2(base[8] * QS, base[9] * QS);
            qa[kf][3] = pack_h2(base[8 * DH + 8] * QS, base[8 * DH + 9] * QS);
        }
    }

    float num[2] = {0.f, 0.f};
    float den[2] = {0.f, 0.f};
    float cbuf[2][8][4];

    // B row (token) = wn*64 + jn*8 + (lane>>2); slot (lane&3)*8 within kf*32
    const uint32_t bbase = sb + (uint32_t)(wn * 64 + (lane >> 2)) * KPITCH
                         + (uint32_t)(lane & 3) * 8;

#pragma unroll 1
    for (int t = 0; t < NT; t++) {
        if (t + 1 < NT && tid == 0) {
            const int nb = (t + 1) & 1;
            const uint32_t mb = sb + SM_MB + 8 * nb;
            MBARRIER_EXPECT_TX(mb, KTILE);
            bulk_g2s(sb + (nb ? SM_K1 : SM_K0),
                     g_Kp + (size_t)(t_base + t + 1) * KTILE, KTILE, mb);
        }
        MBARRIER_WAIT_PARITY(sb + SM_MB + 8 * (t & 1), (t >> 1) & 1);

        const uint32_t kb = bbase + ((t & 1) ? SM_K1 : SM_K0);
        float (*c)[4] = cbuf[t & 1];
#pragma unroll
        for (int jn = 0; jn < 8; jn++)
#pragma unroll
            for (int v = 0; v < 4; v++) c[jn][v] = 0.f;

#pragma unroll
        for (int kf = 0; kf < 8; kf++) {
#pragma unroll
            for (int jn = 0; jn < 8; jn++) {
                uint32_t b0, b1;
                lds64(b0, b1, kb + (uint32_t)jn * (8 * KPITCH) + (uint32_t)kf * 32);
                mma_f16(c[jn], qa[kf], b0, b1);
            }
        }

        if (t > 0) {
            const float* us = (const float*)(smem + SM_U) + (t - 1) * KT;
            attn_epilogue(cbuf[(t - 1) & 1], us, wn, lane, num, den);
        }
        __syncthreads();
    }
    {
        const float* us = (const float*)(smem + SM_U) + (NT - 1) * KT;
        attn_epilogue(cbuf[(NT - 1) & 1], us, wn, lane, num, den);
    }

#pragma unroll
    for (int s = 0; s < 2; s++) {
        num[s] += __shfl_xor_sync(0xffffffffu, num[s], 1);
        num[s] += __shfl_xor_sync(0xffffffffu, num[s], 2);
        den[s] += __shfl_xor_sync(0xffffffffu, den[s], 1);
        den[s] += __shfl_xor_sync(0xffffffffu, den[s], 2);
    }
    if ((lane & 3) == 0) {
        float* rn = (float*)(smem + SM_RN);
        float* rd = (float*)(smem + SM_RD);
        int row = wm * 16 + (lane >> 2);
        rn[wn * 128 + row]     = num[0];
        rd[wn * 128 + row]     = den[0];
        rn[wn * 128 + row + 8] = num[1];
        rd[wn * 128 + row + 8] = den[1];
    }
    __syncthreads();
    if (tid < 128) {
        const float* rn = (const float*)(smem + SM_RN);
        const float* rd = (const float*)(smem + SM_RD);
        g_PN[sp * NROWS + qb * 128 + tid] = rn[tid] + rn[128 + tid];
        g_PD[sp * NROWS + qb * 128 + tid] = rd[tid] + rd[128 + tid];
    }
}

// ---------------------------------------------------------------------------
// Kernel E: combine splits
// ---------------------------------------------------------------------------
__global__ void __launch_bounds__(256) combine_kernel(const float* __restrict__ bout,
                                                      float* __restrict__ out)
{
    int i = blockIdx.x * 256 + threadIdx.x;
    float n = g_PN[i] + g_PN[NROWS + i];
    float d = g_PD[i] + g_PD[NROWS + i];
    out[i] = n / d + __ldg(bout);
}

// ---------------------------------------------------------------------------
extern "C" void kernel_launch(void* const* d_in, const int* in_sizes, int n_in,
                              void* d_out, int out_size)
{
    const float* x    = (const float*)d_in[0];
    const float* Wfc  = (const float*)d_in[1];
    const float* bfc  = (const float*)d_in[2];
    const float* Wg   = (const float*)d_in[3];
    const float* bg   = (const float*)d_in[4];
    const float* Wq   = (const float*)d_in[5];
    const float* bq   = (const float*)d_in[6];
    const float* Wk   = (const float*)d_in[7];
    const float* bk   = (const float*)d_in[8];
    const float* Wv   = (const float*)d_in[9];
    const float* bv   = (const float*)d_in[10];
    const float* Wout = (const float*)d_in[11];
    const float* bout = (const float*)d_in[12];
    float* out = (float*)d_out;

    cudaFuncSetAttribute(attn_mma_kernel, cudaFuncAttributeMaxDynamicSharedMemorySize, SMEM_ATTN);
    cudaFuncSetAttribute(gated_fc_mma_kernel, cudaFuncAttributeMaxDynamicSharedMemorySize, GF_SMEM);
    cudaFuncSetAttribute(qkv_mma_kernel, cudaFuncAttributeMaxDynamicSharedMemorySize, QV_SMEM);

    cvt_x_kernel<<<NROWS * DIN / 1024, 256>>>(x);
    cvt_w_kernel<<<256 * DIN / 256, 256>>>(Wfc, Wg);
    cvt_wqkv_kernel<<<384 * DH / 256, 256>>>(Wq, Wk, Wv);
    gated_fc_mma_kernel<<<NROWS / 64, 512, GF_SMEM>>>(bfc, bg);
    qkv_mma_kernel<<<NROWS / 64, 256, QV_SMEM>>>(bq, bk, bv, Wout);
    attn_mma_kernel<<<dim3(NROWS / 128, 2), 512, SMEM_ATTN>>>();
    combine_kernel<<<NROWS / 256, 256>>>(bout, out);
}

// round 12
// speedup vs baseline: 6.0230x; 1.1125x over previous
#include <cuda_runtime.h>
#include <cuda_bf16.h>
#include <cuda_fp16.h>
#include <cstdint>

#define NROWS 8192
#define DIN   1024
#define DH    128

// ---------------------------------------------------------------------------
// Scratch
// ---------------------------------------------------------------------------
__device__ float g_Q[NROWS * DH];
__device__ float g_U[NROWS];
__device__ float g_PN[2 * NROWS];
__device__ float g_PD[2 * NROWS];
// Packed K (f16, paired-k perm): 64 tiles of [128 rows][288 B]
__device__ __align__(1024) char g_Kp[64 * 36864];
// Packed x hi/lo: per (rowblock 64, stage 32k): [hi 64x80B][lo 64x80B]
__device__ __align__(1024) char g_xp[128 * 32 * 10240];
// Packed W_fc|W_gate hi/lo per stage: [wh 256x80B][wl 256x80B]
__device__ __align__(1024) char g_wp[32 * 40960];
// Packed H hi/lo: per (rowblock 64, stage 32k of DH): [hi 64x80B][lo 64x80B]
__device__ __align__(1024) char g_hp[128 * 4 * 10240];
// Packed W_qkv hi/lo per stage (k of DH): [wh 384x80B][wl 384x80B]
__device__ __align__(1024) char g_wqp[4 * 61440];

__device__ __forceinline__ float sigmoidf_(float z) {
    return 1.0f / (1.0f + __expf(-z));
}
__device__ __forceinline__ uint32_t smem_u32(const void* p) {
    uint32_t a;
    asm("{ .reg .u64 t; cvta.to.shared.u64 t, %1; cvt.u32.u64 %0, t; }" : "=r"(a) : "l"(p));
    return a;
}
__device__ __forceinline__ uint32_t pack_h2(float x, float y) {
    __half2 h = __floats2half2_rn(x, y);
    return *(uint32_t*)&h;
}
__device__ __forceinline__ uint32_t lds32(uint32_t addr) {
    uint32_t v; asm volatile("ld.shared.b32 %0, [%1];" : "=r"(v) : "r"(addr)); return v;
}
__device__ __forceinline__ void lds64(uint32_t& a, uint32_t& b, uint32_t addr) {
    asm volatile("ld.shared.v2.b32 {%0,%1}, [%2];" : "=r"(a), "=r"(b) : "r"(addr));
}
__device__ __forceinline__ void mma_f16(float c[4], const uint32_t a[4],
                                        uint32_t b0, uint32_t b1) {
    asm volatile(
        "mma.sync.aligned.m16n8k16.row.col.f32.f16.f16.f32 "
        "{%0,%1,%2,%3}, {%4,%5,%6,%7}, {%8,%9}, {%0,%1,%2,%3};"
        : "+f"(c[0]), "+f"(c[1]), "+f"(c[2]), "+f"(c[3])
        : "r"(a[0]), "r"(a[1]), "r"(a[2]), "r"(a[3]), "r"(b0), "r"(b1));
}
__device__ __forceinline__ void mma_bf16(float c[4], const uint32_t a[4],
                                         uint32_t b0, uint32_t b1) {
    asm volatile(
        "mma.sync.aligned.m16n8k16.row.col.f32.bf16.bf16.f32 "
        "{%0,%1,%2,%3}, {%4,%5,%6,%7}, {%8,%9}, {%0,%1,%2,%3};"
        : "+f"(c[0]), "+f"(c[1]), "+f"(c[2]), "+f"(c[3])
        : "r"(a[0]), "r"(a[1]), "r"(a[2]), "r"(a[3]), "r"(b0), "r"(b1));
}
__device__ __forceinline__ float ex2f_(float x) {
    float r; asm("ex2.approx.f32 %0, %1;" : "=f"(r) : "f"(x)); return r;
}
__device__ __forceinline__ void bulk_g2s(uint32_t dst, const void* src,
                                         uint32_t bytes, uint32_t mbar) {
    asm volatile(
        "cp.async.bulk.shared::cluster.global.mbarrier::complete_tx::bytes [%0], [%1], %2, [%3];"
        :: "r"(dst), "l"(src), "r"(bytes), "r"(mbar) : "memory");
}
#define MBARRIER_INIT(addr, cnt) \
    asm volatile("mbarrier.init.shared.b64 [%0], %1;" :: "r"(addr), "r"(cnt) : "memory")
#define MBARRIER_ARRIVE(addr) \
    asm volatile("mbarrier.arrive.shared.b64 _, [%0];" :: "r"(addr) : "memory")
#define MBARRIER_EXPECT_TX(addr, bytes) \
    asm volatile("mbarrier.arrive.expect_tx.shared.b64 _, [%0], %1;" \
                 :: "r"(addr), "r"(bytes) : "memory")
#define MBARRIER_WAIT_PARITY(addr, ph) do {                                    \
    uint32_t _m = (uint32_t)(addr);                                            \
    uint32_t _p = (uint32_t)(ph);                                              \
    uint32_t _d;                                                               \
    asm volatile("{\n\t.reg .pred p;\n\t"                                      \
        "mbarrier.try_wait.parity.acquire.cta.shared::cta.b64 p, [%1], %2;\n\t"\
        "selp.b32 %0, 1, 0, p;\n\t}" : "=r"(_d) : "r"(_m), "r"(_p) : "memory");\
    if (!_d) {                                                                 \
        asm volatile("{\n\t.reg .pred P1;\n\t"                                 \
            "WL_%=:\n\t"                                                       \
            "mbarrier.try_wait.parity.acquire.cta.shared::cta.b64 P1, [%0], %1, 0x989680;\n\t" \
            "@P1 bra.uni WD_%=;\n\t"                                           \
            "bra.uni WL_%=;\n\t"                                               \
            "WD_%=:\n\t}" :: "r"(_m), "r"(_p) : "memory");                     \
    }                                                                          \
} while (0)

// paired-k byte offset of element k (even) within a 288B K row
__device__ __forceinline__ uint32_t kh_off(int k) {
    return (uint32_t)((k >> 4) * 32 + ((k & 7) >> 1) * 8 + ((k >> 3) & 1) * 4);
}

// ---------------------------------------------------------------------------
// Prekernel: x -> packed bf16 hi/lo tiles
// ---------------------------------------------------------------------------
__global__ void __launch_bounds__(256) cvt_x_kernel(const float* __restrict__ x)
{
    int i = (blockIdx.x * 256 + threadIdx.x) * 4;
    int row = i >> 10, k = i & 1023;
    float4 v = *(const float4*)&x[i];
    __nv_bfloat16 h0 = __float2bfloat16(v.x);
    __nv_bfloat16 h1 = __float2bfloat16(v.y);
    __nv_bfloat16 h2 = __float2bfloat16(v.z);
    __nv_bfloat16 h3 = __float2bfloat16(v.w);
    __nv_bfloat16 l0 = __float2bfloat16(v.x - __bfloat162float(h0));
    __nv_bfloat16 l1 = __float2bfloat16(v.y - __bfloat162float(h1));
    __nv_bfloat16 l2 = __float2bfloat16(v.z - __bfloat162float(h2));
    __nv_bfloat16 l3 = __float2bfloat16(v.w - __bfloat162float(h3));
    int rb = row >> 6, r = row & 63, stage = k >> 5, kk = k & 31;
    size_t base = (size_t)(rb * 32 + stage) * 10240 + r * 80 + kk * 2;
    uint32_t hp0 = ((uint32_t)__bfloat16_as_ushort(h1) << 16) | __bfloat16_as_ushort(h0);
    uint32_t hp1 = ((uint32_t)__bfloat16_as_ushort(h3) << 16) | __bfloat16_as_ushort(h2);
    uint32_t lp0 = ((uint32_t)__bfloat16_as_ushort(l1) << 16) | __bfloat16_as_ushort(l0);
    uint32_t lp1 = ((uint32_t)__bfloat16_as_ushort(l3) << 16) | __bfloat16_as_ushort(l2);
    *(uint2*)(g_xp + base)        = make_uint2(hp0, hp1);
    *(uint2*)(g_xp + base + 5120) = make_uint2(lp0, lp1);
}

// ---------------------------------------------------------------------------
// Prekernel: W_fc|W_gate -> packed bf16 hi/lo tiles, transposed to [n][k]
// ---------------------------------------------------------------------------
__global__ void __launch_bounds__(256) cvt_w_kernel(const float* __restrict__ Wfc,
                                                    const float* __restrict__ Wg)
{
    int idx = blockIdx.x * 256 + threadIdx.x;   // n*1024 + k
    int n = idx >> 10, k = idx & 1023;
    float v = (n < 128) ? Wfc[(size_t)k * DH + n] : Wg[(size_t)k * DH + (n - 128)];
    __nv_bfloat16 h = __float2bfloat16(v);
    __nv_bfloat16 l = __float2bfloat16(v - __bfloat162float(h));
    int stage = k >> 5, kk = k & 31;
    size_t base = (size_t)stage * 40960 + n * 80 + kk * 2;
    *(__nv_bfloat16*)(g_wp + base)         = h;
    *(__nv_bfloat16*)(g_wp + base + 20480) = l;
}

// ---------------------------------------------------------------------------
// Prekernel: W_q|W_k|W_v -> packed bf16 hi/lo tiles, transposed to [n][k]
// ---------------------------------------------------------------------------
__global__ void __launch_bounds__(256) cvt_wqkv_kernel(const float* __restrict__ Wq,
                                                       const float* __restrict__ Wk,
                                                       const float* __restrict__ Wv)
{
    int idx = blockIdx.x * 256 + threadIdx.x;   // n*128 + k, 384*128 total
    int n = idx >> 7, k = idx & 127;
    float v = (n < 128) ? Wq[(size_t)k * DH + n]
            : (n < 256) ? Wk[(size_t)k * DH + (n - 128)]
                        : Wv[(size_t)k * DH + (n - 256)];
    __nv_bfloat16 h = __float2bfloat16(v);
    __nv_bfloat16 l = __float2bfloat16(v - __bfloat162float(h));
    int stage = k >> 5, kk = k & 31;
    size_t base = (size_t)stage * 61440 + n * 80 + kk * 2;
    *(__nv_bfloat16*)(g_wqp + base)         = h;
    *(__nv_bfloat16*)(g_wqp + base + 30720) = l;
}

// ---------------------------------------------------------------------------
// Kernel A: gated linear, bf16 3-term MMA, 512 threads (wm4 x wn4).
// 3-buffer ring, per-buffer full/consumed mbarriers, NO per-stage CTA barrier.
// ---------------------------------------------------------------------------
#define GF_PITCH 80
#define GF_BUF   51200
#define GF_XH(b)  ((b) * GF_BUF + 0)
#define GF_XL(b)  ((b) * GF_BUF + 5120)
#define GF_WH(b)  ((b) * GF_BUF + 10240)
#define GF_WL(b)  ((b) * GF_BUF + 30720)
#define GF_MB     (3 * GF_BUF)               // full[3] at +0, consumed[3] at +24
#define GF_SMEM   (3 * GF_BUF + 64)

__global__ void __launch_bounds__(512, 1) gated_fc_mma_kernel(
    const float* __restrict__ bfc, const float* __restrict__ bg)
{
    extern __shared__ char smem[];
    const uint32_t sb = smem_u32(smem);
    const int tid  = threadIdx.x;
    const int lane = tid & 31;
    const int wid  = tid >> 5;
    const int wm   = wid & 3;        // 16 rows each
    const int wn   = wid >> 2;       // 0..3, 32 fc + 32 gate cols

    if (tid == 0) {
#pragma unroll
        for (int b = 0; b < 3; b++) {
            MBARRIER_INIT(sb + GF_MB + 8 * b, 1);        // full
            MBARRIER_INIT(sb + GF_MB + 24 + 8 * b, 16);  // consumed (16 warps)
        }
    }
    __syncthreads();

    float c[8][4];
#pragma unroll
    for (int jn = 0; jn < 8; jn++)
#pragma unroll
        for (int v = 0; v < 4; v++) c[jn][v] = 0.f;

    // prologue: fill stages 0,1
    if (tid == 0) {
#pragma unroll
        for (int s = 0; s < 2; s++) {
            MBARRIER_EXPECT_TX(sb + GF_MB + 8 * s, 51200);
            bulk_g2s(sb + GF_XH(s), g_xp + (size_t)(blockIdx.x * 32 + s) * 10240, 10240,
                     sb + GF_MB + 8 * s);
            bulk_g2s(sb + GF_WH(s), g_wp + (size_t)s * 40960, 40960, sb + GF_MB + 8 * s);
        }
    }

    const uint32_t a_off  = (uint32_t)(wm * 16 + (lane >> 2)) * GF_PITCH + (lane & 3) * 4;
    const uint32_t b_lane = (uint32_t)(lane >> 2) * GF_PITCH + (lane & 3) * 4;

#pragma unroll 1
    for (int s = 0; s < 32; s++) {
        const int sp = s + 2;
        if (sp < 32 && tid == 0) {
            const int b2 = sp % 3, o2 = sp / 3;
            if (o2 >= 1) MBARRIER_WAIT_PARITY(sb + GF_MB + 24 + 8 * b2, (o2 - 1) & 1);
            MBARRIER_EXPECT_TX(sb + GF_MB + 8 * b2, 51200);
            bulk_g2s(sb + GF_XH(b2), g_xp + (size_t)(blockIdx.x * 32 + sp) * 10240, 10240,
                     sb + GF_MB + 8 * b2);
            bulk_g2s(sb + GF_WH(b2), g_wp + (size_t)sp * 40960, 40960, sb + GF_MB + 8 * b2);
        }
        const int buf = s % 3;
        MBARRIER_WAIT_PARITY(sb + GF_MB + 8 * buf, (s / 3) & 1);

        const uint32_t xh = sb + GF_XH(buf) + a_off;
        const uint32_t xl = sb + GF_XL(buf) + a_off;
        const uint32_t wh = sb + GF_WH(buf) + b_lane;
        const uint32_t wl = sb + GF_WL(buf) + b_lane;

#pragma unroll
        for (int kf = 0; kf < 2; kf++) {
            uint32_t ah[4], al[4];
            {
                uint32_t ar  = xh + kf * 32;
                uint32_t alr = xl + kf * 32;
                ah[0] = lds32(ar);
                ah[1] = lds32(ar + 8 * GF_PITCH);
                ah[2] = lds32(ar + 16);
                ah[3] = lds32(ar + 8 * GF_PITCH + 16);
                al[0] = lds32(alr);
                al[1] = lds32(alr + 8 * GF_PITCH);
                al[2] = lds32(alr + 16);
                al[3] = lds32(alr + 8 * GF_PITCH + 16);
            }
#pragma unroll
            for (int jn = 0; jn < 8; jn++) {
                const int n0 = (jn < 4) ? wn * 32 + jn * 8 : 128 + wn * 32 + (jn - 4) * 8;
                uint32_t br  = wh + (uint32_t)n0 * GF_PITCH + kf * 32;
                uint32_t blr = wl + (uint32_t)n0 * GF_PITCH + kf * 32;
                uint32_t bh0 = lds32(br),  bh1 = lds32(br + 16);
                uint32_t bl0 = lds32(blr), bl1 = lds32(blr + 16);
                mma_bf16(c[jn], ah, bh0, bh1);
                mma_bf16(c[jn], ah, bl0, bl1);
                mma_bf16(c[jn], al, bh0, bh1);
            }
        }
        if (lane == 0) MBARRIER_ARRIVE(sb + GF_MB + 24 + 8 * buf);
    }

    // epilogue: h = (fc + bfc) * sigmoid(gate + bg) -> packed bf16 hi/lo tiles
#pragma unroll
    for (int jn = 0; jn < 4; jn++) {
        const int n0 = wn * 32 + jn * 8 + 2 * (lane & 3);
        float2 bf  = *(const float2*)&bfc[n0];
        float2 bg2 = *(const float2*)&bg[n0];
        float2 h0, h1;
        h0.x = (c[jn][0] + bf.x) * sigmoidf_(c[jn + 4][0] + bg2.x);
        h0.y = (c[jn][1] + bf.y) * sigmoidf_(c[jn + 4][1] + bg2.y);
        h1.x = (c[jn][2] + bf.x) * sigmoidf_(c[jn + 4][2] + bg2.x);
        h1.y = (c[jn][3] + bf.y) * sigmoidf_(c[jn + 4][3] + bg2.y);
        const int r0 = wm * 16 + (lane >> 2);
        const int stage = n0 >> 5, kk = n0 & 31;
        char* tb = g_hp + ((size_t)blockIdx.x * 4 + stage) * 10240 + kk * 2;
#pragma unroll
        for (int hh = 0; hh < 2; hh++) {
            float2 hv = hh ? h1 : h0;
            int r = r0 + hh * 8;
            __nv_bfloat16 b0 = __float2bfloat16(hv.x);
            __nv_bfloat16 b1 = __float2bfloat16(hv.y);
            __nv_bfloat16 c0 = __float2bfloat16(hv.x - __bfloat162float(b0));
            __nv_bfloat16 c1 = __float2bfloat16(hv.y - __bfloat162float(b1));
            *(uint32_t*)(tb + r * 80) =
                ((uint32_t)__bfloat16_as_ushort(b1) << 16) | __bfloat16_as_ushort(b0);
            *(uint32_t*)(tb + r * 80 + 5120) =
                ((uint32_t)__bfloat16_as_ushort(c1) << 16) | __bfloat16_as_ushort(c0);
        }
    }
}

// ---------------------------------------------------------------------------
// Kernel B: fused QKV + U, bf16 3-term MMA. K written as f16 pairs (perm).
// (only 4 stages -- keep simple 2-buffer + syncthreads design)
// ---------------------------------------------------------------------------
#define QV_BUF   71680
#define QV_XH(b)  ((b) * QV_BUF + 0)
#define QV_XL(b)  ((b) * QV_BUF + 5120)
#define QV_WH(b)  ((b) * QV_BUF + 10240)
#define QV_WL(b)  ((b) * QV_BUF + 40960)
#define QV_MBAR   (2 * QV_BUF)
#define QV_UPART  (2 * QV_BUF + 64)
#define QV_SMEM   (2 * QV_BUF + 64 + 256)

__global__ void __launch_bounds__(256, 1) qkv_mma_kernel(
    const float* __restrict__ bq, const float* __restrict__ bk,
    const float* __restrict__ bv, const float* __restrict__ Wout)
{
    extern __shared__ char smem[];
    const uint32_t sb = smem_u32(smem);
    float* u_part = (float*)(smem + QV_UPART);
    const int tid  = threadIdx.x;
    const int lane = tid & 31;
    const int wid  = tid >> 5;
    const int wm   = wid & 1;
    const int wn   = wid >> 1;
    const int rb   = blockIdx.x * 64;

    if (tid == 0) {
        MBARRIER_INIT(sb + QV_MBAR, 1);
        MBARRIER_INIT(sb + QV_MBAR + 8, 1);
    }
    if (tid < 64) u_part[tid] = 0.f;
    __syncthreads();

    float c[2][12][4];
#pragma unroll
    for (int im = 0; im < 2; im++)
#pragma unroll
        for (int jn = 0; jn < 12; jn++)
#pragma unroll
            for (int v = 0; v < 4; v++) c[im][jn][v] = 0.f;

    if (tid == 0) {
        MBARRIER_EXPECT_TX(sb + QV_MBAR, QV_BUF);
        bulk_g2s(sb + QV_XH(0), g_hp + (size_t)(blockIdx.x * 4) * 10240, 10240, sb + QV_MBAR);
        bulk_g2s(sb + QV_WH(0), g_wqp, 61440, sb + QV_MBAR);
    }

    const uint32_t a_off  = (uint32_t)(wm * 32 + (lane >> 2)) * GF_PITCH + (lane & 3) * 4;
    const uint32_t b_lane = (uint32_t)(lane >> 2) * GF_PITCH + (lane & 3) * 4;

#pragma unroll 1
    for (int s = 0; s < 4; s++) {
        if (s + 1 < 4 && tid == 0) {
            const int nb = (s + 1) & 1;
            const uint32_t mb = sb + QV_MBAR + 8 * nb;
            MBARRIER_EXPECT_TX(mb, QV_BUF);
            bulk_g2s(sb + QV_XH(nb), g_hp + (size_t)(blockIdx.x * 4 + s + 1) * 10240, 10240, mb);
            bulk_g2s(sb + QV_WH(nb), g_wqp + (size_t)(s + 1) * 61440, 61440, mb);
        }
        MBARRIER_WAIT_PARITY(sb + QV_MBAR + 8 * (s & 1), (s >> 1) & 1);

        const int buf = s & 1;
        const uint32_t xh = sb + QV_XH(buf) + a_off;
        const uint32_t xl = sb + QV_XL(buf) + a_off;
        const uint32_t wh = sb + QV_WH(buf) + b_lane;
        const uint32_t wl = sb + QV_WL(buf) + b_lane;

#pragma unroll
        for (int kf = 0; kf < 2; kf++) {
            uint32_t ah[2][4], al[2][4];
#pragma unroll
            for (int im = 0; im < 2; im++) {
                uint32_t ar  = xh + (uint32_t)im * (16 * GF_PITCH) + kf * 32;
                uint32_t alr = xl + (uint32_t)im * (16 * GF_PITCH) + kf * 32;
                ah[im][0] = lds32(ar);
                ah[im][1] = lds32(ar + 8 * GF_PITCH);
                ah[im][2] = lds32(ar + 16);
                ah[im][3] = lds32(ar + 8 * GF_PITCH + 16);
                al[im][0] = lds32(alr);
                al[im][1] = lds32(alr + 8 * GF_PITCH);
                al[im][2] = lds32(alr + 16);
                al[im][3] = lds32(alr + 8 * GF_PITCH + 16);
            }
#pragma unroll
            for (int jn = 0; jn < 12; jn++) {
                const int n0 = wn * 96 + jn * 8;
                uint32_t br  = wh + (uint32_t)n0 * GF_PITCH + kf * 32;
                uint32_t blr = wl + (uint32_t)n0 * GF_PITCH + kf * 32;
                uint32_t bh0 = lds32(br),  bh1 = lds32(br + 16);
                uint32_t bl0 = lds32(blr), bl1 = lds32(blr + 16);
#pragma unroll
                for (int im = 0; im < 2; im++) {
                    mma_bf16(c[im][jn], ah[im], bh0, bh1);
                    mma_bf16(c[im][jn], ah[im], bl0, bl1);
                    mma_bf16(c[im][jn], al[im], bh0, bh1);
                }
            }
        }
        __syncthreads();
    }

    // epilogue: Q store / K f16 perm store / V -> U partials
    float up[4] = {0.f, 0.f, 0.f, 0.f};
#pragma unroll
    for (int im = 0; im < 2; im++) {
#pragma unroll
        for (int jn = 0; jn < 12; jn++) {
            const int n0 = wn * 96 + jn * 8 + 2 * (lane & 3);
            const int r0 = rb + wm * 32 + (lane >> 2) + im * 16;
            if (n0 < 128) {
                float2 bq2 = *(const float2*)&bq[n0];
                float2 q0 = make_float2(c[im][jn][0] + bq2.x, c[im][jn][1] + bq2.y);
                float2 q1 = make_float2(c[im][jn][2] + bq2.x, c[im][jn][3] + bq2.y);
                *(float2*)&g_Q[(size_t)r0 * DH + n0] = q0;
                *(float2*)&g_Q[(size_t)(r0 + 8) * DH + n0] = q1;
            } else if (n0 < 256) {
                const int kc = n0 - 128;   // even
                float2 bk2 = *(const float2*)&bk[kc];
                const uint32_t off = kh_off(kc);
#pragma unroll
                for (int hh = 0; hh < 2; hh++) {
                    int r = r0 + hh * 8;
                    char* kb = g_Kp + (size_t)(r >> 7) * 36864 + (r & 127) * 288;
                    *(uint32_t*)(kb + off) =
                        pack_h2(c[im][jn][hh * 2 + 0] + bk2.x, c[im][jn][hh * 2 + 1] + bk2.y);
                }
            } else {
                const int vc = n0 - 256;
                float2 bv2 = *(const float2*)&bv[vc];
                float2 w2  = *(const float2*)&Wout[vc];
                up[im * 2 + 0] += (c[im][jn][0] + bv2.x) * w2.x + (c[im][jn][1] + bv2.y) * w2.y;
                up[im * 2 + 1] += (c[im][jn][2] + bv2.x) * w2.x + (c[im][jn][3] + bv2.y) * w2.y;
            }
        }
    }
    if (wn >= 2) {
#pragma unroll
        for (int s = 0; s < 4; s++) {
            up[s] += __shfl_xor_sync(0xffffffffu, up[s], 1);
            up[s] += __shfl_xor_sync(0xffffffffu, up[s], 2);
        }
        if ((lane & 3) == 0) {
#pragma unroll
            for (int s = 0; s < 4; s++) {
                int row = wm * 32 + (lane >> 2) + (s >> 1) * 16 + (s & 1) * 8;
                atomicAdd(&u_part[row], up[s]);
            }
        }
    }
    __syncthreads();
    if (tid < 64) g_U[rb + tid] = u_part[tid];
}

// ---------------------------------------------------------------------------
// Kernel D: flash attention, mma.sync f16 m16n8k16, 512 threads,
// KT=128 rows/tile, 3-buffer ring + consumed mbarriers, pipelined epilogue.
// ---------------------------------------------------------------------------
#define KT 128
#define NT (4096 / KT)
#define KPITCH 288
#define KTILE  36864
#define SM_K(b) ((b) * KTILE)
#define SM_U    (3 * KTILE)            // 110592
#define SM_RN   (SM_U + 16384)
#define SM_RD   (SM_RN + 1024)
#define SM_MB   (SM_RD + 1024)         // full[3] at +0, consumed[3] at +24
#define SMEM_ATTN (SM_MB + 64)

__device__ __forceinline__ void attn_epilogue(const float c[8][4], const float* us,
                                              int wn, int lane, float num[2], float den[2])
{
#pragma unroll
    for (int jn = 0; jn < 8; jn++) {
        const int c0 = wn * 64 + jn * 8 + 2 * (lane & 3);
        const float2 uv = *(const float2*)&us[c0];
        float e0 = ex2f_(c[jn][0]);
        float e1 = ex2f_(c[jn][1]);
        float e2 = ex2f_(c[jn][2]);
        float e3 = ex2f_(c[jn][3]);
        num[0] = fmaf(e0, uv.x, num[0]);
        num[0] = fmaf(e1, uv.y, num[0]);
        den[0] += e0 + e1;
        num[1] = fmaf(e2, uv.x, num[1]);
        num[1] = fmaf(e3, uv.y, num[1]);
        den[1] += e2 + e3;
    }
}

__global__ void __launch_bounds__(512, 1) attn_mma_kernel()
{
    extern __shared__ char smem[];
    const uint32_t sb = smem_u32(smem);
    const int tid  = threadIdx.x;
    const int lane = tid & 31;
    const int wid  = tid >> 5;
    const int wm   = wid >> 1;     // 0..7, 16 q-rows each
    const int wn   = wid & 1;      // 0..1, 64 k-cols each
    const int qb   = blockIdx.x;
    const int sp_  = blockIdx.y;
    const int j_base = sp_ * 4096;
    const int t_base = sp_ * NT;

    if (tid == 0) {
#pragma unroll
        for (int b = 0; b < 3; b++) {
            MBARRIER_INIT(sb + SM_MB + 8 * b, 1);        // full
            MBARRIER_INIT(sb + SM_MB + 24 + 8 * b, 16);  // consumed
        }
    }
#pragma unroll
    for (int i = 0; i < 2; i++) {
        int s = tid + 512 * i;
        *(float4*)(smem + SM_U + s * 16) = *(const float4*)&g_U[j_base + s * 4];
    }
    __syncthreads();

    // prologue: fill tiles 0,1
    if (tid == 0) {
#pragma unroll
        for (int t = 0; t < 2; t++) {
            MBARRIER_EXPECT_TX(sb + SM_MB + 8 * t, KTILE);
            bulk_g2s(sb + SM_K(t), g_Kp + (size_t)(t_base + t) * KTILE, KTILE,
                     sb + SM_MB + 8 * t);
        }
    }

    const float QS = 0.1275174341917854f;   // log2(e)/sqrt(128)
    uint32_t qa[8][4];
    {
        const float* qp = g_Q + (size_t)(qb * 128 + wm * 16) * DH;
        const int r = lane >> 2, c2 = (lane & 3) * 2;
#pragma unroll
        for (int kf = 0; kf < 8; kf++) {
            const float* base = qp + (size_t)r * DH + kf * 16 + c2;
            qa[kf][0] = pack_h2(base[0] * QS, base[1] * QS);
            qa[kf][1] = pack_h2(base[8 * DH] * QS, base[8 * DH + 1] * QS);
            qa[kf][2] = pack_h2(base[8] * QS, base[9] * QS);
            qa[kf][3] = pack_h2(base[8 * DH + 8] * QS, base[8 * DH + 9] * QS);
        }
    }

    float num[2] = {0.f, 0.f};
    float den[2] = {0.f, 0.f};
    float cbuf[2][8][4];

    const uint32_t bbase = sb + (uint32_t)(wn * 64 + (lane >> 2)) * KPITCH
                         + (uint32_t)(lane & 3) * 8;

#pragma unroll 1
    for (int t = 0; t < NT; t++) {
        const int tp = t + 2;
        if (tp < NT && tid == 0) {
            const int b2 = tp % 3, o2 = tp / 3;
            if (o2 >= 1) MBARRIER_WAIT_PARITY(sb + SM_MB + 24 + 8 * b2, (o2 - 1) & 1);
            MBARRIER_EXPECT_TX(sb + SM_MB + 8 * b2, KTILE);
            bulk_g2s(sb + SM_K(b2), g_Kp + (size_t)(t_base + tp) * KTILE, KTILE,
                     sb + SM_MB + 8 * b2);
        }
        const int buf = t % 3;
        MBARRIER_WAIT_PARITY(sb + SM_MB + 8 * buf, (t / 3) & 1);

        const uint32_t kb = bbase + SM_K(buf);
        float (*c)[4] = cbuf[t & 1];
#pragma unroll
        for (int jn = 0; jn < 8; jn++)
#pragma unroll
            for (int v = 0; v < 4; v++) c[jn][v] = 0.f;

#pragma unroll
        for (int kf = 0; kf < 8; kf++) {
#pragma unroll
            for (int jn = 0; jn < 8; jn++) {
                uint32_t b0, b1;
                lds64(b0, b1, kb + (uint32_t)jn * (8 * KPITCH) + (uint32_t)kf * 32);
                mma_f16(c[jn], qa[kf], b0, b1);
            }
        }
        if (lane == 0) MBARRIER_ARRIVE(sb + SM_MB + 24 + 8 * buf);

        if (t > 0) {
            const float* us = (const float*)(smem + SM_U) + (t - 1) * KT;
            attn_epilogue(cbuf[(t - 1) & 1], us, wn, lane, num, den);
        }
    }
    {
        const float* us = (const float*)(smem + SM_U) + (NT - 1) * KT;
        attn_epilogue(cbuf[(NT - 1) & 1], us, wn, lane, num, den);
    }

#pragma unroll
    for (int s = 0; s < 2; s++) {
        num[s] += __shfl_xor_sync(0xffffffffu, num[s], 1);
        num[s] += __shfl_xor_sync(0xffffffffu, num[s], 2);
        den[s] += __shfl_xor_sync(0xffffffffu, den[s], 1);
        den[s] += __shfl_xor_sync(0xffffffffu, den[s], 2);
    }
    if ((lane & 3) == 0) {
        float* rn = (float*)(smem + SM_RN);
        float* rd = (float*)(smem + SM_RD);
        int row = wm * 16 + (lane >> 2);
        rn[wn * 128 + row]     = num[0];
        rd[wn * 128 + row]     = den[0];
        rn[wn * 128 + row + 8] = num[1];
        rd[wn * 128 + row + 8] = den[1];
    }
    __syncthreads();
    if (tid < 128) {
        const float* rn = (const float*)(smem + SM_RN);
        const float* rd = (const float*)(smem + SM_RD);
        g_PN[sp_ * NROWS + qb * 128 + tid] = rn[tid] + rn[128 + tid];
        g_PD[sp_ * NROWS + qb * 128 + tid] = rd[tid] + rd[128 + tid];
    }
}

// ---------------------------------------------------------------------------
// Kernel E: combine splits
// ---------------------------------------------------------------------------
__global__ void __launch_bounds__(256) combine_kernel(const float* __restrict__ bout,
                                                      float* __restrict__ out)
{
    int i = blockIdx.x * 256 + threadIdx.x;
    float n = g_PN[i] + g_PN[NROWS + i];
    float d = g_PD[i] + g_PD[NROWS + i];
    out[i] = n / d + __ldg(bout);
}

// ---------------------------------------------------------------------------
extern "C" void kernel_launch(void* const* d_in, const int* in_sizes, int n_in,
                              void* d_out, int out_size)
{
    const float* x    = (const float*)d_in[0];
    const float* Wfc  = (const float*)d_in[1];
    const float* bfc  = (const float*)d_in[2];
    const float* Wg   = (const float*)d_in[3];
    const float* bg   = (const float*)d_in[4];
    const float* Wq   = (const float*)d_in[5];
    const float* bq   = (const float*)d_in[6];
    const float* Wk   = (const float*)d_in[7];
    const float* bk   = (const float*)d_in[8];
    const float* Wv   = (const float*)d_in[9];
    const float* bv   = (const float*)d_in[10];
    const float* Wout = (const float*)d_in[11];
    const float* bout = (const float*)d_in[12];
    float* out = (float*)d_out;

    cudaFuncSetAttribute(attn_mma_kernel, cudaFuncAttributeMaxDynamicSharedMemorySize, SMEM_ATTN);
    cudaFuncSetAttribute(gated_fc_mma_kernel, cudaFuncAttributeMaxDynamicSharedMemorySize, GF_SMEM);
    cudaFuncSetAttribute(qkv_mma_kernel, cudaFuncAttributeMaxDynamicSharedMemorySize, QV_SMEM);

    cvt_x_kernel<<<NROWS * DIN / 1024, 256>>>(x);
    cvt_w_kernel<<<256 * DIN / 256, 256>>>(Wfc, Wg);
    cvt_wqkv_kernel<<<384 * DH / 256, 256>>>(Wq, Wk, Wv);
    gated_fc_mma_kernel<<<NROWS / 64, 512, GF_SMEM>>>(bfc, bg);
    qkv_mma_kernel<<<NROWS / 64, 256, QV_SMEM>>>(bq, bk, bv, Wout);
    attn_mma_kernel<<<dim3(NROWS / 128, 2), 512, SMEM_ATTN>>>();
    combine_kernel<<<NROWS / 256, 256>>>(bout, out);
}

// round 16
// speedup vs baseline: 6.1387x; 1.0192x over previous
#include <cuda_runtime.h>
#include <cuda_bf16.h>
#include <cuda_fp16.h>
#include <cstdint>

#define NROWS 8192
#define DIN   1024
#define DH    128

// ---------------------------------------------------------------------------
// Scratch
// ---------------------------------------------------------------------------
__device__ float g_Q[NROWS * DH];
__device__ float g_U[NROWS];
__device__ float g_PN[2 * NROWS];
__device__ float g_PD[2 * NROWS];
// Packed K (f16, plain [row][k], pitch 304B): 64 tiles of [128 rows][304 B]
__device__ __align__(1024) char g_Kp[64 * 38912];
// Packed x hi/lo: per (rowblock 64, stage 32k): [hi 64x80B][lo 64x80B]
__device__ __align__(1024) char g_xp[128 * 32 * 10240];
// Packed W_fc|W_gate hi/lo per stage: [wh 256x80B][wl 256x80B]
__device__ __align__(1024) char g_wp[32 * 40960];
// Packed H hi/lo: per (rowblock 64, stage 32k of DH): [hi 64x80B][lo 64x80B]
__device__ __align__(1024) char g_hp[128 * 4 * 10240];
// Packed W_qkv hi/lo per stage (k of DH): [wh 384x80B][wl 384x80B]
__device__ __align__(1024) char g_wqp[4 * 61440];

__device__ __forceinline__ float sigmoidf_(float z) {
    return 1.0f / (1.0f + __expf(-z));
}
__device__ __forceinline__ uint32_t smem_u32(const void* p) {
    uint32_t a;
    asm("{ .reg .u64 t; cvta.to.shared.u64 t, %1; cvt.u32.u64 %0, t; }" : "=r"(a) : "l"(p));
    return a;
}
__device__ __forceinline__ uint32_t pack_h2(float x, float y) {
    __half2 h = __floats2half2_rn(x, y);
    return *(uint32_t*)&h;
}
__device__ __forceinline__ void ldsm_x4(uint32_t r[4], uint32_t addr) {
    asm volatile("ldmatrix.sync.aligned.m8n8.x4.shared.b16 {%0,%1,%2,%3}, [%4];"
                 : "=r"(r[0]), "=r"(r[1]), "=r"(r[2]), "=r"(r[3]) : "r"(addr));
}
__device__ __forceinline__ void mma_f16(float c[4], const uint32_t a[4],
                                        uint32_t b0, uint32_t b1) {
    asm volatile(
        "mma.sync.aligned.m16n8k16.row.col.f32.f16.f16.f32 "
        "{%0,%1,%2,%3}, {%4,%5,%6,%7}, {%8,%9}, {%0,%1,%2,%3};"
        : "+f"(c[0]), "+f"(c[1]), "+f"(c[2]), "+f"(c[3])
        : "r"(a[0]), "r"(a[1]), "r"(a[2]), "r"(a[3]), "r"(b0), "r"(b1));
}
__device__ __forceinline__ void mma_bf16(float c[4], const uint32_t a[4],
                                         uint32_t b0, uint32_t b1) {
    asm volatile(
        "mma.sync.aligned.m16n8k16.row.col.f32.bf16.bf16.f32 "
        "{%0,%1,%2,%3}, {%4,%5,%6,%7}, {%8,%9}, {%0,%1,%2,%3};"
        : "+f"(c[0]), "+f"(c[1]), "+f"(c[2]), "+f"(c[3])
        : "r"(a[0]), "r"(a[1]), "r"(a[2]), "r"(a[3]), "r"(b0), "r"(b1));
}
__device__ __forceinline__ float ex2f_(float x) {
    float r; asm("ex2.approx.f32 %0, %1;" : "=f"(r) : "f"(x)); return r;
}
__device__ __forceinline__ void bulk_g2s(uint32_t dst, const void* src,
                                         uint32_t bytes, uint32_t mbar) {
    asm volatile(
        "cp.async.bulk.shared::cluster.global.mbarrier::complete_tx::bytes [%0], [%1], %2, [%3];"
        :: "r"(dst), "l"(src), "r"(bytes), "r"(mbar) : "memory");
}
#define MBARRIER_INIT(addr, cnt) \
    asm volatile("mbarrier.init.shared.b64 [%0], %1;" :: "r"(addr), "r"(cnt) : "memory")
#define MBARRIER_ARRIVE(addr) \
    asm volatile("mbarrier.arrive.shared.b64 _, [%0];" :: "r"(addr) : "memory")
#define MBARRIER_EXPECT_TX(addr, bytes) \
    asm volatile("mbarrier.arrive.expect_tx.shared.b64 _, [%0], %1;" \
                 :: "r"(addr), "r"(bytes) : "memory")
#define MBARRIER_WAIT_PARITY(addr, ph) do {                                    \
    uint32_t _m = (uint32_t)(addr);                                            \
    uint32_t _p = (uint32_t)(ph);                                              \
    uint32_t _d;                                                               \
    asm volatile("{\n\t.reg .pred p;\n\t"                                      \
        "mbarrier.try_wait.parity.acquire.cta.shared::cta.b64 p, [%1], %2;\n\t"\
        "selp.b32 %0, 1, 0, p;\n\t}" : "=r"(_d) : "r"(_m), "r"(_p) : "memory");\
    if (!_d) {                                                                 \
        asm volatile("{\n\t.reg .pred P1;\n\t"                                 \
            "WL_%=:\n\t"                                                       \
            "mbarrier.try_wait.parity.acquire.cta.shared::cta.b64 P1, [%0], %1, 0x989680;\n\t" \
            "@P1 bra.uni WD_%=;\n\t"                                           \
            "bra.uni WL_%=;\n\t"                                               \
            "WD_%=:\n\t}" :: "r"(_m), "r"(_p) : "memory");                     \
    }                                                                          \
} while (0)

// ---------------------------------------------------------------------------
// Prekernel: x -> packed bf16 hi/lo tiles
// ---------------------------------------------------------------------------
__global__ void __launch_bounds__(256) cvt_x_kernel(const float* __restrict__ x)
{
    int i = (blockIdx.x * 256 + threadIdx.x) * 4;
    int row = i >> 10, k = i & 1023;
    float4 v = *(const float4*)&x[i];
    __nv_bfloat16 h0 = __float2bfloat16(v.x);
    __nv_bfloat16 h1 = __float2bfloat16(v.y);
    __nv_bfloat16 h2 = __float2bfloat16(v.z);
    __nv_bfloat16 h3 = __float2bfloat16(v.w);
    __nv_bfloat16 l0 = __float2bfloat16(v.x - __bfloat162float(h0));
    __nv_bfloat16 l1 = __float2bfloat16(v.y - __bfloat162float(h1));
    __nv_bfloat16 l2 = __float2bfloat16(v.z - __bfloat162float(h2));
    __nv_bfloat16 l3 = __float2bfloat16(v.w - __bfloat162float(h3));
    int rb = row >> 6, r = row & 63, stage = k >> 5, kk = k & 31;
    size_t base = (size_t)(rb * 32 + stage) * 10240 + r * 80 + kk * 2;
    uint32_t hp0 = ((uint32_t)__bfloat16_as_ushort(h1) << 16) | __bfloat16_as_ushort(h0);
    uint32_t hp1 = ((uint32_t)__bfloat16_as_ushort(h3) << 16) | __bfloat16_as_ushort(h2);
    uint32_t lp0 = ((uint32_t)__bfloat16_as_ushort(l1) << 16) | __bfloat16_as_ushort(l0);
    uint32_t lp1 = ((uint32_t)__bfloat16_as_ushort(l3) << 16) | __bfloat16_as_ushort(l2);
    *(uint2*)(g_xp + base)        = make_uint2(hp0, hp1);
    *(uint2*)(g_xp + base + 5120) = make_uint2(lp0, lp1);
}

// ---------------------------------------------------------------------------
// Prekernel: W_fc|W_gate -> packed bf16 hi/lo tiles, transposed to [n][k]
// ---------------------------------------------------------------------------
__global__ void __launch_bounds__(256) cvt_w_kernel(const float* __restrict__ Wfc,
                                                    const float* __restrict__ Wg)
{
    int idx = blockIdx.x * 256 + threadIdx.x;   // n*1024 + k
    int n = idx >> 10, k = idx & 1023;
    float v = (n < 128) ? Wfc[(size_t)k * DH + n] : Wg[(size_t)k * DH + (n - 128)];
    __nv_bfloat16 h = __float2bfloat16(v);
    __nv_bfloat16 l = __float2bfloat16(v - __bfloat162float(h));
    int stage = k >> 5, kk = k & 31;
    size_t base = (size_t)stage * 40960 + n * 80 + kk * 2;
    *(__nv_bfloat16*)(g_wp + base)         = h;
    *(__nv_bfloat16*)(g_wp + base + 20480) = l;
}

// ---------------------------------------------------------------------------
// Prekernel: W_q|W_k|W_v -> packed bf16 hi/lo tiles, transposed to [n][k]
// ---------------------------------------------------------------------------
__global__ void __launch_bounds__(256) cvt_wqkv_kernel(const float* __restrict__ Wq,
                                                       const float* __restrict__ Wk,
                                                       const float* __restrict__ Wv)
{
    int idx = blockIdx.x * 256 + threadIdx.x;   // n*128 + k, 384*128 total
    int n = idx >> 7, k = idx & 127;
    float v = (n < 128) ? Wq[(size_t)k * DH + n]
            : (n < 256) ? Wk[(size_t)k * DH + (n - 128)]
                        : Wv[(size_t)k * DH + (n - 256)];
    __nv_bfloat16 h = __float2bfloat16(v);
    __nv_bfloat16 l = __float2bfloat16(v - __bfloat162float(h));
    int stage = k >> 5, kk = k & 31;
    size_t base = (size_t)stage * 61440 + n * 80 + kk * 2;
    *(__nv_bfloat16*)(g_wqp + base)         = h;
    *(__nv_bfloat16*)(g_wqp + base + 30720) = l;
}

// ---------------------------------------------------------------------------
// Kernel A: gated linear, bf16 3-term MMA, 512 threads (wm4 x wn4).
// 3-buffer ring + consumed mbarriers; ALL fragment loads via ldmatrix.x4.
// ---------------------------------------------------------------------------
#define GF_PITCH 80
#define GF_BUF   51200
#define GF_XH(b)  ((b) * GF_BUF + 0)
#define GF_XL(b)  ((b) * GF_BUF + 5120)
#define GF_WH(b)  ((b) * GF_BUF + 10240)
#define GF_WL(b)  ((b) * GF_BUF + 30720)
#define GF_MB     (3 * GF_BUF)
#define GF_SMEM   (3 * GF_BUF + 64)

__global__ void __launch_bounds__(512, 1) gated_fc_mma_kernel(
    const float* __restrict__ bfc, const float* __restrict__ bg)
{
    extern __shared__ char smem[];
    const uint32_t sb = smem_u32(smem);
    const int tid  = threadIdx.x;
    const int lane = tid & 31;
    const int wid  = tid >> 5;
    const int wm   = wid & 3;        // 16 rows each
    const int wn   = wid >> 2;       // 0..3, 32 fc + 32 gate cols

    if (tid == 0) {
#pragma unroll
        for (int b = 0; b < 3; b++) {
            MBARRIER_INIT(sb + GF_MB + 8 * b, 1);
            MBARRIER_INIT(sb + GF_MB + 24 + 8 * b, 16);
        }
    }
    __syncthreads();

    float c[8][4];
#pragma unroll
    for (int jn = 0; jn < 8; jn++)
#pragma unroll
        for (int v = 0; v < 4; v++) c[jn][v] = 0.f;

    if (tid == 0) {
#pragma unroll
        for (int s = 0; s < 2; s++) {
            MBARRIER_EXPECT_TX(sb + GF_MB + 8 * s, 51200);
            bulk_g2s(sb + GF_XH(s), g_xp + (size_t)(blockIdx.x * 32 + s) * 10240, 10240,
                     sb + GF_MB + 8 * s);
            bulk_g2s(sb + GF_WH(s), g_wp + (size_t)s * 40960, 40960, sb + GF_MB + 8 * s);
        }
    }

    // ldmatrix lane address offsets
    const int mat = lane >> 3, r8 = lane & 7;
    // A (m16k16): mat0 rows 0-7 klo, mat1 rows 8-15 klo, mat2 rows 0-7 khi, mat3 rows 8-15 khi
    const uint32_t aoff = (uint32_t)(wm * 16 + (mat & 1) * 8 + r8) * GF_PITCH + (mat >> 1) * 16;
    // B (n8k16 pair): mat0 jn klo, mat1 jn khi, mat2 jn+1 klo, mat3 jn+1 khi
    const uint32_t boff = (uint32_t)((mat >> 1) * 8 + r8) * GF_PITCH + (mat & 1) * 16;

#pragma unroll 1
    for (int s = 0; s < 32; s++) {
        const int sp = s + 2;
        if (sp < 32 && tid == 0) {
            const int b2 = sp % 3, o2 = sp / 3;
            if (o2 >= 1) MBARRIER_WAIT_PARITY(sb + GF_MB + 24 + 8 * b2, (o2 - 1) & 1);
            MBARRIER_EXPECT_TX(sb + GF_MB + 8 * b2, 51200);
            bulk_g2s(sb + GF_XH(b2), g_xp + (size_t)(blockIdx.x * 32 + sp) * 10240, 10240,
                     sb + GF_MB + 8 * b2);
            bulk_g2s(sb + GF_WH(b2), g_wp + (size_t)sp * 40960, 40960, sb + GF_MB + 8 * b2);
        }
        const int buf = s % 3;
        MBARRIER_WAIT_PARITY(sb + GF_MB + 8 * buf, (s / 3) & 1);

        const uint32_t xh = sb + GF_XH(buf) + aoff;
        const uint32_t xl = sb + GF_XL(buf) + aoff;
        const uint32_t wh = sb + GF_WH(buf) + boff;
        const uint32_t wl = sb + GF_WL(buf) + boff;

#pragma unroll
        for (int kf = 0; kf < 2; kf++) {
            uint32_t ah[4], al[4];
            ldsm_x4(ah, xh + kf * 32);
            ldsm_x4(al, xl + kf * 32);
#pragma unroll
            for (int p = 0; p < 4; p++) {   // jn pairs (2p, 2p+1)
                const int n0 = (p < 2) ? wn * 32 + p * 16 : 128 + wn * 32 + (p - 2) * 16;
                uint32_t bh[4], bl[4];
                ldsm_x4(bh, wh + (uint32_t)n0 * GF_PITCH + kf * 32);
                ldsm_x4(bl, wl + (uint32_t)n0 * GF_PITCH + kf * 32);
                mma_bf16(c[2 * p],     ah, bh[0], bh[1]);
                mma_bf16(c[2 * p],     ah, bl[0], bl[1]);
                mma_bf16(c[2 * p],     al, bh[0], bh[1]);
                mma_bf16(c[2 * p + 1], ah, bh[2], bh[3]);
                mma_bf16(c[2 * p + 1], ah, bl[2], bl[3]);
                mma_bf16(c[2 * p + 1], al, bh[2], bh[3]);
            }
        }
        if (lane == 0) MBARRIER_ARRIVE(sb + GF_MB + 24 + 8 * buf);
    }

    // epilogue: h = (fc + bfc) * sigmoid(gate + bg) -> packed bf16 hi/lo tiles
#pragma unroll
    for (int jn = 0; jn < 4; jn++) {
        const int n0 = wn * 32 + jn * 8 + 2 * (lane & 3);
        float2 bf  = *(const float2*)&bfc[n0];
        float2 bg2 = *(const float2*)&bg[n0];
        float2 h0, h1;
        h0.x = (c[jn][0] + bf.x) * sigmoidf_(c[jn + 4][0] + bg2.x);
        h0.y = (c[jn][1] + bf.y) * sigmoidf_(c[jn + 4][1] + bg2.y);
        h1.x = (c[jn][2] + bf.x) * sigmoidf_(c[jn + 4][2] + bg2.x);
        h1.y = (c[jn][3] + bf.y) * sigmoidf_(c[jn + 4][3] + bg2.y);
        const int r0 = wm * 16 + (lane >> 2);
        const int stage = n0 >> 5, kk = n0 & 31;
        char* tb = g_hp + ((size_t)blockIdx.x * 4 + stage) * 10240 + kk * 2;
#pragma unroll
        for (int hh = 0; hh < 2; hh++) {
            float2 hv = hh ? h1 : h0;
            int r = r0 + hh * 8;
            __nv_bfloat16 b0 = __float2bfloat16(hv.x);
            __nv_bfloat16 b1 = __float2bfloat16(hv.y);
            __nv_bfloat16 c0 = __float2bfloat16(hv.x - __bfloat162float(b0));
            __nv_bfloat16 c1 = __float2bfloat16(hv.y - __bfloat162float(b1));
            *(uint32_t*)(tb + r * 80) =
                ((uint32_t)__bfloat16_as_ushort(b1) << 16) | __bfloat16_as_ushort(b0);
            *(uint32_t*)(tb + r * 80 + 5120) =
                ((uint32_t)__bfloat16_as_ushort(c1) << 16) | __bfloat16_as_ushort(c0);
        }
    }
}

// ---------------------------------------------------------------------------
// Kernel B: fused QKV + U, bf16 3-term MMA, ldmatrix loads.
// K written as f16 plain [row][k] pitch-304 tiles.
// ---------------------------------------------------------------------------
#define QV_BUF   71680
#define QV_XH(b)  ((b) * QV_BUF + 0)
#define QV_XL(b)  ((b) * QV_BUF + 5120)
#define QV_WH(b)  ((b) * QV_BUF + 10240)
#define QV_WL(b)  ((b) * QV_BUF + 40960)
#define QV_MBAR   (2 * QV_BUF)
#define QV_UPART  (2 * QV_BUF + 64)
#define QV_SMEM   (2 * QV_BUF + 64 + 256)

__global__ void __launch_bounds__(256, 1) qkv_mma_kernel(
    const float* __restrict__ bq, const float* __restrict__ bk,
    const float* __restrict__ bv, const float* __restrict__ Wout)
{
    extern __shared__ char smem[];
    const uint32_t sb = smem_u32(smem);
    float* u_part = (float*)(smem + QV_UPART);
    const int tid  = threadIdx.x;
    const int lane = tid & 31;
    const int wid  = tid >> 5;
    const int wm   = wid & 1;
    const int wn   = wid >> 1;
    const int rb   = blockIdx.x * 64;

    if (tid == 0) {
        MBARRIER_INIT(sb + QV_MBAR, 1);
        MBARRIER_INIT(sb + QV_MBAR + 8, 1);
    }
    if (tid < 64) u_part[tid] = 0.f;
    __syncthreads();

    float c[2][12][4];
#pragma unroll
    for (int im = 0; im < 2; im++)
#pragma unroll
        for (int jn = 0; jn < 12; jn++)
#pragma unroll
            for (int v = 0; v < 4; v++) c[im][jn][v] = 0.f;

    if (tid == 0) {
        MBARRIER_EXPECT_TX(sb + QV_MBAR, QV_BUF);
        bulk_g2s(sb + QV_XH(0), g_hp + (size_t)(blockIdx.x * 4) * 10240, 10240, sb + QV_MBAR);
        bulk_g2s(sb + QV_WH(0), g_wqp, 61440, sb + QV_MBAR);
    }

    const int mat = lane >> 3, r8 = lane & 7;
    const uint32_t aoff = (uint32_t)(wm * 32 + (mat & 1) * 8 + r8) * GF_PITCH + (mat >> 1) * 16;
    const uint32_t boff = (uint32_t)((mat >> 1) * 8 + r8) * GF_PITCH + (mat & 1) * 16;

#pragma unroll 1
    for (int s = 0; s < 4; s++) {
        if (s + 1 < 4 && tid == 0) {
            const int nb = (s + 1) & 1;
            const uint32_t mb = sb + QV_MBAR + 8 * nb;
            MBARRIER_EXPECT_TX(mb, QV_BUF);
            bulk_g2s(sb + QV_XH(nb), g_hp + (size_t)(blockIdx.x * 4 + s + 1) * 10240, 10240, mb);
            bulk_g2s(sb + QV_WH(nb), g_wqp + (size_t)(s + 1) * 61440, 61440, mb);
        }
        MBARRIER_WAIT_PARITY(sb + QV_MBAR + 8 * (s & 1), (s >> 1) & 1);

        const int buf = s & 1;
        const uint32_t xh = sb + QV_XH(buf) + aoff;
        const uint32_t xl = sb + QV_XL(buf) + aoff;
        const uint32_t wh = sb + QV_WH(buf) + boff;
        const uint32_t wl = sb + QV_WL(buf) + boff;

#pragma unroll
        for (int kf = 0; kf < 2; kf++) {
            uint32_t ah[2][4], al[2][4];
#pragma unroll
            for (int im = 0; im < 2; im++) {
                ldsm_x4(ah[im], xh + (uint32_t)im * (16 * GF_PITCH) + kf * 32);
                ldsm_x4(al[im], xl + (uint32_t)im * (16 * GF_PITCH) + kf * 32);
            }
#pragma unroll
            for (int p = 0; p < 6; p++) {   // jn pairs
                const int n0 = wn * 96 + p * 16;
                uint32_t bh[4], bl[4];
                ldsm_x4(bh, wh + (uint32_t)n0 * GF_PITCH + kf * 32);
                ldsm_x4(bl, wl + (uint32_t)n0 * GF_PITCH + kf * 32);
#pragma unroll
                for (int im = 0; im < 2; im++) {
                    mma_bf16(c[im][2 * p],     ah[im], bh[0], bh[1]);
                    mma_bf16(c[im][2 * p],     ah[im], bl[0], bl[1]);
                    mma_bf16(c[im][2 * p],     al[im], bh[0], bh[1]);
                    mma_bf16(c[im][2 * p + 1], ah[im], bh[2], bh[3]);
                    mma_bf16(c[im][2 * p + 1], ah[im], bl[2], bl[3]);
                    mma_bf16(c[im][2 * p + 1], al[im], bh[2], bh[3]);
                }
            }
        }
        __syncthreads();
    }

    // epilogue: Q store / K f16 plain store / V -> U partials
    float up[4] = {0.f, 0.f, 0.f, 0.f};
#pragma unroll
    for (int im = 0; im < 2; im++) {
#pragma unroll
        for (int jn = 0; jn < 12; jn++) {
            const int n0 = wn * 96 + jn * 8 + 2 * (lane & 3);
            const int r0 = rb + wm * 32 + (lane >> 2) + im * 16;
            if (n0 < 128) {
                float2 bq2 = *(const float2*)&bq[n0];
                float2 q0 = make_float2(c[im][jn][0] + bq2.x, c[im][jn][1] + bq2.y);
                float2 q1 = make_float2(c[im][jn][2] + bq2.x, c[im][jn][3] + bq2.y);
                *(float2*)&g_Q[(size_t)r0 * DH + n0] = q0;
                *(float2*)&g_Q[(size_t)(r0 + 8) * DH + n0] = q1;
            } else if (n0 < 256) {
                const int kc = n0 - 128;   // even
                float2 bk2 = *(const float2*)&bk[kc];
#pragma unroll
                for (int hh = 0; hh < 2; hh++) {
                    int r = r0 + hh * 8;
                    char* kb = g_Kp + (size_t)(r >> 7) * 38912 + (r & 127) * 304;
                    *(uint32_t*)(kb + kc * 2) =
                        pack_h2(c[im][jn][hh * 2 + 0] + bk2.x, c[im][jn][hh * 2 + 1] + bk2.y);
                }
            } else {
                const int vc = n0 - 256;
                float2 bv2 = *(const float2*)&bv[vc];
                float2 w2  = *(const float2*)&Wout[vc];
                up[im * 2 + 0] += (c[im][jn][0] + bv2.x) * w2.x + (c[im][jn][1] + bv2.y) * w2.y;
                up[im * 2 + 1] += (c[im][jn][2] + bv2.x) * w2.x + (c[im][jn][3] + bv2.y) * w2.y;
            }
        }
    }
    if (wn >= 2) {
#pragma unroll
        for (int s = 0; s < 4; s++) {
            up[s] += __shfl_xor_sync(0xffffffffu, up[s], 1);
            up[s] += __shfl_xor_sync(0xffffffffu, up[s], 2);
        }
        if ((lane & 3) == 0) {
#pragma unroll
            for (int s = 0; s < 4; s++) {
                int row = wm * 32 + (lane >> 2) + (s >> 1) * 16 + (s & 1) * 8;
                atomicAdd(&u_part[row], up[s]);
            }
        }
    }
    __syncthreads();
    if (tid < 64) g_U[rb + tid] = u_part[tid];
}

// ---------------------------------------------------------------------------
// Kernel D: flash attention, mma.sync f16 m16n8k16, 512 threads,
// KT=128 rows/tile (plain layout pitch 304), ldmatrix B loads, 3-buffer ring.
// ---------------------------------------------------------------------------
#define KT 128
#define NT (4096 / KT)
#define KPITCH 304
#define KTILE  38912
#define SM_K(b) ((b) * KTILE)
#define SM_U    (3 * KTILE)            // 116736
#define SM_RN   (SM_U + 16384)
#define SM_RD   (SM_RN + 1024)
#define SM_MB   (SM_RD + 1024)
#define SMEM_ATTN (SM_MB + 64)

__device__ __forceinline__ void attn_epilogue(const float c[8][4], const float* us,
                                              int wn, int lane, float num[2], float den[2])
{
#pragma unroll
    for (int jn = 0; jn < 8; jn++) {
        const int c0 = wn * 64 + jn * 8 + 2 * (lane & 3);
        const float2 uv = *(const float2*)&us[c0];
        float e0 = ex2f_(c[jn][0]);
        float e1 = ex2f_(c[jn][1]);
        float e2 = ex2f_(c[jn][2]);
        float e3 = ex2f_(c[jn][3]);
        num[0] = fmaf(e0, uv.x, num[0]);
        num[0] = fmaf(e1, uv.y, num[0]);
        den[0] += e0 + e1;
        num[1] = fmaf(e2, uv.x, num[1]);
        num[1] = fmaf(e3, uv.y, num[1]);
        den[1] += e2 + e3;
    }
}

__global__ void __launch_bounds__(512, 1) attn_mma_kernel()
{
    extern __shared__ char smem[];
    const uint32_t sb = smem_u32(smem);
    const int tid  = threadIdx.x;
    const int lane = tid & 31;
    const int wid  = tid >> 5;
    const int wm   = wid >> 1;     // 0..7, 16 q-rows each
    const int wn   = wid & 1;      // 0..1, 64 k-cols each
    const int qb   = blockIdx.x;
    const int sp_  = blockIdx.y;
    const int j_base = sp_ * 4096;
    const int t_base = sp_ * NT;

    if (tid == 0) {
#pragma unroll
        for (int b = 0; b < 3; b++) {
            MBARRIER_INIT(sb + SM_MB + 8 * b, 1);
            MBARRIER_INIT(sb + SM_MB + 24 + 8 * b, 16);
        }
    }
#pragma unroll
    for (int i = 0; i < 2; i++) {
        int s = tid + 512 * i;
        *(float4*)(smem + SM_U + s * 16) = *(const float4*)&g_U[j_base + s * 4];
    }
    __syncthreads();

    if (tid == 0) {
#pragma unroll
        for (int t = 0; t < 2; t++) {
            MBARRIER_EXPECT_TX(sb + SM_MB + 8 * t, KTILE);
            bulk_g2s(sb + SM_K(t), g_Kp + (size_t)(t_base + t) * KTILE, KTILE,
                     sb + SM_MB + 8 * t);
        }
    }

    const float QS = 0.1275174341917854f;   // log2(e)/sqrt(128)
    uint32_t qa[8][4];
    {
        const float* qp = g_Q + (size_t)(qb * 128 + wm * 16) * DH;
        const int r = lane >> 2, c2 = (lane & 3) * 2;
#pragma unroll
        for (int kf = 0; kf < 8; kf++) {
            const float* base = qp + (size_t)r * DH + kf * 16 + c2;
            qa[kf][0] = pack_h2(base[0] * QS, base[1] * QS);
            qa[kf][1] = pack_h2(base[8 * DH] * QS, base[8 * DH + 1] * QS);
            qa[kf][2] = pack_h2(base[8] * QS, base[9] * QS);
            qa[kf][3] = pack_h2(base[8 * DH + 8] * QS, base[8 * DH + 9] * QS);
        }
    }

    float num[2] = {0.f, 0.f};
    float den[2] = {0.f, 0.f};
    float cbuf[2][8][4];

    // ldmatrix B offsets: row = n-token, chunks 16B: klo at kf*32, khi at +16
    const int mat = lane >> 3, r8 = lane & 7;
    const uint32_t boff = (uint32_t)((mat >> 1) * 8 + r8) * KPITCH + (mat & 1) * 16;

#pragma unroll 1
    for (int t = 0; t < NT; t++) {
        const int tp = t + 2;
        if (tp < NT && tid == 0) {
            const int b2 = tp % 3, o2 = tp / 3;
            if (o2 >= 1) MBARRIER_WAIT_PARITY(sb + SM_MB + 24 + 8 * b2, (o2 - 1) & 1);
            MBARRIER_EXPECT_TX(sb + SM_MB + 8 * b2, KTILE);
            bulk_g2s(sb + SM_K(b2), g_Kp + (size_t)(t_base + tp) * KTILE, KTILE,
                     sb + SM_MB + 8 * b2);
        }
        const int buf = t % 3;
        MBARRIER_WAIT_PARITY(sb + SM_MB + 8 * buf, (t / 3) & 1);

        const uint32_t kb = sb + SM_K(buf) + boff;
        float (*c)[4] = cbuf[t & 1];
#pragma unroll
        for (int jn = 0; jn < 8; jn++)
#pragma unroll
            for (int v = 0; v < 4; v++) c[jn][v] = 0.f;

#pragma unroll
        for (int kf = 0; kf < 8; kf++) {
#pragma unroll
            for (int p = 0; p < 4; p++) {   // jn pairs
                uint32_t b[4];
                ldsm_x4(b, kb + (uint32_t)(wn * 64 + p * 16) * KPITCH + (uint32_t)kf * 32);
                mma_f16(c[2 * p],     qa[kf], b[0], b[1]);
                mma_f16(c[2 * p + 1], qa[kf], b[2], b[3]);
            }
        }
        if (lane == 0) MBARRIER_ARRIVE(sb + SM_MB + 24 + 8 * buf);

        if (t > 0) {
            const float* us = (const float*)(smem + SM_U) + (t - 1) * KT;
            attn_epilogue(cbuf[(t - 1) & 1], us, wn, lane, num, den);
        }
    }
    {
        const float* us = (const float*)(smem + SM_U) + (NT - 1) * KT;
        attn_epilogue(cbuf[(NT - 1) & 1], us, wn, lane, num, den);
    }

#pragma unroll
    for (int s = 0; s < 2; s++) {
        num[s] += __shfl_xor_sync(0xffffffffu, num[s], 1);
        num[s] += __shfl_xor_sync(0xffffffffu, num[s], 2);
        den[s] += __shfl_xor_sync(0xffffffffu, den[s], 1);
        den[s] += __shfl_xor_sync(0xffffffffu, den[s], 2);
    }
    if ((lane & 3) == 0) {
        float* rn = (float*)(smem + SM_RN);
        float* rd = (float*)(smem + SM_RD);
        int row = wm * 16 + (lane >> 2);
        rn[wn * 128 + row]     = num[0];
        rd[wn * 128 + row]     = den[0];
        rn[wn * 128 + row + 8] = num[1];
        rd[wn * 128 + row + 8] = den[1];
    }
    __syncthreads();
    if (tid < 128) {
        const float* rn = (const float*)(smem + SM_RN);
        const float* rd = (const float*)(smem + SM_RD);
        g_PN[sp_ * NROWS + qb * 128 + tid] = rn[tid] + rn[128 + tid];
        g_PD[sp_ * NROWS + qb * 128 + tid] = rd[tid] + rd[128 + tid];
    }
}

// ---------------------------------------------------------------------------
// Kernel E: combine splits
// ---------------------------------------------------------------------------
__global__ void __launch_bounds__(256) combine_kernel(const float* __restrict__ bout,
                                                      float* __restrict__ out)
{
    int i = blockIdx.x * 256 + threadIdx.x;
    float n = g_PN[i] + g_PN[NROWS + i];
    float d = g_PD[i] + g_PD[NROWS + i];
    out[i] = n / d + __ldg(bout);
}

// ---------------------------------------------------------------------------
extern "C" void kernel_launch(void* const* d_in, const int* in_sizes, int n_in,
                              void* d_out, int out_size)
{
    const float* x    = (const float*)d_in[0];
    const float* Wfc  = (const float*)d_in[1];
    const float* bfc  = (const float*)d_in[2];
    const float* Wg   = (const float*)d_in[3];
    const float* bg   = (const float*)d_in[4];
    const float* Wq   = (const float*)d_in[5];
    const float* bq   = (const float*)d_in[6];
    const float* Wk   = (const float*)d_in[7];
    const float* bk   = (const float*)d_in[8];
    const float* Wv   = (const float*)d_in[9];
    const float* bv   = (const float*)d_in[10];
    const float* Wout = (const float*)d_in[11];
    const float* bout = (const float*)d_in[12];
    float* out = (float*)d_out;

    cudaFuncSetAttribute(attn_mma_kernel, cudaFuncAttributeMaxDynamicSharedMemorySize, SMEM_ATTN);
    cudaFuncSetAttribute(gated_fc_mma_kernel, cudaFuncAttributeMaxDynamicSharedMemorySize, GF_SMEM);
    cudaFuncSetAttribute(qkv_mma_kernel, cudaFuncAttributeMaxDynamicSharedMemorySize, QV_SMEM);

    cvt_x_kernel<<<NROWS * DIN / 1024, 256>>>(x);
    cvt_w_kernel<<<256 * DIN / 256, 256>>>(Wfc, Wg);
    cvt_wqkv_kernel<<<384 * DH / 256, 256>>>(Wq, Wk, Wv);
    gated_fc_mma_kernel<<<NROWS / 64, 512, GF_SMEM>>>(bfc, bg);
    qkv_mma_kernel<<<NROWS / 64, 256, QV_SMEM>>>(bq, bk, bv, Wout);
    attn_mma_kernel<<<dim3(NROWS / 128, 2), 512, SMEM_ATTN>>>();
    combine_kernel<<<NROWS / 256, 256>>>(bout, out);
}

// round 17
// speedup vs baseline: 7.2609x; 1.1828x over previous
#include <cuda_runtime.h>
#include <cuda_bf16.h>
#include <cuda_fp16.h>
#include <cstdint>

#define NROWS 8192
#define DIN   1024
#define DH    128

// ---------------------------------------------------------------------------
// Scratch
// ---------------------------------------------------------------------------
__device__ float g_Q[NROWS * DH];
__device__ float g_U[NROWS];
__device__ float g_PN[2 * NROWS];
__device__ float g_PD[2 * NROWS];
// Packed K (f16, plain [row][k], pitch 304B): 64 tiles of [128 rows][304 B]
__device__ __align__(1024) char g_Kp[64 * 38912];
// Packed x hi/lo: per (rowblock 64, stage 32k): [hi 64x80B][lo 64x80B]
__device__ __align__(1024) char g_xp[128 * 32 * 10240];
// Packed W_fc|W_gate hi/lo per stage: [wh 256x80B][wl 256x80B]
__device__ __align__(1024) char g_wp[32 * 40960];
// Packed H hi/lo: per (rowblock 64, stage 32k of DH): [hi 64x80B][lo 64x80B]
__device__ __align__(1024) char g_hp[128 * 4 * 10240];
// Packed W_qkv hi/lo per stage (k of DH): [wh 384x80B][wl 384x80B]
__device__ __align__(1024) char g_wqp[4 * 61440];

__device__ __forceinline__ float sigmoidf_(float z) {
    return 1.0f / (1.0f + __expf(-z));
}
__device__ __forceinline__ uint32_t smem_u32(const void* p) {
    uint32_t a;
    asm("{ .reg .u64 t; cvta.to.shared.u64 t, %1; cvt.u32.u64 %0, t; }" : "=r"(a) : "l"(p));
    return a;
}
__device__ __forceinline__ uint32_t pack_h2(float x, float y) {
    __half2 h = __floats2half2_rn(x, y);
    return *(uint32_t*)&h;
}
__device__ __forceinline__ void ldsm_x4(uint32_t r[4], uint32_t addr) {
    asm volatile("ldmatrix.sync.aligned.m8n8.x4.shared.b16 {%0,%1,%2,%3}, [%4];"
                 : "=r"(r[0]), "=r"(r[1]), "=r"(r[2]), "=r"(r[3]) : "r"(addr));
}
__device__ __forceinline__ void mma_f16(float c[4], const uint32_t a[4],
                                        uint32_t b0, uint32_t b1) {
    asm volatile(
        "mma.sync.aligned.m16n8k16.row.col.f32.f16.f16.f32 "
        "{%0,%1,%2,%3}, {%4,%5,%6,%7}, {%8,%9}, {%0,%1,%2,%3};"
        : "+f"(c[0]), "+f"(c[1]), "+f"(c[2]), "+f"(c[3])
        : "r"(a[0]), "r"(a[1]), "r"(a[2]), "r"(a[3]), "r"(b0), "r"(b1));
}
__device__ __forceinline__ void mma_bf16(float c[4], const uint32_t a[4],
                                         uint32_t b0, uint32_t b1) {
    asm volatile(
        "mma.sync.aligned.m16n8k16.row.col.f32.bf16.bf16.f32 "
        "{%0,%1,%2,%3}, {%4,%5,%6,%7}, {%8,%9}, {%0,%1,%2,%3};"
        : "+f"(c[0]), "+f"(c[1]), "+f"(c[2]), "+f"(c[3])
        : "r"(a[0]), "r"(a[1]), "r"(a[2]), "r"(a[3]), "r"(b0), "r"(b1));
}
__device__ __forceinline__ float ex2f_(float x) {
    float r; asm("ex2.approx.f32 %0, %1;" : "=f"(r) : "f"(x)); return r;
}
__device__ __forceinline__ void bulk_g2s(uint32_t dst, const void* src,
                                         uint32_t bytes, uint32_t mbar) {
    asm volatile(
        "cp.async.bulk.shared::cluster.global.mbarrier::complete_tx::bytes [%0], [%1], %2, [%3];"
        :: "r"(dst), "l"(src), "r"(bytes), "r"(mbar) : "memory");
}
#define MBARRIER_INIT(addr, cnt) \
    asm volatile("mbarrier.init.shared.b64 [%0], %1;" :: "r"(addr), "r"(cnt) : "memory")
#define MBARRIER_ARRIVE(addr) \
    asm volatile("mbarrier.arrive.shared.b64 _, [%0];" :: "r"(addr) : "memory")
#define MBARRIER_EXPECT_TX(addr, bytes) \
    asm volatile("mbarrier.arrive.expect_tx.shared.b64 _, [%0], %1;" \
                 :: "r"(addr), "r"(bytes) : "memory")
#define MBARRIER_WAIT_PARITY(addr, ph) do {                                    \
    uint32_t _m = (uint32_t)(addr);                                            \
    uint32_t _p = (uint32_t)(ph);                                              \
    uint32_t _d;                                                               \
    asm volatile("{\n\t.reg .pred p;\n\t"                                      \
        "mbarrier.try_wait.parity.acquire.cta.shared::cta.b64 p, [%1], %2;\n\t"\
        "selp.b32 %0, 1, 0, p;\n\t}" : "=r"(_d) : "r"(_m), "r"(_p) : "memory");\
    if (!_d) {                                                                 \
        asm volatile("{\n\t.reg .pred P1;\n\t"                                 \
            "WL_%=:\n\t"                                                       \
            "mbarrier.try_wait.parity.acquire.cta.shared::cta.b64 P1, [%0], %1, 0x989680;\n\t" \
            "@P1 bra.uni WD_%=;\n\t"                                           \
            "bra.uni WL_%=;\n\t"                                               \
            "WD_%=:\n\t}" :: "r"(_m), "r"(_p) : "memory");                     \
    }                                                                          \
} while (0)

// ---------------------------------------------------------------------------
// Prekernel: x -> packed bf16 hi/lo tiles
// ---------------------------------------------------------------------------
__global__ void __launch_bounds__(256) cvt_x_kernel(const float* __restrict__ x)
{
    int i = (blockIdx.x * 256 + threadIdx.x) * 4;
    int row = i >> 10, k = i & 1023;
    float4 v = *(const float4*)&x[i];
    __nv_bfloat16 h0 = __float2bfloat16(v.x);
    __nv_bfloat16 h1 = __float2bfloat16(v.y);
    __nv_bfloat16 h2 = __float2bfloat16(v.z);
    __nv_bfloat16 h3 = __float2bfloat16(v.w);
    __nv_bfloat16 l0 = __float2bfloat16(v.x - __bfloat162float(h0));
    __nv_bfloat16 l1 = __float2bfloat16(v.y - __bfloat162float(h1));
    __nv_bfloat16 l2 = __float2bfloat16(v.z - __bfloat162float(h2));
    __nv_bfloat16 l3 = __float2bfloat16(v.w - __bfloat162float(h3));
    int rb = row >> 6, r = row & 63, stage = k >> 5, kk = k & 31;
    size_t base = (size_t)(rb * 32 + stage) * 10240 + r * 80 + kk * 2;
    uint32_t hp0 = ((uint32_t)__bfloat16_as_ushort(h1) << 16) | __bfloat16_as_ushort(h0);
    uint32_t hp1 = ((uint32_t)__bfloat16_as_ushort(h3) << 16) | __bfloat16_as_ushort(h2);
    uint32_t lp0 = ((uint32_t)__bfloat16_as_ushort(l1) << 16) | __bfloat16_as_ushort(l0);
    uint32_t lp1 = ((uint32_t)__bfloat16_as_ushort(l3) << 16) | __bfloat16_as_ushort(l2);
    *(uint2*)(g_xp + base)        = make_uint2(hp0, hp1);
    *(uint2*)(g_xp + base + 5120) = make_uint2(lp0, lp1);
}

// ---------------------------------------------------------------------------
// Prekernel: W_fc|W_gate -> packed bf16 hi/lo tiles, transposed to [n][k]
// ---------------------------------------------------------------------------
__global__ void __launch_bounds__(256) cvt_w_kernel(const float* __restrict__ Wfc,
                                                    const float* __restrict__ Wg)
{
    int idx = blockIdx.x * 256 + threadIdx.x;   // n*1024 + k
    int n = idx >> 10, k = idx & 1023;
    float v = (n < 128) ? Wfc[(size_t)k * DH + n] : Wg[(size_t)k * DH + (n - 128)];
    __nv_bfloat16 h = __float2bfloat16(v);
    __nv_bfloat16 l = __float2bfloat16(v - __bfloat162float(h));
    int stage = k >> 5, kk = k & 31;
    size_t base = (size_t)stage * 40960 + n * 80 + kk * 2;
    *(__nv_bfloat16*)(g_wp + base)         = h;
    *(__nv_bfloat16*)(g_wp + base + 20480) = l;
}

// ---------------------------------------------------------------------------
// Prekernel: W_q|W_k|W_v -> packed bf16 hi/lo tiles, transposed to [n][k]
// ---------------------------------------------------------------------------
__global__ void __launch_bounds__(256) cvt_wqkv_kernel(const float* __restrict__ Wq,
                                                       const float* __restrict__ Wk,
                                                       const float* __restrict__ Wv)
{
    int idx = blockIdx.x * 256 + threadIdx.x;   // n*128 + k, 384*128 total
    int n = idx >> 7, k = idx & 127;
    float v = (n < 128) ? Wq[(size_t)k * DH + n]
            : (n < 256) ? Wk[(size_t)k * DH + (n - 128)]
                        : Wv[(size_t)k * DH + (n - 256)];
    __nv_bfloat16 h = __float2bfloat16(v);
    __nv_bfloat16 l = __float2bfloat16(v - __bfloat162float(h));
    int stage = k >> 5, kk = k & 31;
    size_t base = (size_t)stage * 61440 + n * 80 + kk * 2;
    *(__nv_bfloat16*)(g_wqp + base)         = h;
    *(__nv_bfloat16*)(g_wqp + base + 30720) = l;
}

// ---------------------------------------------------------------------------
// Kernel A: gated linear, bf16 3-term MMA, 512 threads.
// NEW tiling wm2 x wn8: 32 rows x (16 fc + 16 gate) cols per warp -> square
// fragment traffic (8 KB/warp/stage). 3-buffer ring, ldmatrix loads.
// ---------------------------------------------------------------------------
#define GF_PITCH 80
#define GF_BUF   51200
#define GF_XH(b)  ((b) * GF_BUF + 0)
#define GF_XL(b)  ((b) * GF_BUF + 5120)
#define GF_WH(b)  ((b) * GF_BUF + 10240)
#define GF_WL(b)  ((b) * GF_BUF + 30720)
#define GF_MB     (3 * GF_BUF)
#define GF_SMEM   (3 * GF_BUF + 64)

__global__ void __launch_bounds__(512, 1) gated_fc_mma_kernel(
    const float* __restrict__ bfc, const float* __restrict__ bg)
{
    extern __shared__ char smem[];
    const uint32_t sb = smem_u32(smem);
    const int tid  = threadIdx.x;
    const int lane = tid & 31;
    const int wid  = tid >> 5;
    const int wm   = wid & 1;        // 32 rows each
    const int wn   = wid >> 1;       // 0..7: 16 fc cols + matching 16 gate cols

    if (tid == 0) {
#pragma unroll
        for (int b = 0; b < 3; b++) {
            MBARRIER_INIT(sb + GF_MB + 8 * b, 1);
            MBARRIER_INIT(sb + GF_MB + 24 + 8 * b, 16);
        }
    }
    __syncthreads();

    // c[im][0..1] = fc (two n8 halves), c[im][2..3] = gate
    float c[2][4][4];
#pragma unroll
    for (int im = 0; im < 2; im++)
#pragma unroll
        for (int jn = 0; jn < 4; jn++)
#pragma unroll
            for (int v = 0; v < 4; v++) c[im][jn][v] = 0.f;

    if (tid == 0) {
#pragma unroll
        for (int s = 0; s < 2; s++) {
            MBARRIER_EXPECT_TX(sb + GF_MB + 8 * s, 51200);
            bulk_g2s(sb + GF_XH(s), g_xp + (size_t)(blockIdx.x * 32 + s) * 10240, 10240,
                     sb + GF_MB + 8 * s);
            bulk_g2s(sb + GF_WH(s), g_wp + (size_t)s * 40960, 40960, sb + GF_MB + 8 * s);
        }
    }

    const int mat = lane >> 3, r8 = lane & 7;
    const uint32_t aoff = (uint32_t)(wm * 32 + (mat & 1) * 8 + r8) * GF_PITCH + (mat >> 1) * 16;
    const uint32_t boff = (uint32_t)((mat >> 1) * 8 + r8) * GF_PITCH + (mat & 1) * 16;
    const uint32_t nfc = (uint32_t)(wn * 16) * GF_PITCH;
    const uint32_t ngt = (uint32_t)(128 + wn * 16) * GF_PITCH;

#pragma unroll 1
    for (int s = 0; s < 32; s++) {
        const int sp = s + 2;
        if (sp < 32 && tid == 0) {
            const int b2 = sp % 3, o2 = sp / 3;
            if (o2 >= 1) MBARRIER_WAIT_PARITY(sb + GF_MB + 24 + 8 * b2, (o2 - 1) & 1);
            MBARRIER_EXPECT_TX(sb + GF_MB + 8 * b2, 51200);
            bulk_g2s(sb + GF_XH(b2), g_xp + (size_t)(blockIdx.x * 32 + sp) * 10240, 10240,
                     sb + GF_MB + 8 * b2);
            bulk_g2s(sb + GF_WH(b2), g_wp + (size_t)sp * 40960, 40960, sb + GF_MB + 8 * b2);
        }
        const int buf = s % 3;
        MBARRIER_WAIT_PARITY(sb + GF_MB + 8 * buf, (s / 3) & 1);

        const uint32_t xh = sb + GF_XH(buf) + aoff;
        const uint32_t xl = sb + GF_XL(buf) + aoff;
        const uint32_t wh = sb + GF_WH(buf) + boff;
        const uint32_t wl = sb + GF_WL(buf) + boff;

#pragma unroll
        for (int kf = 0; kf < 2; kf++) {
            uint32_t ah[2][4], al[2][4];
#pragma unroll
            for (int im = 0; im < 2; im++) {
                ldsm_x4(ah[im], xh + (uint32_t)im * (16 * GF_PITCH) + kf * 32);
                ldsm_x4(al[im], xl + (uint32_t)im * (16 * GF_PITCH) + kf * 32);
            }
            uint32_t bfh[4], bfl[4], bgh[4], bgl[4];
            ldsm_x4(bfh, wh + nfc + kf * 32);
            ldsm_x4(bfl, wl + nfc + kf * 32);
            ldsm_x4(bgh, wh + ngt + kf * 32);
            ldsm_x4(bgl, wl + ngt + kf * 32);
#pragma unroll
            for (int im = 0; im < 2; im++) {
                mma_bf16(c[im][0], ah[im], bfh[0], bfh[1]);
                mma_bf16(c[im][0], ah[im], bfl[0], bfl[1]);
                mma_bf16(c[im][0], al[im], bfh[0], bfh[1]);
                mma_bf16(c[im][1], ah[im], bfh[2], bfh[3]);
                mma_bf16(c[im][1], ah[im], bfl[2], bfl[3]);
                mma_bf16(c[im][1], al[im], bfh[2], bfh[3]);
                mma_bf16(c[im][2], ah[im], bgh[0], bgh[1]);
                mma_bf16(c[im][2], ah[im], bgl[0], bgl[1]);
                mma_bf16(c[im][2], al[im], bgh[0], bgh[1]);
                mma_bf16(c[im][3], ah[im], bgh[2], bgh[3]);
                mma_bf16(c[im][3], ah[im], bgl[2], bgl[3]);
                mma_bf16(c[im][3], al[im], bgh[2], bgh[3]);
            }
        }
        if (lane == 0) MBARRIER_ARRIVE(sb + GF_MB + 24 + 8 * buf);
    }

    // epilogue: h = (fc + bfc) * sigmoid(gate + bg) -> packed bf16 hi/lo tiles
#pragma unroll
    for (int im = 0; im < 2; im++) {
#pragma unroll
        for (int jh = 0; jh < 2; jh++) {
            const int n0 = wn * 16 + jh * 8 + 2 * (lane & 3);
            float2 bf  = *(const float2*)&bfc[n0];
            float2 bg2 = *(const float2*)&bg[n0];
            float2 h0, h1;
            h0.x = (c[im][jh][0] + bf.x) * sigmoidf_(c[im][jh + 2][0] + bg2.x);
            h0.y = (c[im][jh][1] + bf.y) * sigmoidf_(c[im][jh + 2][1] + bg2.y);
            h1.x = (c[im][jh][2] + bf.x) * sigmoidf_(c[im][jh + 2][2] + bg2.x);
            h1.y = (c[im][jh][3] + bf.y) * sigmoidf_(c[im][jh + 2][3] + bg2.y);
            const int r0 = wm * 32 + im * 16 + (lane >> 2);
            const int stage = n0 >> 5, kk = n0 & 31;
            char* tb = g_hp + ((size_t)blockIdx.x * 4 + stage) * 10240 + kk * 2;
#pragma unroll
            for (int hh = 0; hh < 2; hh++) {
                float2 hv = hh ? h1 : h0;
                int r = r0 + hh * 8;
                __nv_bfloat16 b0 = __float2bfloat16(hv.x);
                __nv_bfloat16 b1 = __float2bfloat16(hv.y);
                __nv_bfloat16 c0 = __float2bfloat16(hv.x - __bfloat162float(b0));
                __nv_bfloat16 c1 = __float2bfloat16(hv.y - __bfloat162float(b1));
                *(uint32_t*)(tb + r * 80) =
                    ((uint32_t)__bfloat16_as_ushort(b1) << 16) | __bfloat16_as_ushort(b0);
                *(uint32_t*)(tb + r * 80 + 5120) =
                    ((uint32_t)__bfloat16_as_ushort(c1) << 16) | __bfloat16_as_ushort(c0);
            }
        }
    }
}

// ---------------------------------------------------------------------------
// Kernel B: fused QKV + U, bf16 3-term MMA, ldmatrix loads. (unchanged)
// ---------------------------------------------------------------------------
#define QV_BUF   71680
#define QV_XH(b)  ((b) * QV_BUF + 0)
#define QV_XL(b)  ((b) * QV_BUF + 5120)
#define QV_WH(b)  ((b) * QV_BUF + 10240)
#define QV_WL(b)  ((b) * QV_BUF + 40960)
#define QV_MBAR   (2 * QV_BUF)
#define QV_UPART  (2 * QV_BUF + 64)
#define QV_SMEM   (2 * QV_BUF + 64 + 256)

__global__ void __launch_bounds__(256, 1) qkv_mma_kernel(
    const float* __restrict__ bq, const float* __restrict__ bk,
    const float* __restrict__ bv, const float* __restrict__ Wout)
{
    extern __shared__ char smem[];
    const uint32_t sb = smem_u32(smem);
    float* u_part = (float*)(smem + QV_UPART);
    const int tid  = threadIdx.x;
    const int lane = tid & 31;
    const int wid  = tid >> 5;
    const int wm   = wid & 1;
    const int wn   = wid >> 1;
    const int rb   = blockIdx.x * 64;

    if (tid == 0) {
        MBARRIER_INIT(sb + QV_MBAR, 1);
        MBARRIER_INIT(sb + QV_MBAR + 8, 1);
    }
    if (tid < 64) u_part[tid] = 0.f;
    __syncthreads();

    float c[2][12][4];
#pragma unroll
    for (int im = 0; im < 2; im++)
#pragma unroll
        for (int jn = 0; jn < 12; jn++)
#pragma unroll
            for (int v = 0; v < 4; v++) c[im][jn][v] = 0.f;

    if (tid == 0) {
        MBARRIER_EXPECT_TX(sb + QV_MBAR, QV_BUF);
        bulk_g2s(sb + QV_XH(0), g_hp + (size_t)(blockIdx.x * 4) * 10240, 10240, sb + QV_MBAR);
        bulk_g2s(sb + QV_WH(0), g_wqp, 61440, sb + QV_MBAR);
    }

    const int mat = lane >> 3, r8 = lane & 7;
    const uint32_t aoff = (uint32_t)(wm * 32 + (mat & 1) * 8 + r8) * GF_PITCH + (mat >> 1) * 16;
    const uint32_t boff = (uint32_t)((mat >> 1) * 8 + r8) * GF_PITCH + (mat & 1) * 16;

#pragma unroll 1
    for (int s = 0; s < 4; s++) {
        if (s + 1 < 4 && tid == 0) {
            const int nb = (s + 1) & 1;
            const uint32_t mb = sb + QV_MBAR + 8 * nb;
            MBARRIER_EXPECT_TX(mb, QV_BUF);
            bulk_g2s(sb + QV_XH(nb), g_hp + (size_t)(blockIdx.x * 4 + s + 1) * 10240, 10240, mb);
            bulk_g2s(sb + QV_WH(nb), g_wqp + (size_t)(s + 1) * 61440, 61440, mb);
        }
        MBARRIER_WAIT_PARITY(sb + QV_MBAR + 8 * (s & 1), (s >> 1) & 1);

        const int buf = s & 1;
        const uint32_t xh = sb + QV_XH(buf) + aoff;
        const uint32_t xl = sb + QV_XL(buf) + aoff;
        const uint32_t wh = sb + QV_WH(buf) + boff;
        const uint32_t wl = sb + QV_WL(buf) + boff;

#pragma unroll
        for (int kf = 0; kf < 2; kf++) {
            uint32_t ah[2][4], al[2][4];
#pragma unroll
            for (int im = 0; im < 2; im++) {
                ldsm_x4(ah[im], xh + (uint32_t)im * (16 * GF_PITCH) + kf * 32);
                ldsm_x4(al[im], xl + (uint32_t)im * (16 * GF_PITCH) + kf * 32);
            }
#pragma unroll
            for (int p = 0; p < 6; p++) {
                const int n0 = wn * 96 + p * 16;
                uint32_t bh[4], bl[4];
                ldsm_x4(bh, wh + (uint32_t)n0 * GF_PITCH + kf * 32);
                ldsm_x4(bl, wl + (uint32_t)n0 * GF_PITCH + kf * 32);
#pragma unroll
                for (int im = 0; im < 2; im++) {
                    mma_bf16(c[im][2 * p],     ah[im], bh[0], bh[1]);
                    mma_bf16(c[im][2 * p],     ah[im], bl[0], bl[1]);
                    mma_bf16(c[im][2 * p],     al[im], bh[0], bh[1]);
                    mma_bf16(c[im][2 * p + 1], ah[im], bh[2], bh[3]);
                    mma_bf16(c[im][2 * p + 1], ah[im], bl[2], bl[3]);
                    mma_bf16(c[im][2 * p + 1], al[im], bh[2], bh[3]);
                }
            }
        }
        __syncthreads();
    }

    float up[4] = {0.f, 0.f, 0.f, 0.f};
#pragma unroll
    for (int im = 0; im < 2; im++) {
#pragma unroll
        for (int jn = 0; jn < 12; jn++) {
            const int n0 = wn * 96 + jn * 8 + 2 * (lane & 3);
            const int r0 = rb + wm * 32 + (lane >> 2) + im * 16;
            if (n0 < 128) {
                float2 bq2 = *(const float2*)&bq[n0];
                float2 q0 = make_float2(c[im][jn][0] + bq2.x, c[im][jn][1] + bq2.y);
                float2 q1 = make_float2(c[im][jn][2] + bq2.x, c[im][jn][3] + bq2.y);
                *(float2*)&g_Q[(size_t)r0 * DH + n0] = q0;
                *(float2*)&g_Q[(size_t)(r0 + 8) * DH + n0] = q1;
            } else if (n0 < 256) {
                const int kc = n0 - 128;
                float2 bk2 = *(const float2*)&bk[kc];
#pragma unroll
                for (int hh = 0; hh < 2; hh++) {
                    int r = r0 + hh * 8;
                    char* kb = g_Kp + (size_t)(r >> 7) * 38912 + (r & 127) * 304;
                    *(uint32_t*)(kb + kc * 2) =
                        pack_h2(c[im][jn][hh * 2 + 0] + bk2.x, c[im][jn][hh * 2 + 1] + bk2.y);
                }
            } else {
                const int vc = n0 - 256;
                float2 bv2 = *(const float2*)&bv[vc];
                float2 w2  = *(const float2*)&Wout[vc];
                up[im * 2 + 0] += (c[im][jn][0] + bv2.x) * w2.x + (c[im][jn][1] + bv2.y) * w2.y;
                up[im * 2 + 1] += (c[im][jn][2] + bv2.x) * w2.x + (c[im][jn][3] + bv2.y) * w2.y;
            }
        }
    }
    if (wn >= 2) {
#pragma unroll
        for (int s = 0; s < 4; s++) {
            up[s] += __shfl_xor_sync(0xffffffffu, up[s], 1);
            up[s] += __shfl_xor_sync(0xffffffffu, up[s], 2);
        }
        if ((lane & 3) == 0) {
#pragma unroll
            for (int s = 0; s < 4; s++) {
                int row = wm * 32 + (lane >> 2) + (s >> 1) * 16 + (s & 1) * 8;
                atomicAdd(&u_part[row], up[s]);
            }
        }
    }
    __syncthreads();
    if (tid < 64) g_U[rb + tid] = u_part[tid];
}

// ---------------------------------------------------------------------------
// Kernel D: flash attention, mma.sync f16, 512 threads.
// NEW tiling wm4 x wn4: 32 q-rows (A in regs) x 32 tokens per warp -> B smem
// reads halve. Single accumulator set, immediate epilogue, 3-buffer ring.
// ---------------------------------------------------------------------------
#define KT 128
#define NT (4096 / KT)
#define KPITCH 304
#define KTILE  38912
#define SM_K(b) ((b) * KTILE)
#define SM_U    (3 * KTILE)            // 116736
#define SM_RN   (SM_U + 16384)
#define SM_RD   (SM_RN + 2048)
#define SM_MB   (SM_RD + 2048)
#define SMEM_ATTN (SM_MB + 64)

__global__ void __launch_bounds__(512, 1) attn_mma_kernel()
{
    extern __shared__ char smem[];
    const uint32_t sb = smem_u32(smem);
    const int tid  = threadIdx.x;
    const int lane = tid & 31;
    const int wid  = tid >> 5;
    const int wm   = wid >> 2;     // 0..3, 32 q-rows each
    const int wn   = wid & 3;      // 0..3, 32 tokens each
    const int qb   = blockIdx.x;
    const int sp_  = blockIdx.y;
    const int j_base = sp_ * 4096;
    const int t_base = sp_ * NT;

    if (tid == 0) {
#pragma unroll
        for (int b = 0; b < 3; b++) {
            MBARRIER_INIT(sb + SM_MB + 8 * b, 1);
            MBARRIER_INIT(sb + SM_MB + 24 + 8 * b, 16);
        }
    }
#pragma unroll
    for (int i = 0; i < 2; i++) {
        int s = tid + 512 * i;
        *(float4*)(smem + SM_U + s * 16) = *(const float4*)&g_U[j_base + s * 4];
    }
    __syncthreads();

    if (tid == 0) {
#pragma unroll
        for (int t = 0; t < 2; t++) {
            MBARRIER_EXPECT_TX(sb + SM_MB + 8 * t, KTILE);
            bulk_g2s(sb + SM_K(t), g_Kp + (size_t)(t_base + t) * KTILE, KTILE,
                     sb + SM_MB + 8 * t);
        }
    }

    const float QS = 0.1275174341917854f;   // log2(e)/sqrt(128)
    uint32_t qa[2][8][4];
    {
        const float* qp = g_Q + (size_t)(qb * 128 + wm * 32) * DH;
        const int r = lane >> 2, c2 = (lane & 3) * 2;
#pragma unroll
        for (int im = 0; im < 2; im++) {
#pragma unroll
            for (int kf = 0; kf < 8; kf++) {
                const float* base = qp + (size_t)(im * 16 + r) * DH + kf * 16 + c2;
                qa[im][kf][0] = pack_h2(base[0] * QS, base[1] * QS);
                qa[im][kf][1] = pack_h2(base[8 * DH] * QS, base[8 * DH + 1] * QS);
                qa[im][kf][2] = pack_h2(base[8] * QS, base[9] * QS);
                qa[im][kf][3] = pack_h2(base[8 * DH + 8] * QS, base[8 * DH + 9] * QS);
            }
        }
    }

    float num[4] = {0.f, 0.f, 0.f, 0.f};
    float den[4] = {0.f, 0.f, 0.f, 0.f};

    const int mat = lane >> 3, r8 = lane & 7;
    const uint32_t boff = (uint32_t)((mat >> 1) * 8 + r8) * KPITCH + (mat & 1) * 16;

#pragma unroll 1
    for (int t = 0; t < NT; t++) {
        const int tp = t + 2;
        if (tp < NT && tid == 0) {
            const int b2 = tp % 3, o2 = tp / 3;
            if (o2 >= 1) MBARRIER_WAIT_PARITY(sb + SM_MB + 24 + 8 * b2, (o2 - 1) & 1);
            MBARRIER_EXPECT_TX(sb + SM_MB + 8 * b2, KTILE);
            bulk_g2s(sb + SM_K(b2), g_Kp + (size_t)(t_base + tp) * KTILE, KTILE,
                     sb + SM_MB + 8 * b2);
        }
        const int buf = t % 3;
        MBARRIER_WAIT_PARITY(sb + SM_MB + 8 * buf, (t / 3) & 1);

        const uint32_t kb = sb + SM_K(buf) + boff;
        float c[2][4][4];
#pragma unroll
        for (int im = 0; im < 2; im++)
#pragma unroll
            for (int jn = 0; jn < 4; jn++)
#pragma unroll
                for (int v = 0; v < 4; v++) c[im][jn][v] = 0.f;

#pragma unroll
        for (int kf = 0; kf < 8; kf++) {
#pragma unroll
            for (int p = 0; p < 2; p++) {
                uint32_t b[4];
                ldsm_x4(b, kb + (uint32_t)(wn * 32 + p * 16) * KPITCH + (uint32_t)kf * 32);
#pragma unroll
                for (int im = 0; im < 2; im++) {
                    mma_f16(c[im][2 * p],     qa[im][kf], b[0], b[1]);
                    mma_f16(c[im][2 * p + 1], qa[im][kf], b[2], b[3]);
                }
            }
        }
        if (lane == 0) MBARRIER_ARRIVE(sb + SM_MB + 24 + 8 * buf);

        // immediate epilogue (cross-warp skew via ring hides it)
        const float* us = (const float*)(smem + SM_U) + t * KT;
#pragma unroll
        for (int im = 0; im < 2; im++) {
#pragma unroll
            for (int jn = 0; jn < 4; jn++) {
                const int c0 = wn * 32 + (jn >> 1) * 16 + (jn & 1) * 8 + 2 * (lane & 3);
                const float2 uv = *(const float2*)&us[c0];
                float e0 = ex2f_(c[im][jn][0]);
                float e1 = ex2f_(c[im][jn][1]);
                float e2 = ex2f_(c[im][jn][2]);
                float e3 = ex2f_(c[im][jn][3]);
                num[im * 2 + 0] = fmaf(e0, uv.x, num[im * 2 + 0]);
                num[im * 2 + 0] = fmaf(e1, uv.y, num[im * 2 + 0]);
                den[im * 2 + 0] += e0 + e1;
                num[im * 2 + 1] = fmaf(e2, uv.x, num[im * 2 + 1]);
                num[im * 2 + 1] = fmaf(e3, uv.y, num[im * 2 + 1]);
                den[im * 2 + 1] += e2 + e3;
            }
        }
    }

#pragma unroll
    for (int s = 0; s < 4; s++) {
        num[s] += __shfl_xor_sync(0xffffffffu, num[s], 1);
        num[s] += __shfl_xor_sync(0xffffffffu, num[s], 2);
        den[s] += __shfl_xor_sync(0xffffffffu, den[s], 1);
        den[s] += __shfl_xor_sync(0xffffffffu, den[s], 2);
    }
    if ((lane & 3) == 0) {
        float* rn = (float*)(smem + SM_RN);
        float* rd = (float*)(smem + SM_RD);
#pragma unroll
        for (int s = 0; s < 4; s++) {
            int row = wm * 32 + (s >> 1) * 16 + (s & 1) * 8 + (lane >> 2);
            rn[wn * 128 + row] = num[s];
            rd[wn * 128 + row] = den[s];
        }
    }
    __syncthreads();
    if (tid < 128) {
        const float* rn = (const float*)(smem + SM_RN);
        const float* rd = (const float*)(smem + SM_RD);
        g_PN[sp_ * NROWS + qb * 128 + tid] =
            rn[tid] + rn[128 + tid] + rn[256 + tid] + rn[384 + tid];
        g_PD[sp_ * NROWS + qb * 128 + tid] =
            rd[tid] + rd[128 + tid] + rd[256 + tid] + rd[384 + tid];
    }
}

// ---------------------------------------------------------------------------
// Kernel E: combine splits
// ---------------------------------------------------------------------------
__global__ void __launch_bounds__(256) combine_kernel(const float* __restrict__ bout,
                                                      float* __restrict__ out)
{
    int i = blockIdx.x * 256 + threadIdx.x;
    float n = g_PN[i] + g_PN[NROWS + i];
    float d = g_PD[i] + g_PD[NROWS + i];
    out[i] = n / d + __ldg(bout);
}

// ---------------------------------------------------------------------------
extern "C" void kernel_launch(void* const* d_in, const int* in_sizes, int n_in,
                              void* d_out, int out_size)
{
    const float* x    = (const float*)d_in[0];
    const float* Wfc  = (const float*)d_in[1];
    const float* bfc  = (const float*)d_in[2];
    const float* Wg   = (const float*)d_in[3];
    const float* bg   = (const float*)d_in[4];
    const float* Wq   = (const float*)d_in[5];
    const float* bq   = (const float*)d_in[6];
    const float* Wk   = (const float*)d_in[7];
    const float* bk   = (const float*)d_in[8];
    const float* Wv   = (const float*)d_in[9];
    const float* bv   = (const float*)d_in[10];
    const float* Wout = (const float*)d_in[11];
    const float* bout = (const float*)d_in[12];
    float* out = (float*)d_out;

    cudaFuncSetAttribute(attn_mma_kernel, cudaFuncAttributeMaxDynamicSharedMemorySize, SMEM_ATTN);
    cudaFuncSetAttribute(gated_fc_mma_kernel, cudaFuncAttributeMaxDynamicSharedMemorySize, GF_SMEM);
    cudaFuncSetAttribute(qkv_mma_kernel, cudaFuncAttributeMaxDynamicSharedMemorySize, QV_SMEM);

    cvt_x_kernel<<<NROWS * DIN / 1024, 256>>>(x);
    cvt_w_kernel<<<256 * DIN / 256, 256>>>(Wfc, Wg);
    cvt_wqkv_kernel<<<384 * DH / 256, 256>>>(Wq, Wk, Wv);
    gated_fc_mma_kernel<<<NROWS / 64, 512, GF_SMEM>>>(bfc, bg);
    qkv_mma_kernel<<<NROWS / 64, 256, QV_SMEM>>>(bq, bk, bv, Wout);
    attn_mma_kernel<<<dim3(NROWS / 128, 2), 512, SMEM_ATTN>>>();
    combine_kernel<<<NROWS / 256, 256>>>(bout, out);
}